// round 1
// baseline (speedup 1.0000x reference)
#include <cuda_runtime.h>
#include <cstdint>

typedef unsigned long long ull;

constexpr int kB = 64;      // batch
constexpr int kT = 256;     // time
constexpr int kH = 512;     // hidden
constexpr int kG = 2048;    // 4*H gate cols
constexpr int kNCTA = 128;  // persistent recurrence CTAs

// ---------------- scratch (static device allocs are the sanctioned path) ----
__device__ float  g_G[(size_t)kB * kT * kG];    // input projections (128 MB)
__device__ float  g_h0[(size_t)kB * kT * kH];   // layer-0 output sequence (32 MB)
__device__ float2 g_hbuf[2][kH / 2][kB];        // ping-pong h, packed along k-pairs
__device__ int            g_count;
__device__ volatile int   g_flag;

// ---------------- helpers ----------------------------------------------------
__device__ __forceinline__ ull fma2(ull a, ull b, ull c) {
    ull d;
    asm("fma.rn.f32x2 %0, %1, %2, %3;" : "=l"(d) : "l"(a), "l"(b), "l"(c));
    return d;
}
__device__ __forceinline__ float lo32(ull v) { return __uint_as_float((unsigned)v); }
__device__ __forceinline__ float hi32(ull v) { return __uint_as_float((unsigned)(v >> 32)); }

__device__ __forceinline__ float sigf(float x) {
    x = fminf(fmaxf(x, -30.f), 30.f);
    return 1.f / (1.f + __expf(-x));
}
__device__ __forceinline__ float tanh_(float x) {
    x = fminf(fmaxf(x, -15.f), 15.f);
    float e = __expf(-2.f * x);
    return (1.f - e) / (1.f + e);
}

// ---------------- input-projection GEMM --------------------------------------
// C[m][n] = sum_k A[m][k] * W[k][n] + bi[n] + bh[n]
// M = 16384, N = 2048, K = 512. 64x64 block tile, 4x4 thread tile, K-tile 16,
// f32x2 packed along k-pairs, double-buffered SMEM.
// Also resets the global barrier state for the following recurrence kernel.
__global__ void __launch_bounds__(256, 2)
gemm_inproj(const float* __restrict__ A, const float* __restrict__ W,
            const float* __restrict__ bi, const float* __restrict__ bh,
            float* __restrict__ C)
{
    if (blockIdx.x == 0 && blockIdx.y == 0 && threadIdx.x == 0) {
        g_count = 0;
        g_flag = 0;
    }
    __shared__ ull As[2][8][64];   // [buf][k-pair][m]
    __shared__ ull Bs[2][8][64];   // [buf][k-pair][n]

    const int tid = threadIdx.x;
    const int m0 = blockIdx.x * 64;
    const int n0 = blockIdx.y * 64;
    const int tx = tid & 15;        // n base
    const int ty = tid >> 4;        // m quad

    const int am = tid >> 2;        // A stage: row within tile
    const int ak = tid & 3;         // A stage: which float4 along k
    const int br = tid >> 4;        // B stage: k row within tile
    const int bn = (tid & 15) * 4;  // B stage: n offset

    const float* Arow = A + (size_t)(m0 + am) * kH + ak * 4;
    const float* Wrow = W + (size_t)br * kG + n0 + bn;

    // prologue: stage tile 0
    {
        float4 a4 = *(const float4*)(Arow);
        float4 b4 = *(const float4*)(Wrow);
        ((float2*)&As[0][ak * 2][am])[0]     = make_float2(a4.x, a4.y);
        ((float2*)&As[0][ak * 2 + 1][am])[0] = make_float2(a4.z, a4.w);
        float* bd = (float*)&Bs[0][br >> 1][0];
        const int pb = br & 1;
        bd[(bn + 0) * 2 + pb] = b4.x;
        bd[(bn + 1) * 2 + pb] = b4.y;
        bd[(bn + 2) * 2 + pb] = b4.z;
        bd[(bn + 3) * 2 + pb] = b4.w;
    }
    __syncthreads();

    ull acc[4][4];
#pragma unroll
    for (int i = 0; i < 4; i++)
#pragma unroll
        for (int q = 0; q < 4; q++) acc[i][q] = 0ull;

    for (int kt = 0; kt < 32; kt++) {
        const int cur = kt & 1;
        float4 a4, b4;
        const bool more = (kt < 31);
        if (more) {
            a4 = *(const float4*)(Arow + (kt + 1) * 16);
            b4 = *(const float4*)(Wrow + (size_t)(kt + 1) * 16 * kG);
        }
#pragma unroll
        for (int kk = 0; kk < 8; kk++) {
            ull a[4], b[4];
#pragma unroll
            for (int i = 0; i < 4; i++) a[i] = As[cur][kk][ty * 4 + i];
#pragma unroll
            for (int q = 0; q < 4; q++) b[q] = Bs[cur][kk][tx + 16 * q];
#pragma unroll
            for (int i = 0; i < 4; i++)
#pragma unroll
                for (int q = 0; q < 4; q++)
                    acc[i][q] = fma2(a[i], b[q], acc[i][q]);
        }
        if (more) {
            const int nb = cur ^ 1;
            ((float2*)&As[nb][ak * 2][am])[0]     = make_float2(a4.x, a4.y);
            ((float2*)&As[nb][ak * 2 + 1][am])[0] = make_float2(a4.z, a4.w);
            float* bd = (float*)&Bs[nb][br >> 1][0];
            const int pb = br & 1;
            bd[(bn + 0) * 2 + pb] = b4.x;
            bd[(bn + 1) * 2 + pb] = b4.y;
            bd[(bn + 2) * 2 + pb] = b4.z;
            bd[(bn + 3) * 2 + pb] = b4.w;
        }
        __syncthreads();
    }

#pragma unroll
    for (int q = 0; q < 4; q++) {
        const int n = n0 + tx + 16 * q;
        const float bias = __ldg(bi + n) + __ldg(bh + n);
#pragma unroll
        for (int i = 0; i < 4; i++) {
            const int m = m0 + ty * 4 + i;
            C[(size_t)m * kG + n] = lo32(acc[i][q]) + hi32(acc[i][q]) + bias;
        }
    }
}

// ---------------- global barrier (all 128 persistent CTAs) -------------------
__device__ __forceinline__ void gbar(int idx, int tid)
{
    __syncthreads();
    if (tid == 0) {
        const int prev = atomicAdd(&g_count, 1);
        if (prev == idx * kNCTA - 1) {
            atomicExch((int*)&g_flag, idx);
        } else {
            while (g_flag < idx) { }
        }
        __threadfence();
    }
    __syncthreads();
}

// ---------------- persistent LSTM recurrence ---------------------------------
// 128 CTAs x 128 threads. CTA `cta` owns hidden units j0..j0+3 (16 gate cols).
// SMEM: hs [256][64] ull (packed h, 128KB) | Whs [256][16] ull (32KB, resident
// for all 256 steps) | gs [16][64] f32 gate staging | cs [4][64] f32 cell state.
extern __shared__ ull s_mem[];

__global__ void __launch_bounds__(128, 1)
lstm_recur(const float* __restrict__ G, const float* __restrict__ Wh,
           float* __restrict__ seqout, float* __restrict__ hT,
           float* __restrict__ cT)
{
    ull*   hs  = s_mem;                       // 16384 ull
    ull*   Whs = s_mem + 256 * 64;            // 4096 ull
    float* gs  = (float*)(Whs + 256 * 16);    // 1024 f32
    float* cs  = gs + 16 * 64;                // 256 f32

    const int tid = threadIdx.x;
    const int cta = blockIdx.x;
    const int j0  = cta * 4;

    // stage Wh slice, packed along k-pairs: Whs[kk][c] = (Wh[2kk][gc], Wh[2kk+1][gc])
    for (int k = tid; k < kH; k += 128) {
        float* dst = (float*)(Whs + (size_t)(k >> 1) * 16);
        const int par = k & 1;
#pragma unroll
        for (int g = 0; g < 4; g++) {
            float4 w = *(const float4*)(Wh + (size_t)k * kG + g * kH + j0);
            dst[(g * 4 + 0) * 2 + par] = w.x;
            dst[(g * 4 + 1) * 2 + par] = w.y;
            dst[(g * 4 + 2) * 2 + par] = w.z;
            dst[(g * 4 + 3) * 2 + par] = w.w;
        }
    }
    // zero owned slice of h ping buffer (parity 0) and cell state
    g_hbuf[0][cta * 2 + (tid >> 6)][tid & 63] = make_float2(0.f, 0.f);
    cs[tid] = 0.f;
    cs[tid + 128] = 0.f;
    __threadfence();
    gbar(1, tid);

    const int c2 = tid >> 4;   // 0..7: column pair
    const int bq = tid & 15;   // batch lane base (b = bq + 16q)

    for (int t = 0; t < kT; t++) {
        const int cur = t & 1;
        // stage full h (packed) into SMEM; .cg so we never hit a stale L1 line
        {
            const float4* src = (const float4*)(&g_hbuf[cur][0][0]);
            float4* dst = (float4*)hs;
#pragma unroll 8
            for (int i = tid; i < 8192; i += 128)
                dst[i] = __ldcg(src + i);
        }
        // prefetch this step's input projection (epilogue threads)
        float gin[4][4];
        if (tid < kB) {
            const float* gp = G + ((size_t)tid * kT + t) * kG + j0;
#pragma unroll
            for (int g = 0; g < 4; g++) {
                float4 v = __ldcs((const float4*)(gp + g * kH));
                gin[g][0] = v.x; gin[g][1] = v.y; gin[g][2] = v.z; gin[g][3] = v.w;
            }
        }
        __syncthreads();

        // gate GEMM: gates[b][c] = h[b][:] . Wh[:][c]  (f32x2, k-pair packed)
        ull acc[4][2];
#pragma unroll
        for (int q = 0; q < 4; q++) { acc[q][0] = 0ull; acc[q][1] = 0ull; }
#pragma unroll 4
        for (int kk = 0; kk < 256; kk++) {
            const ull w0 = Whs[kk * 16 + 2 * c2];
            const ull w1 = Whs[kk * 16 + 2 * c2 + 1];
#pragma unroll
            for (int q = 0; q < 4; q++) {
                const ull hv = hs[kk * 64 + bq + 16 * q];
                acc[q][0] = fma2(hv, w0, acc[q][0]);
                acc[q][1] = fma2(hv, w1, acc[q][1]);
            }
        }
#pragma unroll
        for (int q = 0; q < 4; q++) {
            const int b = bq + 16 * q;
            gs[(2 * c2) * 64 + b]     = lo32(acc[q][0]) + hi32(acc[q][0]);
            gs[(2 * c2 + 1) * 64 + b] = lo32(acc[q][1]) + hi32(acc[q][1]);
        }
        __syncthreads();

        // pointwise LSTM cell (one thread per batch element)
        if (tid < kB) {
            const int b = tid;
            float hv[4], cv[4];
#pragma unroll
            for (int u = 0; u < 4; u++) {
                const float iv = sigf(gs[(0  + u) * 64 + b] + gin[0][u]);
                const float fv = sigf(gs[(4  + u) * 64 + b] + gin[1][u]);
                const float gv = tanh_(gs[(8  + u) * 64 + b] + gin[2][u]);
                const float ov = sigf(gs[(12 + u) * 64 + b] + gin[3][u]);
                const float cn = fv * cs[u * 64 + b] + iv * gv;
                cs[u * 64 + b] = cn;
                cv[u] = cn;
                hv[u] = ov * tanh_(cn);
            }
            *(float4*)(seqout + ((size_t)b * kT + t) * kH + j0) =
                make_float4(hv[0], hv[1], hv[2], hv[3]);
            const int nxt = cur ^ 1;
            g_hbuf[nxt][cta * 2][b]     = make_float2(hv[0], hv[1]);
            g_hbuf[nxt][cta * 2 + 1][b] = make_float2(hv[2], hv[3]);
            if (t == kT - 1) {
                *(float4*)(hT + (size_t)b * kH + j0) =
                    make_float4(hv[0], hv[1], hv[2], hv[3]);
                *(float4*)(cT + (size_t)b * kH + j0) =
                    make_float4(cv[0], cv[1], cv[2], cv[3]);
            }
        }
        __threadfence();
        gbar(2 + t, tid);
    }
}

// ---------------- launch ------------------------------------------------------
extern "C" void kernel_launch(void* const* d_in, const int* in_sizes, int n_in,
                              void* d_out, int out_size)
{
    const float* x  = (const float*)d_in[0];
    const float* Wi = (const float*)d_in[1];
    const float* Wh = (const float*)d_in[2];
    const float* bi = (const float*)d_in[3];
    const float* bh = (const float*)d_in[4];

    float* out  = (float*)d_out;
    float* outs = out;                                  // [B,T,H]
    float* hT   = out + (size_t)kB * kT * kH;           // [L,B,H]
    float* cT   = hT + (size_t)2 * kB * kH;             // [L,B,H]

    float* Gp;  cudaGetSymbolAddress((void**)&Gp,  g_G);
    float* h0p; cudaGetSymbolAddress((void**)&h0p, g_h0);

    const size_t smem = (size_t)(256 * 64 + 256 * 16) * sizeof(ull)
                      + (16 * 64 + 4 * 64) * sizeof(float);  // 168960 B
    cudaFuncSetAttribute(lstm_recur, cudaFuncAttributeMaxDynamicSharedMemorySize,
                         (int)smem);

    dim3 ggrid(256, 32);

    // layer 0
    gemm_inproj<<<ggrid, 256>>>(x, Wi, bi, bh, Gp);
    lstm_recur<<<kNCTA, 128, smem>>>(Gp, Wh, h0p, hT, cT);
    // layer 1
    gemm_inproj<<<ggrid, 256>>>(h0p, Wi + (size_t)kH * kG, bi + kG, bh + kG, Gp);
    lstm_recur<<<kNCTA, 128, smem>>>(Gp, Wh + (size_t)kH * kG,
                                     outs, hT + (size_t)kB * kH,
                                     cT + (size_t)kB * kH);
}

// round 2
// speedup vs baseline: 1.4032x; 1.4032x over previous
#include <cuda_runtime.h>
#include <cstdint>

typedef unsigned long long ull;

constexpr int kB = 64;      // batch
constexpr int kT = 256;     // time
constexpr int kH = 512;     // hidden
constexpr int kG = 2048;    // 4*H gate cols
constexpr int kNCTA = 128;  // persistent recurrence CTAs

// ---------------- scratch ----------------------------------------------------
__device__ float  g_G[(size_t)kB * kT * kG];    // input projections (128 MB)
__device__ float  g_h0[(size_t)kB * kT * kH];   // layer-0 output sequence (32 MB)
__device__ float4 g_hbuf[2][kH / 4][kB];        // ping-pong h: [quad][b] = h[4q..4q+3]
__device__ int            g_count;
__device__ volatile int   g_flag;

// ---------------- helpers ----------------------------------------------------
__device__ __forceinline__ ull fma2(ull a, ull b, ull c) {
    ull d;
    asm("fma.rn.f32x2 %0, %1, %2, %3;" : "=l"(d) : "l"(a), "l"(b), "l"(c));
    return d;
}
__device__ __forceinline__ float lo32(ull v) { return __uint_as_float((unsigned)v); }
__device__ __forceinline__ float hi32(ull v) { return __uint_as_float((unsigned)(v >> 32)); }

__device__ __forceinline__ float sigf(float x) {
    x = fminf(fmaxf(x, -30.f), 30.f);
    return 1.f / (1.f + __expf(-x));
}
__device__ __forceinline__ float tanh_(float x) {
    x = fminf(fmaxf(x, -15.f), 15.f);
    float e = __expf(-2.f * x);
    return (1.f - e) / (1.f + e);
}

// ---------------- input-projection GEMM --------------------------------------
// C[m][n] = A[m][:] . W[:][n] + bi[n] + bh[n]
// M=16384, N=2048, K=512. 128x64 block tile, 256 threads, 8x4 thread tile,
// f32x2 packed along k-pairs, double-buffered SMEM.
__global__ void __launch_bounds__(256, 2)
gemm_inproj(const float* __restrict__ A, const float* __restrict__ W,
            const float* __restrict__ bi, const float* __restrict__ bh,
            float* __restrict__ C)
{
    if (blockIdx.x == 0 && blockIdx.y == 0 && threadIdx.x == 0) {
        g_count = 0;
        g_flag = 0;
    }
    __shared__ ull As[2][8][128];   // [buf][k-pair][m]
    __shared__ ull Bs[2][8][64];    // [buf][k-pair][n]

    const int tid = threadIdx.x;
    const int m0 = blockIdx.x * 128;
    const int n0 = blockIdx.y * 64;
    const int tx = tid & 15;        // n base
    const int ty = tid >> 4;        // m octet (0..15)

    // staging indices
    const int ar0 = tid >> 2;           // A rows for j=0 (0..63)
    const int akf = tid & 3;            // which float4 along k-tile
    const int brk = tid >> 4;           // B k-row (0..15)
    const int bnf = (tid & 15) * 4;     // B n offset

    auto stageA = [&](int buf, float4 a0, float4 a1) {
        ((float2*)&As[buf][2 * akf][ar0])[0]           = make_float2(a0.x, a0.y);
        ((float2*)&As[buf][2 * akf + 1][ar0])[0]       = make_float2(a0.z, a0.w);
        ((float2*)&As[buf][2 * akf][ar0 + 64])[0]      = make_float2(a1.x, a1.y);
        ((float2*)&As[buf][2 * akf + 1][ar0 + 64])[0]  = make_float2(a1.z, a1.w);
    };
    auto stageB = [&](int buf, float4 b4) {
        float* bd = (float*)&Bs[buf][brk >> 1][0];
        const int pb = brk & 1;
        bd[(bnf + 0) * 2 + pb] = b4.x;
        bd[(bnf + 1) * 2 + pb] = b4.y;
        bd[(bnf + 2) * 2 + pb] = b4.z;
        bd[(bnf + 3) * 2 + pb] = b4.w;
    };
    auto loadA = [&](int kt, int j) -> float4 {
        return *(const float4*)&A[(size_t)(m0 + ar0 + 64 * j) * kH + kt * 16 + akf * 4];
    };
    auto loadB = [&](int kt) -> float4 {
        return *(const float4*)&W[(size_t)(kt * 16 + brk) * kG + n0 + bnf];
    };

    // prologue
    stageA(0, loadA(0, 0), loadA(0, 1));
    stageB(0, loadB(0));
    __syncthreads();

    ull acc[8][4];
#pragma unroll
    for (int i = 0; i < 8; i++)
#pragma unroll
        for (int q = 0; q < 4; q++) acc[i][q] = 0ull;

    for (int kt = 0; kt < 32; kt++) {
        const int cur = kt & 1;
        float4 a0, a1, b4;
        const bool more = (kt < 31);
        if (more) {
            a0 = loadA(kt + 1, 0);
            a1 = loadA(kt + 1, 1);
            b4 = loadB(kt + 1);
        }
#pragma unroll
        for (int kk = 0; kk < 8; kk++) {
            ulonglong2 a2[4];
            ull b[4];
#pragma unroll
            for (int j2 = 0; j2 < 4; j2++)
                a2[j2] = *(const ulonglong2*)&As[cur][kk][ty * 8 + 2 * j2];
#pragma unroll
            for (int q = 0; q < 4; q++) b[q] = Bs[cur][kk][tx + 16 * q];
#pragma unroll
            for (int j2 = 0; j2 < 4; j2++)
#pragma unroll
                for (int q = 0; q < 4; q++) {
                    acc[2 * j2][q]     = fma2(a2[j2].x, b[q], acc[2 * j2][q]);
                    acc[2 * j2 + 1][q] = fma2(a2[j2].y, b[q], acc[2 * j2 + 1][q]);
                }
        }
        if (more) {
            stageA(cur ^ 1, a0, a1);
            stageB(cur ^ 1, b4);
        }
        __syncthreads();
    }

#pragma unroll
    for (int q = 0; q < 4; q++) {
        const int n = n0 + tx + 16 * q;
        const float bias = __ldg(bi + n) + __ldg(bh + n);
#pragma unroll
        for (int i = 0; i < 8; i++) {
            const int m = m0 + ty * 8 + i;
            C[(size_t)m * kG + n] = lo32(acc[i][q]) + hi32(acc[i][q]) + bias;
        }
    }
}

// ---------------- global barrier (all 128 persistent CTAs) -------------------
__device__ __forceinline__ void gbar(int idx, int tid)
{
    __syncthreads();
    if (tid == 0) {
        const int prev = atomicAdd(&g_count, 1);
        if (prev == idx * kNCTA - 1) {
            atomicExch((int*)&g_flag, idx);
        } else {
            while (g_flag < idx) { }
        }
        __threadfence();
    }
    __syncthreads();
}

// ---------------- persistent LSTM recurrence ---------------------------------
// 128 CTAs x 256 threads. CTA owns 4 hidden units (16 gate cols).
// Thread layout: tid = kq*64 + cq*16 + bq   (kq: k-quarter, cq: col-quarter)
// Each k-group (64 threads, 2 warps) stages ONLY its own 32KB h-chunk and
// computes on it; partial gate sums are reduced via gs[4][16][64].
// SMEM: hs 128KB | Whs 32KB | gs 16KB | cs 1KB.
extern __shared__ ull s_mem[];

__global__ void __launch_bounds__(256, 1)
lstm_recur(const float* __restrict__ G, const float* __restrict__ Wh,
           float* __restrict__ seqout, float* __restrict__ hT,
           float* __restrict__ cT)
{
    ulonglong2* hs2  = (ulonglong2*)s_mem;          // [128 quad][64 b]
    ulonglong2* Whs2 = hs2 + 128 * 64;              // [128 quad][16 col]
    float*      gs   = (float*)(Whs2 + 128 * 16);   // [4 kq][16 col][64 b]
    float*      cs   = gs + 4 * 16 * 64;            // [4 u][64 b]

    const int tid = threadIdx.x;
    const int cta = blockIdx.x;
    const int j0  = cta * 4;

    const int kq = tid >> 6;         // 0..3
    const int lt = tid & 63;
    const int cq = (tid >> 4) & 3;   // 0..3 (4 gate cols each)
    const int bq = tid & 15;

    // stage Wh slice: Whs2[quad][c] = { wpair(2quad,c), wpair(2quad+1,c) }
    // where wpair(kp,c) = (Wh[2kp][gc], Wh[2kp+1][gc]), gc = g*kH + j0 + u, c = g*4+u
    for (int k = tid; k < kH; k += 256) {
        const int quad = k >> 2;
        const int p    = (k >> 1) & 1;
        const int par  = k & 1;
#pragma unroll
        for (int g = 0; g < 4; g++) {
            float4 w = *(const float4*)(Wh + (size_t)k * kG + g * kH + j0);
            float* d0 = (float*)&Whs2[quad * 16 + g * 4 + 0];
            float* d1 = (float*)&Whs2[quad * 16 + g * 4 + 1];
            float* d2 = (float*)&Whs2[quad * 16 + g * 4 + 2];
            float* d3 = (float*)&Whs2[quad * 16 + g * 4 + 3];
            d0[p * 2 + par] = w.x;
            d1[p * 2 + par] = w.y;
            d2[p * 2 + par] = w.z;
            d3[p * 2 + par] = w.w;
        }
    }
    // zero h ping buffer (own quad) and cell state
    if (tid < kB) g_hbuf[0][cta][tid] = make_float4(0.f, 0.f, 0.f, 0.f);
    cs[tid] = 0.f;
    __threadfence();
    gbar(1, tid);

    for (int t = 0; t < kT; t++) {
        const int cur = t & 1;

        // prefetch this step's input projection (pointwise threads)
        float gin[4][4];
        if (tid < kB) {
            const float* gp = G + ((size_t)tid * kT + t) * kG + j0;
#pragma unroll
            for (int g = 0; g < 4; g++) {
                float4 v = __ldcs((const float4*)(gp + g * kH));
                gin[g][0] = v.x; gin[g][1] = v.y; gin[g][2] = v.z; gin[g][3] = v.w;
            }
        }

        // stage ONLY this k-group's h chunk (quads kq*32 .. kq*32+32)
        {
            const float4* src = &g_hbuf[cur][0][0];
#pragma unroll 8
            for (int j = 0; j < 32; j++) {
                const int idx = kq * 2048 + j * 64 + lt;
                float4 v = __ldcg(src + idx);
                hs2[idx] = *(ulonglong2*)&v;
            }
        }
        // sync the 2 warps of this k-group (named barrier kq+1)
        asm volatile("bar.sync %0, 64;" :: "r"(kq + 1) : "memory");

        // partial gate GEMM over this k-chunk
        ull acc[4][4];   // [batch q][col c]
#pragma unroll
        for (int q = 0; q < 4; q++)
#pragma unroll
            for (int c = 0; c < 4; c++) acc[q][c] = 0ull;

        const int q0 = kq * 32;
#pragma unroll 4
        for (int Q = 0; Q < 32; Q++) {
            const int quad = q0 + Q;
            ulonglong2 wv[4];
#pragma unroll
            for (int c = 0; c < 4; c++)
                wv[c] = Whs2[quad * 16 + cq * 4 + c];
#pragma unroll
            for (int q = 0; q < 4; q++) {
                const ulonglong2 hv = hs2[quad * 64 + bq + 16 * q];
#pragma unroll
                for (int c = 0; c < 4; c++) {
                    acc[q][c] = fma2(hv.x, wv[c].x, acc[q][c]);
                    acc[q][c] = fma2(hv.y, wv[c].y, acc[q][c]);
                }
            }
        }
#pragma unroll
        for (int q = 0; q < 4; q++) {
            const int b = bq + 16 * q;
#pragma unroll
            for (int c = 0; c < 4; c++)
                gs[(kq * 16 + cq * 4 + c) * 64 + b] =
                    lo32(acc[q][c]) + hi32(acc[q][c]);
        }
        __syncthreads();

        // pointwise LSTM cell (one thread per batch element)
        if (tid < kB) {
            const int b = tid;
            float hv[4], cv[4];
#pragma unroll
            for (int u = 0; u < 4; u++) {
                float pre[4];
#pragma unroll
                for (int g = 0; g < 4; g++) {
                    const int c = g * 4 + u;
                    pre[g] = gin[g][u]
                           + gs[(0 * 16 + c) * 64 + b]
                           + gs[(1 * 16 + c) * 64 + b]
                           + gs[(2 * 16 + c) * 64 + b]
                           + gs[(3 * 16 + c) * 64 + b];
                }
                const float iv = sigf(pre[0]);
                const float fv = sigf(pre[1]);
                const float gv = tanh_(pre[2]);
                const float ov = sigf(pre[3]);
                const float cn = fv * cs[u * 64 + b] + iv * gv;
                cs[u * 64 + b] = cn;
                cv[u] = cn;
                hv[u] = ov * tanh_(cn);
            }
            *(float4*)(seqout + ((size_t)b * kT + t) * kH + j0) =
                make_float4(hv[0], hv[1], hv[2], hv[3]);
            g_hbuf[cur ^ 1][cta][b] = make_float4(hv[0], hv[1], hv[2], hv[3]);
            if (t == kT - 1) {
                *(float4*)(hT + (size_t)b * kH + j0) =
                    make_float4(hv[0], hv[1], hv[2], hv[3]);
                *(float4*)(cT + (size_t)b * kH + j0) =
                    make_float4(cv[0], cv[1], cv[2], cv[3]);
            }
            __threadfence();
        }
        gbar(2 + t, tid);
    }
}

// ---------------- launch ------------------------------------------------------
extern "C" void kernel_launch(void* const* d_in, const int* in_sizes, int n_in,
                              void* d_out, int out_size)
{
    const float* x  = (const float*)d_in[0];
    const float* Wi = (const float*)d_in[1];
    const float* Wh = (const float*)d_in[2];
    const float* bi = (const float*)d_in[3];
    const float* bh = (const float*)d_in[4];

    float* out  = (float*)d_out;
    float* outs = out;                                  // [B,T,H]
    float* hT   = out + (size_t)kB * kT * kH;           // [L,B,H]
    float* cT   = hT + (size_t)2 * kB * kH;             // [L,B,H]

    float* Gp;  cudaGetSymbolAddress((void**)&Gp,  g_G);
    float* h0p; cudaGetSymbolAddress((void**)&h0p, g_h0);

    const size_t smem = (size_t)(128 * 64 + 128 * 16) * sizeof(ulonglong2)
                      + (4 * 16 * 64 + 4 * 64) * sizeof(float);  // ~181 KB
    cudaFuncSetAttribute(lstm_recur, cudaFuncAttributeMaxDynamicSharedMemorySize,
                         (int)smem);

    dim3 ggrid(128, 32);

    // layer 0
    gemm_inproj<<<ggrid, 256>>>(x, Wi, bi, bh, Gp);
    lstm_recur<<<kNCTA, 256, smem>>>(Gp, Wh, h0p, hT, cT);
    // layer 1
    gemm_inproj<<<ggrid, 256>>>(h0p, Wi + (size_t)kH * kG, bi + kG, bh + kG, Gp);
    lstm_recur<<<kNCTA, 256, smem>>>(Gp, Wh + (size_t)kH * kG,
                                     outs, hT + (size_t)kB * kH,
                                     cT + (size_t)kB * kH);
}

// round 3
// speedup vs baseline: 1.5876x; 1.1314x over previous
#include <cuda_runtime.h>
#include <cstdint>

typedef unsigned long long ull;

constexpr int kB = 64;      // batch
constexpr int kT = 256;     // time
constexpr int kH = 512;     // hidden
constexpr int kG = 2048;    // 4*H gate cols
constexpr int kCG = 32;     // column groups (16 hidden units each)
constexpr int kBG = 4;      // batch groups (16 batch elements each)
constexpr int kGrpCTA = kCG;  // CTAs per barrier group

// ---------------- scratch ----------------------------------------------------
__device__ float  g_G[(size_t)kB * kT * kG];    // input projections (128 MB)
__device__ float  g_h0[(size_t)kB * kT * kH];   // layer-0 output sequence (32 MB)
__device__ float4 g_hbuf[2][kH / 4][kB];        // ping-pong h: [quad][b] = h[4q..4q+3]
__device__ int           g_cnt[kBG * 32];       // per-batch-group barrier counters
__device__ volatile int  g_flg[kBG * 32];       // per-batch-group barrier flags

// ---------------- helpers ----------------------------------------------------
__device__ __forceinline__ ull fma2(ull a, ull b, ull c) {
    ull d;
    asm("fma.rn.f32x2 %0, %1, %2, %3;" : "=l"(d) : "l"(a), "l"(b), "l"(c));
    return d;
}
__device__ __forceinline__ float lo32(ull v) { return __uint_as_float((unsigned)v); }
__device__ __forceinline__ float hi32(ull v) { return __uint_as_float((unsigned)(v >> 32)); }

__device__ __forceinline__ float sigf(float x) {
    x = fminf(fmaxf(x, -30.f), 30.f);
    return 1.f / (1.f + __expf(-x));
}
__device__ __forceinline__ float tanh_(float x) {
    x = fminf(fmaxf(x, -15.f), 15.f);
    float e = __expf(-2.f * x);
    return (1.f - e) / (1.f + e);
}

// ---------------- input-projection GEMM --------------------------------------
// C[m][n] = A[m][:] . W[:][n] + bi[n] + bh[n]
// M=16384, N=2048, K=512. 128x64 block tile, 256 threads, 8x4 thread tile.
// Also resets the group-barrier state for the following recurrence kernel.
__global__ void __launch_bounds__(256, 2)
gemm_inproj(const float* __restrict__ A, const float* __restrict__ W,
            const float* __restrict__ bi, const float* __restrict__ bh,
            float* __restrict__ C)
{
    if (blockIdx.x == 0 && blockIdx.y == 0 && threadIdx.x < kBG) {
        g_cnt[threadIdx.x * 32] = 0;
        g_flg[threadIdx.x * 32] = 0;
    }
    __shared__ ull As[2][8][128];   // [buf][k-pair][m]
    __shared__ ull Bs[2][8][64];    // [buf][k-pair][n]

    const int tid = threadIdx.x;
    const int m0 = blockIdx.x * 128;
    const int n0 = blockIdx.y * 64;
    const int tx = tid & 15;
    const int ty = tid >> 4;

    const int ar0 = tid >> 2;
    const int akf = tid & 3;
    const int brk = tid >> 4;
    const int bnf = (tid & 15) * 4;

    auto stageA = [&](int buf, float4 a0, float4 a1) {
        ((float2*)&As[buf][2 * akf][ar0])[0]           = make_float2(a0.x, a0.y);
        ((float2*)&As[buf][2 * akf + 1][ar0])[0]       = make_float2(a0.z, a0.w);
        ((float2*)&As[buf][2 * akf][ar0 + 64])[0]      = make_float2(a1.x, a1.y);
        ((float2*)&As[buf][2 * akf + 1][ar0 + 64])[0]  = make_float2(a1.z, a1.w);
    };
    auto stageB = [&](int buf, float4 b4) {
        float* bd = (float*)&Bs[buf][brk >> 1][0];
        const int pb = brk & 1;
        bd[(bnf + 0) * 2 + pb] = b4.x;
        bd[(bnf + 1) * 2 + pb] = b4.y;
        bd[(bnf + 2) * 2 + pb] = b4.z;
        bd[(bnf + 3) * 2 + pb] = b4.w;
    };
    auto loadA = [&](int kt, int j) -> float4 {
        return *(const float4*)&A[(size_t)(m0 + ar0 + 64 * j) * kH + kt * 16 + akf * 4];
    };
    auto loadB = [&](int kt) -> float4 {
        return *(const float4*)&W[(size_t)(kt * 16 + brk) * kG + n0 + bnf];
    };

    stageA(0, loadA(0, 0), loadA(0, 1));
    stageB(0, loadB(0));
    __syncthreads();

    ull acc[8][4];
#pragma unroll
    for (int i = 0; i < 8; i++)
#pragma unroll
        for (int q = 0; q < 4; q++) acc[i][q] = 0ull;

    for (int kt = 0; kt < 32; kt++) {
        const int cur = kt & 1;
        float4 a0, a1, b4;
        const bool more = (kt < 31);
        if (more) {
            a0 = loadA(kt + 1, 0);
            a1 = loadA(kt + 1, 1);
            b4 = loadB(kt + 1);
        }
#pragma unroll
        for (int kk = 0; kk < 8; kk++) {
            ulonglong2 a2[4];
            ull b[4];
#pragma unroll
            for (int j2 = 0; j2 < 4; j2++)
                a2[j2] = *(const ulonglong2*)&As[cur][kk][ty * 8 + 2 * j2];
#pragma unroll
            for (int q = 0; q < 4; q++) b[q] = Bs[cur][kk][tx + 16 * q];
#pragma unroll
            for (int j2 = 0; j2 < 4; j2++)
#pragma unroll
                for (int q = 0; q < 4; q++) {
                    acc[2 * j2][q]     = fma2(a2[j2].x, b[q], acc[2 * j2][q]);
                    acc[2 * j2 + 1][q] = fma2(a2[j2].y, b[q], acc[2 * j2 + 1][q]);
                }
        }
        if (more) {
            stageA(cur ^ 1, a0, a1);
            stageB(cur ^ 1, b4);
        }
        __syncthreads();
    }

#pragma unroll
    for (int q = 0; q < 4; q++) {
        const int n = n0 + tx + 16 * q;
        const float bias = __ldg(bi + n) + __ldg(bh + n);
#pragma unroll
        for (int i = 0; i < 8; i++) {
            const int m = m0 + ty * 8 + i;
            C[(size_t)m * kG + n] = lo32(acc[i][q]) + hi32(acc[i][q]) + bias;
        }
    }
}

// ---------------- persistent LSTM recurrence ---------------------------------
// 128 CTAs = 32 col-groups (cg) x 4 batch-groups (bg), 256 threads.
// CTA owns 16 hidden units (cols cg*16..+15 in each of 4 gate blocks) for the
// 16 batch elements bg*16..+15. Barrier is scoped to the 32 CTAs of one bg.
// SMEM: Whs 128KB | hs 32KB | gs 17KB | cs 1.1KB  (~179KB total)
extern __shared__ ull s_mem[];

__global__ void __launch_bounds__(256, 1)
lstm_recur(const float* __restrict__ G, const float* __restrict__ Wh,
           float* __restrict__ seqout, float* __restrict__ hT,
           float* __restrict__ cT)
{
    ulonglong2* Whs = (ulonglong2*)s_mem;           // [128 quad][64 c]
    ulonglong2* hs  = Whs + 128 * 64;               // [128 quad][16 b]
    float*      gs  = (float*)(hs + 128 * 16);      // [4 kq][64 c][17]
    float*      cs  = gs + 4 * 64 * 17;             // [16 u][17]

    const int tid = threadIdx.x;
    const int cg  = blockIdx.x >> 2;     // 0..31
    const int bg  = blockIdx.x & 3;      // 0..3
    const int u0  = cg * 16;             // first hidden unit owned

    // GEMM thread layout: tid = kq*64 + ct*4 + bt
    const int kq = tid >> 6;             // k-quarter (32 quads each)
    const int lt = tid & 63;
    const int ct = (tid >> 2) & 15;      // 4 cols each -> 64 cols
    const int bt = tid & 3;              // 4 batches each -> 16 b

    // pointwise layout: tid = b*16 + u
    const int pb = tid >> 4;             // local batch 0..15
    const int pu = tid & 15;             // local unit 0..15
    const int bglob = bg * 16 + pb;

    // ---- stage Wh slice: Whs[quad][c] holds k=4q..4q+3 for col c (c=g*16+uu)
    for (int k = tid; k < kH; k += 256) {
        const int quad = k >> 2;
        const int comp = k & 3;
#pragma unroll
        for (int g = 0; g < 4; g++) {
#pragma unroll
            for (int v = 0; v < 4; v++) {
                float4 w = *(const float4*)(Wh + (size_t)k * kG + g * kH + u0 + v * 4);
                float* d = (float*)&Whs[quad * 64 + g * 16 + v * 4];
                d[0 * 4 + comp]  = w.x;   // note: each ulonglong2 = 4 floats
                d[1 * 4 + comp]  = w.y;
                d[2 * 4 + comp]  = w.z;
                d[3 * 4 + comp]  = w.w;
            }
        }
    }
    // zero our slice of h ping buffer (parity 0) and cell state
    {
        // our produced h: units u0..u0+15 (quads cg*4..cg*4+3), batches bglob set
        if (tid < 64) {
            const int q = cg * 4 + (tid >> 4);
            const int b = bg * 16 + (tid & 15);
            g_hbuf[0][q][b] = make_float4(0.f, 0.f, 0.f, 0.f);
        }
        cs[pu * 17 + pb] = 0.f;
    }
    __threadfence();
    // ---- group barrier (idx 1)
    {
        __syncthreads();
        if (tid == 0) {
            const int prev = atomicAdd(&g_cnt[bg * 32], 1);
            if (prev == 1 * kGrpCTA - 1) atomicExch((int*)&g_flg[bg * 32], 1);
            else while (g_flg[bg * 32] < 1) { }
            __threadfence();
        }
        __syncthreads();
    }

    for (int t = 0; t < kT; t++) {
        const int cur = t & 1;

        // prefetch this step's input projection for (pb, pu)
        float gin[4];
        {
            const float* gp = G + ((size_t)bglob * kT + t) * kG + u0 + pu;
#pragma unroll
            for (int g = 0; g < 4; g++)
                gin[g] = __ldcs(gp + g * kH);
        }

        // stage this k-group's h chunk: quads kq*32..+32, 16 batches (8 elems/thread)
        {
#pragma unroll
            for (int j = 0; j < 8; j++) {
                const int e = kq * 512 + j * 64 + lt;
                const int quad = e >> 4;
                const int b = e & 15;
                float4 v = __ldcg(&g_hbuf[cur][quad][bg * 16 + b]);
                hs[e] = *(ulonglong2*)&v;
            }
        }
        asm volatile("bar.sync %0, 64;" :: "r"(kq + 1) : "memory");

        // partial gate GEMM over this k-chunk: acc[b'][c'] (4x4)
        ull acc[4][4];
#pragma unroll
        for (int j = 0; j < 4; j++)
#pragma unroll
            for (int i = 0; i < 4; i++) acc[j][i] = 0ull;

        const int q0 = kq * 32;
#pragma unroll 4
        for (int Q = 0; Q < 32; Q++) {
            const int quad = q0 + Q;
            ulonglong2 wv[4], hv[4];
#pragma unroll
            for (int i = 0; i < 4; i++)
                wv[i] = Whs[quad * 64 + ct * 4 + i];
#pragma unroll
            for (int j = 0; j < 4; j++)
                hv[j] = hs[quad * 16 + bt + 4 * j];
#pragma unroll
            for (int j = 0; j < 4; j++)
#pragma unroll
                for (int i = 0; i < 4; i++) {
                    acc[j][i] = fma2(hv[j].x, wv[i].x, acc[j][i]);
                    acc[j][i] = fma2(hv[j].y, wv[i].y, acc[j][i]);
                }
        }
#pragma unroll
        for (int j = 0; j < 4; j++) {
            const int b = bt + 4 * j;
#pragma unroll
            for (int i = 0; i < 4; i++)
                gs[(kq * 64 + ct * 4 + i) * 17 + b] =
                    lo32(acc[j][i]) + hi32(acc[j][i]);
        }
        __syncthreads();

        // pointwise LSTM cell: one thread per (batch, unit)
        {
            float pre[4];
#pragma unroll
            for (int g = 0; g < 4; g++) {
                const int c = g * 16 + pu;
                pre[g] = gin[g]
                       + gs[(0 * 64 + c) * 17 + pb]
                       + gs[(1 * 64 + c) * 17 + pb]
                       + gs[(2 * 64 + c) * 17 + pb]
                       + gs[(3 * 64 + c) * 17 + pb];
            }
            const float iv = sigf(pre[0]);
            const float fv = sigf(pre[1]);
            const float gv = tanh_(pre[2]);
            const float ov = sigf(pre[3]);
            const float cn = fv * cs[pu * 17 + pb] + iv * gv;
            cs[pu * 17 + pb] = cn;
            const float hv = ov * tanh_(cn);

            seqout[((size_t)bglob * kT + t) * kH + u0 + pu] = hv;
            float* hb = (float*)&g_hbuf[cur ^ 1][cg * 4 + (pu >> 2)][bglob];
            hb[pu & 3] = hv;
            if (t == kT - 1) {
                hT[(size_t)bglob * kH + u0 + pu] = hv;
                cT[(size_t)bglob * kH + u0 + pu] = cn;
            }
            __threadfence();
        }

        // group barrier (idx t+2)
        {
            const int idx = t + 2;
            __syncthreads();
            if (tid == 0) {
                const int prev = atomicAdd(&g_cnt[bg * 32], 1);
                if (prev == idx * kGrpCTA - 1) atomicExch((int*)&g_flg[bg * 32], idx);
                else while (g_flg[bg * 32] < idx) { }
                __threadfence();
            }
            __syncthreads();
        }
    }
}

// ---------------- launch ------------------------------------------------------
extern "C" void kernel_launch(void* const* d_in, const int* in_sizes, int n_in,
                              void* d_out, int out_size)
{
    const float* x  = (const float*)d_in[0];
    const float* Wi = (const float*)d_in[1];
    const float* Wh = (const float*)d_in[2];
    const float* bi = (const float*)d_in[3];
    const float* bh = (const float*)d_in[4];

    float* out  = (float*)d_out;
    float* outs = out;                                  // [B,T,H]
    float* hT   = out + (size_t)kB * kT * kH;           // [L,B,H]
    float* cT   = hT + (size_t)2 * kB * kH;             // [L,B,H]

    float* Gp;  cudaGetSymbolAddress((void**)&Gp,  g_G);
    float* h0p; cudaGetSymbolAddress((void**)&h0p, g_h0);

    const size_t smem = (size_t)(128 * 64 + 128 * 16) * sizeof(ulonglong2)
                      + (4 * 64 * 17 + 16 * 17) * sizeof(float);  // ~179 KB
    cudaFuncSetAttribute(lstm_recur, cudaFuncAttributeMaxDynamicSharedMemorySize,
                         (int)smem);

    dim3 ggrid(128, 32);

    // layer 0
    gemm_inproj<<<ggrid, 256>>>(x, Wi, bi, bh, Gp);
    lstm_recur<<<kCG * kBG, 256, smem>>>(Gp, Wh, h0p, hT, cT);
    // layer 1
    gemm_inproj<<<ggrid, 256>>>(h0p, Wi + (size_t)kH * kG, bi + kG, bh + kG, Gp);
    lstm_recur<<<kCG * kBG, 256, smem>>>(Gp, Wh + (size_t)kH * kG,
                                         outs, hT + (size_t)kB * kH,
                                         cT + (size_t)kB * kH);
}

// round 4
// speedup vs baseline: 1.5964x; 1.0056x over previous
#include <cuda_runtime.h>
#include <cstdint>

typedef unsigned long long ull;

constexpr int kB = 64;      // batch
constexpr int kT = 256;     // time
constexpr int kH = 512;     // hidden
constexpr int kG = 2048;    // 4*H gate cols
constexpr int kCG = 32;     // column groups (16 hidden units each)
constexpr int kBG = 4;      // batch groups (16 batch elements each)
constexpr int kGrpCTA = kCG;  // CTAs per barrier group

// ---------------- scratch ----------------------------------------------------
__device__ float  g_G[(size_t)kB * kT * kG];    // input projections (128 MB)
__device__ float  g_h0[(size_t)kB * kT * kH];   // layer-0 output sequence (32 MB)
__device__ float4 g_hbuf[2][kH / 4][kB];        // ping-pong h: [quad][b] = h[4q..4q+3]
__device__ int g_cnt[kBG * 32];                 // per-batch-group barrier counters
__device__ int g_flg[kBG * 32];                 // per-batch-group barrier flags

// ---------------- helpers ----------------------------------------------------
__device__ __forceinline__ ull fma2(ull a, ull b, ull c) {
    ull d;
    asm("fma.rn.f32x2 %0, %1, %2, %3;" : "=l"(d) : "l"(a), "l"(b), "l"(c));
    return d;
}
__device__ __forceinline__ float lo32(ull v) { return __uint_as_float((unsigned)v); }
__device__ __forceinline__ float hi32(ull v) { return __uint_as_float((unsigned)(v >> 32)); }

__device__ __forceinline__ float sigf(float x) {
    x = fminf(fmaxf(x, -30.f), 30.f);
    return 1.f / (1.f + __expf(-x));
}
__device__ __forceinline__ float tanh_(float x) {
    x = fminf(fmaxf(x, -15.f), 15.f);
    float e = __expf(-2.f * x);
    return (1.f - e) / (1.f + e);
}

// scoped-atomics group barrier: release/acquire, NO threadfence, NO L1 flush
__device__ __forceinline__ void gbar_rel(int idx, int tid, int bg)
{
    __syncthreads();
    if (tid == 0) {
        int* cnt = &g_cnt[bg * 32];
        int* flg = &g_flg[bg * 32];
        int prev;
        asm volatile("atom.acq_rel.gpu.global.add.s32 %0, [%1], 1;"
                     : "=r"(prev) : "l"(cnt) : "memory");
        if (prev == idx * kGrpCTA - 1) {
            int dummy;
            asm volatile("atom.release.gpu.global.exch.b32 %0, [%1], %2;"
                         : "=r"(dummy) : "l"(flg), "r"(idx) : "memory");
        } else {
            int v;
            do {
                asm volatile("ld.acquire.gpu.global.s32 %0, [%1];"
                             : "=r"(v) : "l"(flg) : "memory");
            } while (v < idx);
        }
    }
    __syncthreads();
}

// ---------------- input-projection GEMM --------------------------------------
// C[m][n] = A[m][:] . W[:][n] + bi[n] + bh[n]
// M=16384, N=2048, K=512. 128x64 block tile, 256 threads, 8x4 thread tile.
// Also resets the group-barrier state for the following recurrence kernel.
__global__ void __launch_bounds__(256, 2)
gemm_inproj(const float* __restrict__ A, const float* __restrict__ W,
            const float* __restrict__ bi, const float* __restrict__ bh,
            float* __restrict__ C)
{
    if (blockIdx.x == 0 && blockIdx.y == 0 && threadIdx.x < kBG) {
        g_cnt[threadIdx.x * 32] = 0;
        g_flg[threadIdx.x * 32] = 0;
    }
    __shared__ ull As[2][8][128];   // [buf][k-pair][m]
    __shared__ ull Bs[2][8][64];    // [buf][k-pair][n]

    const int tid = threadIdx.x;
    const int m0 = blockIdx.x * 128;
    const int n0 = blockIdx.y * 64;
    const int tx = tid & 15;
    const int ty = tid >> 4;

    const int ar0 = tid >> 2;
    const int akf = tid & 3;
    const int brk = tid >> 4;
    const int bnf = (tid & 15) * 4;

    auto stageA = [&](int buf, float4 a0, float4 a1) {
        ((float2*)&As[buf][2 * akf][ar0])[0]           = make_float2(a0.x, a0.y);
        ((float2*)&As[buf][2 * akf + 1][ar0])[0]       = make_float2(a0.z, a0.w);
        ((float2*)&As[buf][2 * akf][ar0 + 64])[0]      = make_float2(a1.x, a1.y);
        ((float2*)&As[buf][2 * akf + 1][ar0 + 64])[0]  = make_float2(a1.z, a1.w);
    };
    auto stageB = [&](int buf, float4 b4) {
        float* bd = (float*)&Bs[buf][brk >> 1][0];
        const int pb = brk & 1;
        bd[(bnf + 0) * 2 + pb] = b4.x;
        bd[(bnf + 1) * 2 + pb] = b4.y;
        bd[(bnf + 2) * 2 + pb] = b4.z;
        bd[(bnf + 3) * 2 + pb] = b4.w;
    };
    auto loadA = [&](int kt, int j) -> float4 {
        return *(const float4*)&A[(size_t)(m0 + ar0 + 64 * j) * kH + kt * 16 + akf * 4];
    };
    auto loadB = [&](int kt) -> float4 {
        return *(const float4*)&W[(size_t)(kt * 16 + brk) * kG + n0 + bnf];
    };

    stageA(0, loadA(0, 0), loadA(0, 1));
    stageB(0, loadB(0));
    __syncthreads();

    ull acc[8][4];
#pragma unroll
    for (int i = 0; i < 8; i++)
#pragma unroll
        for (int q = 0; q < 4; q++) acc[i][q] = 0ull;

    for (int kt = 0; kt < 32; kt++) {
        const int cur = kt & 1;
        float4 a0, a1, b4;
        const bool more = (kt < 31);
        if (more) {
            a0 = loadA(kt + 1, 0);
            a1 = loadA(kt + 1, 1);
            b4 = loadB(kt + 1);
        }
#pragma unroll
        for (int kk = 0; kk < 8; kk++) {
            ulonglong2 a2[4];
            ull b[4];
#pragma unroll
            for (int j2 = 0; j2 < 4; j2++)
                a2[j2] = *(const ulonglong2*)&As[cur][kk][ty * 8 + 2 * j2];
#pragma unroll
            for (int q = 0; q < 4; q++) b[q] = Bs[cur][kk][tx + 16 * q];
#pragma unroll
            for (int j2 = 0; j2 < 4; j2++)
#pragma unroll
                for (int q = 0; q < 4; q++) {
                    acc[2 * j2][q]     = fma2(a2[j2].x, b[q], acc[2 * j2][q]);
                    acc[2 * j2 + 1][q] = fma2(a2[j2].y, b[q], acc[2 * j2 + 1][q]);
                }
        }
        if (more) {
            stageA(cur ^ 1, a0, a1);
            stageB(cur ^ 1, b4);
        }
        __syncthreads();
    }

#pragma unroll
    for (int q = 0; q < 4; q++) {
        const int n = n0 + tx + 16 * q;
        const float bias = __ldg(bi + n) + __ldg(bh + n);
#pragma unroll
        for (int i = 0; i < 8; i++) {
            const int m = m0 + ty * 8 + i;
            C[(size_t)m * kG + n] = lo32(acc[i][q]) + hi32(acc[i][q]) + bias;
        }
    }
}

// ---------------- persistent LSTM recurrence ---------------------------------
// 128 CTAs = 32 col-groups (cg) x 4 batch-groups (bg), 512 threads (16 warps).
// CTA owns 16 hidden units (64 gate cols) for 16 batch elements.
// GEMM layout: tid = kq*64 + ct*4 + bt  (kq: k-eighth = 64 k-values, ct: 16
// col-quads, bt: 4 batch lanes). Thread tile 4 cols x 4 batches.
// Pointwise layout: tid<256: tid = pb*16 + pu, cell state in registers.
// SMEM: Whs 128KB | hs 32KB | gs 34KB  (~194KB, 1 CTA/SM)
extern __shared__ ull s_mem[];

__global__ void __launch_bounds__(512, 1)
lstm_recur(const float* __restrict__ G, const float* __restrict__ Wh,
           float* __restrict__ seqout, float* __restrict__ hT,
           float* __restrict__ cT)
{
    ulonglong2* Whs = (ulonglong2*)s_mem;           // [128 quad][64 c]
    ulonglong2* hs  = Whs + 128 * 64;               // [128 quad][16 b]
    float*      gs  = (float*)(hs + 128 * 16);      // [8 kq][64 c][17]

    const int tid = threadIdx.x;
    const int cg  = blockIdx.x >> 2;     // 0..31
    const int bg  = blockIdx.x & 3;      // 0..3
    const int u0  = cg * 16;

    // GEMM layout
    const int kq = tid >> 6;             // 0..7 (16 quads each)
    const int lt = tid & 63;
    const int ct = (tid >> 2) & 15;
    const int bt = tid & 3;

    // pointwise layout (threads 0..255)
    const int pb = (tid >> 4) & 15;
    const int pu = tid & 15;
    const int bglob = bg * 16 + pb;
    const bool pw = (tid < 256);

    // ---- stage Wh slice: Whs[quad][c] holds k=4q..4q+3 for col c (c=g*16+uu)
    {
        const int k = tid;               // 512 threads = 512 k, one each
        const int quad = k >> 2;
        const int comp = k & 3;
#pragma unroll
        for (int g = 0; g < 4; g++) {
#pragma unroll
            for (int v = 0; v < 4; v++) {
                float4 w = *(const float4*)(Wh + (size_t)k * kG + g * kH + u0 + v * 4);
                float* d = (float*)&Whs[quad * 64 + g * 16 + v * 4];
                d[0 * 4 + comp] = w.x;
                d[1 * 4 + comp] = w.y;
                d[2 * 4 + comp] = w.z;
                d[3 * 4 + comp] = w.w;
            }
        }
    }
    // zero our slice of the h ping buffer (parity 0)
    if (tid < 64) {
        const int q = cg * 4 + (tid >> 4);
        const int b = bg * 16 + (tid & 15);
        g_hbuf[0][q][b] = make_float4(0.f, 0.f, 0.f, 0.f);
    }
    float c_state = 0.f;   // cell state for (bglob, u0+pu), pointwise threads

    gbar_rel(1, tid, bg);

    for (int t = 0; t < kT; t++) {
        const int cur = t & 1;

        // prefetch this step's input projection (pointwise threads)
        float gin0, gin1, gin2, gin3;
        if (pw) {
            const float* gp = G + ((size_t)bglob * kT + t) * kG + u0 + pu;
            gin0 = __ldcs(gp);
            gin1 = __ldcs(gp + kH);
            gin2 = __ldcs(gp + 2 * kH);
            gin3 = __ldcs(gp + 3 * kH);
        }

        // stage this k-group's h chunk (16 quads x 16 b = 256 ull2, 4/thread)
        {
#pragma unroll
            for (int j = 0; j < 4; j++) {
                const int e = kq * 256 + j * 64 + lt;
                const int quad = e >> 4;
                const int b = e & 15;
                float4 v = __ldcg(&g_hbuf[cur][quad][bg * 16 + b]);
                hs[e] = *(ulonglong2*)&v;
            }
        }
        asm volatile("bar.sync %0, 64;" :: "r"(kq + 1) : "memory");

        // partial gate GEMM over this k-chunk: acc[b'][c'] (4x4)
        ull acc[4][4];
#pragma unroll
        for (int j = 0; j < 4; j++)
#pragma unroll
            for (int i = 0; i < 4; i++) acc[j][i] = 0ull;

        const int q0 = kq * 16;
#pragma unroll 2
        for (int Q = 0; Q < 16; Q++) {
            const int quad = q0 + Q;
            ulonglong2 wv[4], hv[4];
#pragma unroll
            for (int i = 0; i < 4; i++)
                wv[i] = Whs[quad * 64 + ct * 4 + i];
#pragma unroll
            for (int j = 0; j < 4; j++)
                hv[j] = hs[quad * 16 + bt + 4 * j];
#pragma unroll
            for (int j = 0; j < 4; j++)
#pragma unroll
                for (int i = 0; i < 4; i++) {
                    acc[j][i] = fma2(hv[j].x, wv[i].x, acc[j][i]);
                    acc[j][i] = fma2(hv[j].y, wv[i].y, acc[j][i]);
                }
        }
#pragma unroll
        for (int j = 0; j < 4; j++) {
            const int b = bt + 4 * j;
#pragma unroll
            for (int i = 0; i < 4; i++)
                gs[(kq * 64 + ct * 4 + i) * 17 + b] =
                    lo32(acc[j][i]) + hi32(acc[j][i]);
        }
        __syncthreads();

        // pointwise LSTM cell: one thread per (batch, unit), c in register
        if (pw) {
            float pre0 = gin0, pre1 = gin1, pre2 = gin2, pre3 = gin3;
#pragma unroll
            for (int q = 0; q < 8; q++) {
                pre0 += gs[(q * 64 + 0 * 16 + pu) * 17 + pb];
                pre1 += gs[(q * 64 + 1 * 16 + pu) * 17 + pb];
                pre2 += gs[(q * 64 + 2 * 16 + pu) * 17 + pb];
                pre3 += gs[(q * 64 + 3 * 16 + pu) * 17 + pb];
            }
            const float iv = sigf(pre0);
            const float fv = sigf(pre1);
            const float gv = tanh_(pre2);
            const float ov = sigf(pre3);
            c_state = fv * c_state + iv * gv;
            const float hval = ov * tanh_(c_state);

            seqout[((size_t)bglob * kT + t) * kH + u0 + pu] = hval;
            float* hb = (float*)&g_hbuf[cur ^ 1][cg * 4 + (pu >> 2)][bglob];
            hb[pu & 3] = hval;
            if (t == kT - 1) {
                hT[(size_t)bglob * kH + u0 + pu] = hval;
                cT[(size_t)bglob * kH + u0 + pu] = c_state;
            }
        }

        gbar_rel(t + 2, tid, bg);
    }
}

// ---------------- launch ------------------------------------------------------
extern "C" void kernel_launch(void* const* d_in, const int* in_sizes, int n_in,
                              void* d_out, int out_size)
{
    const float* x  = (const float*)d_in[0];
    const float* Wi = (const float*)d_in[1];
    const float* Wh = (const float*)d_in[2];
    const float* bi = (const float*)d_in[3];
    const float* bh = (const float*)d_in[4];

    float* out  = (float*)d_out;
    float* outs = out;                                  // [B,T,H]
    float* hT   = out + (size_t)kB * kT * kH;           // [L,B,H]
    float* cT   = hT + (size_t)2 * kB * kH;             // [L,B,H]

    float* Gp;  cudaGetSymbolAddress((void**)&Gp,  g_G);
    float* h0p; cudaGetSymbolAddress((void**)&h0p, g_h0);

    const size_t smem = (size_t)(128 * 64 + 128 * 16) * sizeof(ulonglong2)
                      + (size_t)(8 * 64 * 17) * sizeof(float);   // 198656 B
    cudaFuncSetAttribute(lstm_recur, cudaFuncAttributeMaxDynamicSharedMemorySize,
                         (int)smem);

    dim3 ggrid(128, 32);

    // layer 0
    gemm_inproj<<<ggrid, 256>>>(x, Wi, bi, bh, Gp);
    lstm_recur<<<kCG * kBG, 512, smem>>>(Gp, Wh, h0p, hT, cT);
    // layer 1
    gemm_inproj<<<ggrid, 256>>>(h0p, Wi + (size_t)kH * kG, bi + kG, bh + kG, Gp);
    lstm_recur<<<kCG * kBG, 512, smem>>>(Gp, Wh + (size_t)kH * kG,
                                         outs, hT + (size_t)kB * kH,
                                         cT + (size_t)kB * kH);
}

// round 7
// speedup vs baseline: 1.8796x; 1.1774x over previous
#include <cuda_runtime.h>
#include <cuda_bf16.h>
#include <cstdint>

typedef unsigned long long ull;

constexpr int kB = 64;      // batch
constexpr int kT = 256;     // time
constexpr int kH = 512;     // hidden
constexpr int kG = 2048;    // 4*H gate cols
constexpr int kM = kB * kT; // 16384 GEMM rows
constexpr int kCG = 32;     // column groups (16 hidden units each)
constexpr int kBG = 4;      // batch groups (16 batch elements each)
constexpr int kGrpCTA = kCG;

// ---------------- scratch ----------------------------------------------------
__device__ float  g_G[(size_t)kM * kG];          // input projections (128 MB)
__device__ float  g_h0[(size_t)kM * kH];         // layer-0 output sequence (32 MB)
__device__ float4 g_hbuf[2][kH / 4][kB];         // ping-pong h
__device__ __nv_bfloat16 g_As[(size_t)kM * 1024];     // A split hi|lo (32 MB)
__device__ __nv_bfloat16 g_WhT[(size_t)kG * kH];      // W hi, transposed [N,K]
__device__ __nv_bfloat16 g_WlT[(size_t)kG * kH];      // W lo, transposed [N,K]
__device__ int g_cnt[kBG * 32];
__device__ int g_flg[kBG * 32];

// ---------------- generic helpers --------------------------------------------
__device__ __forceinline__ ull fma2(ull a, ull b, ull c) {
    ull d;
    asm("fma.rn.f32x2 %0, %1, %2, %3;" : "=l"(d) : "l"(a), "l"(b), "l"(c));
    return d;
}
__device__ __forceinline__ float lo32(ull v) { return __uint_as_float((unsigned)v); }
__device__ __forceinline__ float hi32(ull v) { return __uint_as_float((unsigned)(v >> 32)); }

__device__ __forceinline__ float sigf(float x) {
    x = fminf(fmaxf(x, -30.f), 30.f);
    return 1.f / (1.f + __expf(-x));
}
__device__ __forceinline__ float tanh_(float x) {
    x = fminf(fmaxf(x, -15.f), 15.f);
    float e = __expf(-2.f * x);
    return (1.f - e) / (1.f + e);
}

// mma.sync m16n8k16 bf16 (generic PTX, sm_80+ -> compiles for compute_103)
__device__ __forceinline__ void mma_bf16(float* c, const uint32_t* a,
                                         const uint32_t* b) {
    asm volatile(
        "mma.sync.aligned.m16n8k16.row.col.f32.bf16.bf16.f32 "
        "{%0,%1,%2,%3}, {%4,%5,%6,%7}, {%8,%9}, {%0,%1,%2,%3};"
        : "+f"(c[0]), "+f"(c[1]), "+f"(c[2]), "+f"(c[3])
        : "r"(a[0]), "r"(a[1]), "r"(a[2]), "r"(a[3]), "r"(b[0]), "r"(b[1]));
}

// ---------------- split/prep kernels ------------------------------------------
// A split: A_s[m][0..511] = bf16(A), A_s[m][512..1023] = bf16(A - hi).
// Block 0 also resets the recurrence barrier state.
__global__ void __launch_bounds__(256)
split_x(const float* __restrict__ X)
{
    if (blockIdx.x == 0 && threadIdx.x < kBG) {
        g_cnt[threadIdx.x * 32] = 0;
        g_flg[threadIdx.x * 32] = 0;
    }
    size_t i = ((size_t)blockIdx.x * 256 + threadIdx.x) * 4;
    float4 v = *(const float4*)(X + i);
    size_t m = i >> 9;
    int k = (int)(i & 511);
    __nv_bfloat16 h0 = __float2bfloat16_rn(v.x);
    __nv_bfloat16 h1 = __float2bfloat16_rn(v.y);
    __nv_bfloat16 h2 = __float2bfloat16_rn(v.z);
    __nv_bfloat16 h3 = __float2bfloat16_rn(v.w);
    __nv_bfloat16 l0 = __float2bfloat16_rn(v.x - __bfloat162float(h0));
    __nv_bfloat16 l1 = __float2bfloat16_rn(v.y - __bfloat162float(h1));
    __nv_bfloat16 l2 = __float2bfloat16_rn(v.z - __bfloat162float(h2));
    __nv_bfloat16 l3 = __float2bfloat16_rn(v.w - __bfloat162float(h3));
    __nv_bfloat16* ph = g_As + m * 1024 + k;
    __nv_bfloat16* pl = ph + 512;
    *(__nv_bfloat162*)(ph)     = __nv_bfloat162(h0, h1);
    *(__nv_bfloat162*)(ph + 2) = __nv_bfloat162(h2, h3);
    *(__nv_bfloat162*)(pl)     = __nv_bfloat162(l0, l1);
    *(__nv_bfloat162*)(pl + 2) = __nv_bfloat162(l2, l3);
}

// W split + transpose: W [512, 2048] fp32 -> WhT/WlT [2048, 512] bf16
__global__ void __launch_bounds__(256)
split_w(const float* __restrict__ W)
{
    __shared__ float tile[32][33];
    const int tx = threadIdx.x & 31;
    const int ty = threadIdx.x >> 5;      // 0..7
    const int n0 = blockIdx.x * 32;
    const int k0 = blockIdx.y * 32;
#pragma unroll
    for (int j = 0; j < 4; j++)
        tile[ty + j * 8][tx] = W[(size_t)(k0 + ty + j * 8) * kG + n0 + tx];
    __syncthreads();
#pragma unroll
    for (int j = 0; j < 4; j++) {
        const int n = n0 + ty + j * 8;
        const int k = k0 + tx;
        const float v = tile[tx][ty + j * 8];
        __nv_bfloat16 hi = __float2bfloat16_rn(v);
        __nv_bfloat16 lo = __float2bfloat16_rn(v - __bfloat162float(hi));
        g_WhT[(size_t)n * kH + k] = hi;
        g_WlT[(size_t)n * kH + k] = lo;
    }
}

// ---------------- HMMA input-projection GEMM ----------------------------------
// C[m][n] = Ah.Wh + Al.Wh + Ah.Wl + bi[n] + bh[n]   (3-term bf16 split)
// CTA: 128x128 tile, 8 warps of 64x32. K-tile 32, all terms share staged tiles.
// Staging: 2 threads/row, each thread covers 16 bf16 = TWO uint4 (32 bytes).
constexpr int kLds = 40;   // padded row length (bf16) -> conflict-free frags

__global__ void __launch_bounds__(256, 2)
gemm_mma(const float* __restrict__ bi, const float* __restrict__ bh,
         float* __restrict__ C)
{
    __shared__ __align__(16) __nv_bfloat16 Ah[128 * kLds];
    __shared__ __align__(16) __nv_bfloat16 Al[128 * kLds];
    __shared__ __align__(16) __nv_bfloat16 Bh[128 * kLds];
    __shared__ __align__(16) __nv_bfloat16 Bl[128 * kLds];

    const int tid  = threadIdx.x;
    const int wid  = tid >> 5;
    const int lane = tid & 31;
    const int g    = lane >> 2;
    const int tig  = lane & 3;
    const int n0 = blockIdx.x * 128;
    const int m0 = blockIdx.y * 128;
    const int wm = (wid >> 2) * 64;     // warp m offset
    const int wn = (wid & 3) * 32;      // warp n offset

    const int lr = tid >> 1;            // staging row 0..127
    const int lh = tid & 1;             // staging half (16 bf16 each)

    float acc[4][4][4];
#pragma unroll
    for (int mf = 0; mf < 4; mf++)
#pragma unroll
        for (int nf = 0; nf < 4; nf++)
#pragma unroll
            for (int i = 0; i < 4; i++) acc[mf][nf][i] = 0.f;

    float2 bias2[4];
#pragma unroll
    for (int nf = 0; nf < 4; nf++) {
        const int n = n0 + wn + nf * 8 + tig * 2;
        bias2[nf].x = __ldg(bi + n) + __ldg(bh + n);
        bias2[nf].y = __ldg(bi + n + 1) + __ldg(bh + n + 1);
    }

    for (int kt = 0; kt < 16; kt++) {
        const int koff = kt * 32 + lh * 16;   // element offset, 16 bf16 per thread
        const __nv_bfloat16* pa = g_As  + (size_t)(m0 + lr) * 1024 + koff;
        const __nv_bfloat16* pl = pa + 512;
        const __nv_bfloat16* pb = g_WhT + (size_t)(n0 + lr) * 512 + koff;
        const __nv_bfloat16* pc = g_WlT + (size_t)(n0 + lr) * 512 + koff;
        uint4 vah0 = *(const uint4*)(pa);
        uint4 vah1 = *(const uint4*)(pa + 8);
        uint4 val0 = *(const uint4*)(pl);
        uint4 val1 = *(const uint4*)(pl + 8);
        uint4 vbh0 = *(const uint4*)(pb);
        uint4 vbh1 = *(const uint4*)(pb + 8);
        uint4 vbl0 = *(const uint4*)(pc);
        uint4 vbl1 = *(const uint4*)(pc + 8);
        __syncthreads();
        __nv_bfloat16* da = Ah + lr * kLds + lh * 16;
        __nv_bfloat16* dl = Al + lr * kLds + lh * 16;
        __nv_bfloat16* db = Bh + lr * kLds + lh * 16;
        __nv_bfloat16* dc = Bl + lr * kLds + lh * 16;
        *(uint4*)(da)     = vah0;
        *(uint4*)(da + 8) = vah1;
        *(uint4*)(dl)     = val0;
        *(uint4*)(dl + 8) = val1;
        *(uint4*)(db)     = vbh0;
        *(uint4*)(db + 8) = vbh1;
        *(uint4*)(dc)     = vbl0;
        *(uint4*)(dc + 8) = vbl1;
        __syncthreads();

        const uint32_t* Ah32 = (const uint32_t*)Ah;
        const uint32_t* Al32 = (const uint32_t*)Al;
        const uint32_t* Bh32 = (const uint32_t*)Bh;
        const uint32_t* Bl32 = (const uint32_t*)Bl;
        constexpr int L = kLds / 2;   // 20 b32 per row

#pragma unroll
        for (int ks = 0; ks < 2; ks++) {
            const int kb = ks * 8;
            uint32_t bhf[4][2], blf[4][2];
#pragma unroll
            for (int nf = 0; nf < 4; nf++) {
                const int rn = (wn + nf * 8 + g) * L + kb + tig;
                bhf[nf][0] = Bh32[rn];
                bhf[nf][1] = Bh32[rn + 4];
                blf[nf][0] = Bl32[rn];
                blf[nf][1] = Bl32[rn + 4];
            }
#pragma unroll
            for (int mf = 0; mf < 4; mf++) {
                const int r0 = (wm + mf * 16 + g) * L + kb + tig;
                const int r1 = r0 + 8 * L;
                uint32_t ah[4], al[4];
                ah[0] = Ah32[r0];     ah[1] = Ah32[r1];
                ah[2] = Ah32[r0 + 4]; ah[3] = Ah32[r1 + 4];
                al[0] = Al32[r0];     al[1] = Al32[r1];
                al[2] = Al32[r0 + 4]; al[3] = Al32[r1 + 4];
#pragma unroll
                for (int nf = 0; nf < 4; nf++) {
                    mma_bf16(acc[mf][nf], ah, bhf[nf]);
                    mma_bf16(acc[mf][nf], al, bhf[nf]);
                    mma_bf16(acc[mf][nf], ah, blf[nf]);
                }
            }
        }
    }

    // epilogue: fragment -> global with fused bias
#pragma unroll
    for (int mf = 0; mf < 4; mf++) {
        const int m = m0 + wm + mf * 16 + g;
#pragma unroll
        for (int nf = 0; nf < 4; nf++) {
            const int n = n0 + wn + nf * 8 + tig * 2;
            float2 o0, o1;
            o0.x = acc[mf][nf][0] + bias2[nf].x;
            o0.y = acc[mf][nf][1] + bias2[nf].y;
            o1.x = acc[mf][nf][2] + bias2[nf].x;
            o1.y = acc[mf][nf][3] + bias2[nf].y;
            *(float2*)(C + (size_t)m * kG + n)       = o0;
            *(float2*)(C + (size_t)(m + 8) * kG + n) = o1;
        }
    }
}

// ---------------- scoped-atomics group barrier ---------------------------------
__device__ __forceinline__ void gbar_rel(int idx, int tid, int bg)
{
    __syncthreads();
    if (tid == 0) {
        int* cnt = &g_cnt[bg * 32];
        int* flg = &g_flg[bg * 32];
        int prev;
        asm volatile("atom.acq_rel.gpu.global.add.s32 %0, [%1], 1;"
                     : "=r"(prev) : "l"(cnt) : "memory");
        if (prev == idx * kGrpCTA - 1) {
            int dummy;
            asm volatile("atom.release.gpu.global.exch.b32 %0, [%1], %2;"
                         : "=r"(dummy) : "l"(flg), "r"(idx) : "memory");
        } else {
            int v;
            do {
                asm volatile("ld.acquire.gpu.global.s32 %0, [%1];"
                             : "=r"(v) : "l"(flg) : "memory");
            } while (v < idx);
        }
    }
    __syncthreads();
}

// ---------------- persistent LSTM recurrence (unchanged, passing) --------------
extern __shared__ ull s_mem[];

__global__ void __launch_bounds__(512, 1)
lstm_recur(const float* __restrict__ G, const float* __restrict__ Wh,
           float* __restrict__ seqout, float* __restrict__ hT,
           float* __restrict__ cT)
{
    ulonglong2* Whs = (ulonglong2*)s_mem;           // [128 quad][64 c]
    ulonglong2* hs  = Whs + 128 * 64;               // [128 quad][16 b]
    float*      gs  = (float*)(hs + 128 * 16);      // [8 kq][64 c][17]

    const int tid = threadIdx.x;
    const int cg  = blockIdx.x >> 2;
    const int bg  = blockIdx.x & 3;
    const int u0  = cg * 16;

    const int kq = tid >> 6;
    const int lt = tid & 63;
    const int ct = (tid >> 2) & 15;
    const int bt = tid & 3;

    const int pb = (tid >> 4) & 15;
    const int pu = tid & 15;
    const int bglob = bg * 16 + pb;
    const bool pw = (tid < 256);

    {
        const int k = tid;
        const int quad = k >> 2;
        const int comp = k & 3;
#pragma unroll
        for (int g = 0; g < 4; g++) {
#pragma unroll
            for (int v = 0; v < 4; v++) {
                float4 w = *(const float4*)(Wh + (size_t)k * kG + g * kH + u0 + v * 4);
                float* d = (float*)&Whs[quad * 64 + g * 16 + v * 4];
                d[0 * 4 + comp] = w.x;
                d[1 * 4 + comp] = w.y;
                d[2 * 4 + comp] = w.z;
                d[3 * 4 + comp] = w.w;
            }
        }
    }
    if (tid < 64) {
        const int q = cg * 4 + (tid >> 4);
        const int b = bg * 16 + (tid & 15);
        g_hbuf[0][q][b] = make_float4(0.f, 0.f, 0.f, 0.f);
    }
    float c_state = 0.f;

    gbar_rel(1, tid, bg);

    for (int t = 0; t < kT; t++) {
        const int cur = t & 1;

        float gin0, gin1, gin2, gin3;
        if (pw) {
            const float* gp = G + ((size_t)bglob * kT + t) * kG + u0 + pu;
            gin0 = __ldcs(gp);
            gin1 = __ldcs(gp + kH);
            gin2 = __ldcs(gp + 2 * kH);
            gin3 = __ldcs(gp + 3 * kH);
        }

        {
#pragma unroll
            for (int j = 0; j < 4; j++) {
                const int e = kq * 256 + j * 64 + lt;
                const int quad = e >> 4;
                const int b = e & 15;
                float4 v = __ldcg(&g_hbuf[cur][quad][bg * 16 + b]);
                hs[e] = *(ulonglong2*)&v;
            }
        }
        asm volatile("bar.sync %0, 64;" :: "r"(kq + 1) : "memory");

        ull acc[4][4];
#pragma unroll
        for (int j = 0; j < 4; j++)
#pragma unroll
            for (int i = 0; i < 4; i++) acc[j][i] = 0ull;

        const int q0 = kq * 16;
#pragma unroll 2
        for (int Q = 0; Q < 16; Q++) {
            const int quad = q0 + Q;
            ulonglong2 wv[4], hv[4];
#pragma unroll
            for (int i = 0; i < 4; i++)
                wv[i] = Whs[quad * 64 + ct * 4 + i];
#pragma unroll
            for (int j = 0; j < 4; j++)
                hv[j] = hs[quad * 16 + bt + 4 * j];
#pragma unroll
            for (int j = 0; j < 4; j++)
#pragma unroll
                for (int i = 0; i < 4; i++) {
                    acc[j][i] = fma2(hv[j].x, wv[i].x, acc[j][i]);
                    acc[j][i] = fma2(hv[j].y, wv[i].y, acc[j][i]);
                }
        }
#pragma unroll
        for (int j = 0; j < 4; j++) {
            const int b = bt + 4 * j;
#pragma unroll
            for (int i = 0; i < 4; i++)
                gs[(kq * 64 + ct * 4 + i) * 17 + b] =
                    lo32(acc[j][i]) + hi32(acc[j][i]);
        }
        __syncthreads();

        if (pw) {
            float pre0 = gin0, pre1 = gin1, pre2 = gin2, pre3 = gin3;
#pragma unroll
            for (int q = 0; q < 8; q++) {
                pre0 += gs[(q * 64 + 0 * 16 + pu) * 17 + pb];
                pre1 += gs[(q * 64 + 1 * 16 + pu) * 17 + pb];
                pre2 += gs[(q * 64 + 2 * 16 + pu) * 17 + pb];
                pre3 += gs[(q * 64 + 3 * 16 + pu) * 17 + pb];
            }
            const float iv = sigf(pre0);
            const float fv = sigf(pre1);
            const float gv = tanh_(pre2);
            const float ov = sigf(pre3);
            c_state = fv * c_state + iv * gv;
            const float hval = ov * tanh_(c_state);

            seqout[((size_t)bglob * kT + t) * kH + u0 + pu] = hval;
            float* hb = (float*)&g_hbuf[cur ^ 1][cg * 4 + (pu >> 2)][bglob];
            hb[pu & 3] = hval;
            if (t == kT - 1) {
                hT[(size_t)bglob * kH + u0 + pu] = hval;
                cT[(size_t)bglob * kH + u0 + pu] = c_state;
            }
        }

        gbar_rel(t + 2, tid, bg);
    }
}

// ---------------- launch ------------------------------------------------------
extern "C" void kernel_launch(void* const* d_in, const int* in_sizes, int n_in,
                              void* d_out, int out_size)
{
    const float* x  = (const float*)d_in[0];
    const float* Wi = (const float*)d_in[1];
    const float* Wh = (const float*)d_in[2];
    const float* bi = (const float*)d_in[3];
    const float* bh = (const float*)d_in[4];

    float* out  = (float*)d_out;
    float* outs = out;
    float* hT   = out + (size_t)kB * kT * kH;
    float* cT   = hT + (size_t)2 * kB * kH;

    float* Gp;  cudaGetSymbolAddress((void**)&Gp,  g_G);
    float* h0p; cudaGetSymbolAddress((void**)&h0p, g_h0);

    const size_t smemR = (size_t)(128 * 64 + 128 * 16) * sizeof(ulonglong2)
                       + (size_t)(8 * 64 * 17) * sizeof(float);
    cudaFuncSetAttribute(lstm_recur, cudaFuncAttributeMaxDynamicSharedMemorySize,
                         (int)smemR);

    const dim3 gGemm(kG / 128, kM / 128);   // (16, 128)

    // ---- layer 0
    split_w<<<dim3(64, 16), 256>>>(Wi);
    split_x<<<kM * kH / 1024, 256>>>(x);
    gemm_mma<<<gGemm, 256>>>(bi, bh, Gp);
    lstm_recur<<<kCG * kBG, 512, smemR>>>(Gp, Wh, h0p, hT, cT);

    // ---- layer 1
    split_w<<<dim3(64, 16), 256>>>(Wi + (size_t)kH * kG);
    split_x<<<kM * kH / 1024, 256>>>(h0p);
    gemm_mma<<<gGemm, 256>>>(bi + kG, bh + kG, Gp);
    lstm_recur<<<kCG * kBG, 512, smemR>>>(Gp, Wh + (size_t)kH * kG,
                                          outs, hT + (size_t)kB * kH,
                                          cT + (size_t)kB * kH);
}

// round 8
// speedup vs baseline: 2.6234x; 1.3958x over previous
#include <cuda_runtime.h>
#include <cuda_bf16.h>
#include <cstdint>

typedef unsigned long long ull;

constexpr int kB = 64;      // batch
constexpr int kT = 256;     // time
constexpr int kH = 512;     // hidden
constexpr int kG = 2048;    // 4*H gate cols
constexpr int kM = kB * kT; // 16384 GEMM rows
constexpr int kCG = 32;     // column groups (16 hidden units each)
constexpr int kBG = 4;      // batch groups (16 batch elements each)
constexpr int kGrpCTA = kCG;

// ---------------- scratch ----------------------------------------------------
__device__ float  g_G[(size_t)kM * kG];            // input projections (128 MB)
__device__ float  g_h0[(size_t)kM * kH];           // layer-0 output sequence
__device__ __nv_bfloat16 g_As[(size_t)kM * 1024];  // A split hi|lo (32 MB)
__device__ __nv_bfloat16 g_WiTh[(size_t)kG * kH];  // Wi hi, transposed [N,K]
__device__ __nv_bfloat16 g_WiTl[(size_t)kG * kH];  // Wi lo
__device__ __nv_bfloat16 g_WhTh[(size_t)kG * kH];  // Wh hi, transposed [N,K]
__device__ __nv_bfloat16 g_WhTl[(size_t)kG * kH];  // Wh lo
__device__ __nv_bfloat16 g_hbf[2][kB][1024];       // ping-pong h, hi|lo per row
__device__ int g_cnt[kBG * 32];
__device__ int g_flg[kBG * 32];

// ---------------- helpers -----------------------------------------------------
__device__ __forceinline__ float sigf(float x) {
    x = fminf(fmaxf(x, -30.f), 30.f);
    return 1.f / (1.f + __expf(-x));
}
__device__ __forceinline__ float tanh_(float x) {
    x = fminf(fmaxf(x, -15.f), 15.f);
    float e = __expf(-2.f * x);
    return (1.f - e) / (1.f + e);
}

// mma.sync m16n8k16 bf16 (generic PTX -> compiles for compute_103)
__device__ __forceinline__ void mma_bf16(float* c, const uint32_t* a,
                                         const uint32_t* b) {
    asm volatile(
        "mma.sync.aligned.m16n8k16.row.col.f32.bf16.bf16.f32 "
        "{%0,%1,%2,%3}, {%4,%5,%6,%7}, {%8,%9}, {%0,%1,%2,%3};"
        : "+f"(c[0]), "+f"(c[1]), "+f"(c[2]), "+f"(c[3])
        : "r"(a[0]), "r"(a[1]), "r"(a[2]), "r"(a[3]), "r"(b[0]), "r"(b[1]));
}

// ---------------- split/prep kernels -------------------------------------------
// A split: A_s[m][0..511]=bf16(A), [512..1023]=bf16(A-hi). Resets barriers.
__global__ void __launch_bounds__(256)
split_x(const float* __restrict__ X)
{
    if (blockIdx.x == 0 && threadIdx.x < kBG) {
        g_cnt[threadIdx.x * 32] = 0;
        g_flg[threadIdx.x * 32] = 0;
    }
    size_t i = ((size_t)blockIdx.x * 256 + threadIdx.x) * 4;
    float4 v = *(const float4*)(X + i);
    size_t m = i >> 9;
    int k = (int)(i & 511);
    __nv_bfloat16 h0 = __float2bfloat16_rn(v.x);
    __nv_bfloat16 h1 = __float2bfloat16_rn(v.y);
    __nv_bfloat16 h2 = __float2bfloat16_rn(v.z);
    __nv_bfloat16 h3 = __float2bfloat16_rn(v.w);
    __nv_bfloat16 l0 = __float2bfloat16_rn(v.x - __bfloat162float(h0));
    __nv_bfloat16 l1 = __float2bfloat16_rn(v.y - __bfloat162float(h1));
    __nv_bfloat16 l2 = __float2bfloat16_rn(v.z - __bfloat162float(h2));
    __nv_bfloat16 l3 = __float2bfloat16_rn(v.w - __bfloat162float(h3));
    __nv_bfloat16* ph = g_As + m * 1024 + k;
    __nv_bfloat16* pl = ph + 512;
    *(__nv_bfloat162*)(ph)     = __nv_bfloat162(h0, h1);
    *(__nv_bfloat162*)(ph + 2) = __nv_bfloat162(h2, h3);
    *(__nv_bfloat162*)(pl)     = __nv_bfloat162(l0, l1);
    *(__nv_bfloat162*)(pl + 2) = __nv_bfloat162(l2, l3);
}

// W split + transpose: W [512, 2048] fp32 -> dH/dL [2048, 512] bf16
__global__ void __launch_bounds__(256)
split_pair(const float* __restrict__ W, __nv_bfloat16* __restrict__ dH,
           __nv_bfloat16* __restrict__ dL)
{
    __shared__ float tile[32][33];
    const int tx = threadIdx.x & 31;
    const int ty = threadIdx.x >> 5;
    const int n0 = blockIdx.x * 32;
    const int k0 = blockIdx.y * 32;
#pragma unroll
    for (int j = 0; j < 4; j++)
        tile[ty + j * 8][tx] = W[(size_t)(k0 + ty + j * 8) * kG + n0 + tx];
    __syncthreads();
#pragma unroll
    for (int j = 0; j < 4; j++) {
        const int n = n0 + ty + j * 8;
        const int k = k0 + tx;
        const float v = tile[tx][ty + j * 8];
        __nv_bfloat16 hi = __float2bfloat16_rn(v);
        __nv_bfloat16 lo = __float2bfloat16_rn(v - __bfloat162float(hi));
        dH[(size_t)n * kH + k] = hi;
        dL[(size_t)n * kH + k] = lo;
    }
}

// ---------------- HMMA input-projection GEMM (unchanged, passing) --------------
constexpr int kLds = 40;

__global__ void __launch_bounds__(256, 2)
gemm_mma(const float* __restrict__ bi, const float* __restrict__ bh,
         float* __restrict__ C)
{
    __shared__ __align__(16) __nv_bfloat16 Ah[128 * kLds];
    __shared__ __align__(16) __nv_bfloat16 Al[128 * kLds];
    __shared__ __align__(16) __nv_bfloat16 Bh[128 * kLds];
    __shared__ __align__(16) __nv_bfloat16 Bl[128 * kLds];

    const int tid  = threadIdx.x;
    const int wid  = tid >> 5;
    const int lane = tid & 31;
    const int g    = lane >> 2;
    const int tig  = lane & 3;
    const int n0 = blockIdx.x * 128;
    const int m0 = blockIdx.y * 128;
    const int wm = (wid >> 2) * 64;
    const int wn = (wid & 3) * 32;

    const int lr = tid >> 1;
    const int lh = tid & 1;

    float acc[4][4][4];
#pragma unroll
    for (int mf = 0; mf < 4; mf++)
#pragma unroll
        for (int nf = 0; nf < 4; nf++)
#pragma unroll
            for (int i = 0; i < 4; i++) acc[mf][nf][i] = 0.f;

    float2 bias2[4];
#pragma unroll
    for (int nf = 0; nf < 4; nf++) {
        const int n = n0 + wn + nf * 8 + tig * 2;
        bias2[nf].x = __ldg(bi + n) + __ldg(bh + n);
        bias2[nf].y = __ldg(bi + n + 1) + __ldg(bh + n + 1);
    }

    for (int kt = 0; kt < 16; kt++) {
        const int koff = kt * 32 + lh * 16;
        const __nv_bfloat16* pa = g_As   + (size_t)(m0 + lr) * 1024 + koff;
        const __nv_bfloat16* pl = pa + 512;
        const __nv_bfloat16* pb = g_WiTh + (size_t)(n0 + lr) * 512 + koff;
        const __nv_bfloat16* pc = g_WiTl + (size_t)(n0 + lr) * 512 + koff;
        uint4 vah0 = *(const uint4*)(pa);
        uint4 vah1 = *(const uint4*)(pa + 8);
        uint4 val0 = *(const uint4*)(pl);
        uint4 val1 = *(const uint4*)(pl + 8);
        uint4 vbh0 = *(const uint4*)(pb);
        uint4 vbh1 = *(const uint4*)(pb + 8);
        uint4 vbl0 = *(const uint4*)(pc);
        uint4 vbl1 = *(const uint4*)(pc + 8);
        __syncthreads();
        __nv_bfloat16* da = Ah + lr * kLds + lh * 16;
        __nv_bfloat16* dl = Al + lr * kLds + lh * 16;
        __nv_bfloat16* db = Bh + lr * kLds + lh * 16;
        __nv_bfloat16* dc = Bl + lr * kLds + lh * 16;
        *(uint4*)(da)     = vah0;
        *(uint4*)(da + 8) = vah1;
        *(uint4*)(dl)     = val0;
        *(uint4*)(dl + 8) = val1;
        *(uint4*)(db)     = vbh0;
        *(uint4*)(db + 8) = vbh1;
        *(uint4*)(dc)     = vbl0;
        *(uint4*)(dc + 8) = vbl1;
        __syncthreads();

        const uint32_t* Ah32 = (const uint32_t*)Ah;
        const uint32_t* Al32 = (const uint32_t*)Al;
        const uint32_t* Bh32 = (const uint32_t*)Bh;
        const uint32_t* Bl32 = (const uint32_t*)Bl;
        constexpr int L = kLds / 2;

#pragma unroll
        for (int ks = 0; ks < 2; ks++) {
            const int kb = ks * 8;
            uint32_t bhf[4][2], blf[4][2];
#pragma unroll
            for (int nf = 0; nf < 4; nf++) {
                const int rn = (wn + nf * 8 + g) * L + kb + tig;
                bhf[nf][0] = Bh32[rn];
                bhf[nf][1] = Bh32[rn + 4];
                blf[nf][0] = Bl32[rn];
                blf[nf][1] = Bl32[rn + 4];
            }
#pragma unroll
            for (int mf = 0; mf < 4; mf++) {
                const int r0 = (wm + mf * 16 + g) * L + kb + tig;
                const int r1 = r0 + 8 * L;
                uint32_t ah[4], al[4];
                ah[0] = Ah32[r0];     ah[1] = Ah32[r1];
                ah[2] = Ah32[r0 + 4]; ah[3] = Ah32[r1 + 4];
                al[0] = Al32[r0];     al[1] = Al32[r1];
                al[2] = Al32[r0 + 4]; al[3] = Al32[r1 + 4];
#pragma unroll
                for (int nf = 0; nf < 4; nf++) {
                    mma_bf16(acc[mf][nf], ah, bhf[nf]);
                    mma_bf16(acc[mf][nf], al, bhf[nf]);
                    mma_bf16(acc[mf][nf], ah, blf[nf]);
                }
            }
        }
    }

#pragma unroll
    for (int mf = 0; mf < 4; mf++) {
        const int m = m0 + wm + mf * 16 + g;
#pragma unroll
        for (int nf = 0; nf < 4; nf++) {
            const int n = n0 + wn + nf * 8 + tig * 2;
            float2 o0, o1;
            o0.x = acc[mf][nf][0] + bias2[nf].x;
            o0.y = acc[mf][nf][1] + bias2[nf].y;
            o1.x = acc[mf][nf][2] + bias2[nf].x;
            o1.y = acc[mf][nf][3] + bias2[nf].y;
            *(float2*)(C + (size_t)m * kG + n)       = o0;
            *(float2*)(C + (size_t)(m + 8) * kG + n) = o1;
        }
    }
}

// ---------------- scoped-atomics group barrier ---------------------------------
__device__ __forceinline__ void gbar_rel(int idx, int tid, int bg)
{
    __syncthreads();
    if (tid == 0) {
        int* cnt = &g_cnt[bg * 32];
        int* flg = &g_flg[bg * 32];
        int prev;
        asm volatile("atom.acq_rel.gpu.global.add.s32 %0, [%1], 1;"
                     : "=r"(prev) : "l"(cnt) : "memory");
        if (prev == idx * kGrpCTA - 1) {
            int dummy;
            asm volatile("atom.release.gpu.global.exch.b32 %0, [%1], %2;"
                         : "=r"(dummy) : "l"(flg), "r"(idx) : "memory");
        } else {
            int v;
            do {
                asm volatile("ld.acquire.gpu.global.s32 %0, [%1];"
                             : "=r"(v) : "l"(flg) : "memory");
            } while (v < idx);
        }
    }
    __syncthreads();
}

// ---------------- persistent HMMA LSTM recurrence ------------------------------
// 128 CTAs = 32 col-groups x 4 batch-groups, 256 threads (8 warps).
// Warp w owns gate-col slice [w*8, w*8+8) of the CTA's 64 cols, full K=512.
// Wh B-fragments (bf16 hi+lo, 4-term split) live in 128 registers for ALL steps.
// Per step: stage h (16 x 1024 bf16 hi|lo, 32KB) -> 32 ksteps x 4 MMA -> gs
// -> pointwise (h emitted as bf16 hi/lo to global ping-pong).
__global__ void __launch_bounds__(256, 1)
lstm_recur_mma(const float* __restrict__ G,
               const __nv_bfloat16* __restrict__ WTh,
               const __nv_bfloat16* __restrict__ WTl,
               float* __restrict__ seqout, float* __restrict__ hT,
               float* __restrict__ cT)
{
    __shared__ __align__(16) __nv_bfloat16 Ahs[16][1032];  // [b][k hi | 512+k lo]
    __shared__ float gs[64 * 20];                          // [col][batch(pad 20)]

    const int tid = threadIdx.x;
    const int cg  = blockIdx.x >> 2;
    const int bg  = blockIdx.x & 3;
    const int u0  = cg * 16;

    const int wid  = tid >> 5;       // n-slice 0..7
    const int lane = tid & 31;
    const int g8   = lane >> 2;      // 0..7
    const int tig  = lane & 3;

    const int pb = tid >> 4;         // local batch 0..15
    const int pu = tid & 15;         // local unit 0..15
    const int bglob = bg * 16 + pb;

    // ---- load Wh B-fragments into registers (col c, full K, hi+lo)
    const int c  = wid * 8 + g8;                       // 0..63
    const int ng = (c >> 4) * kH + u0 + (c & 15);      // global gate col
    uint32_t bh[32][2], bl[32][2];
#pragma unroll
    for (int ks = 0; ks < 32; ks++) {
        const int kk = ks * 16 + tig * 2;
        bh[ks][0] = *(const uint32_t*)(WTh + (size_t)ng * 512 + kk);
        bh[ks][1] = *(const uint32_t*)(WTh + (size_t)ng * 512 + kk + 8);
        bl[ks][0] = *(const uint32_t*)(WTl + (size_t)ng * 512 + kk);
        bl[ks][1] = *(const uint32_t*)(WTl + (size_t)ng * 512 + kk + 8);
    }

    // zero our slice of the h ping buffer (parity 0)
    g_hbf[0][bglob][u0 + pu]       = __float2bfloat16_rn(0.f);
    g_hbf[0][bglob][512 + u0 + pu] = __float2bfloat16_rn(0.f);
    float c_state = 0.f;

    gbar_rel(1, tid, bg);

    for (int t = 0; t < kT; t++) {
        const int cur = t & 1;

        // prefetch input projection
        const float* gp = G + ((size_t)bglob * kT + t) * kG + u0 + pu;
        const float gin0 = __ldcs(gp);
        const float gin1 = __ldcs(gp + kH);
        const float gin2 = __ldcs(gp + 2 * kH);
        const float gin3 = __ldcs(gp + 3 * kH);

        // stage h hi|lo: 16 rows x 1024 bf16 = 2048 uint4, 8 per thread
#pragma unroll
        for (int j = 0; j < 8; j++) {
            const int e = tid + j * 256;
            const int row = e >> 7;
            const int seg = e & 127;
            const uint4* src = (const uint4*)(&g_hbf[cur][bg * 16 + row][0]) + seg;
            uint4 v = __ldcg(src);
            *(uint4*)(&Ahs[row][seg * 8]) = v;
        }
        __syncthreads();

        // gate GEMM: one 16x8 tile per warp, K=512, 4-term bf16 split
        float acc[4] = {0.f, 0.f, 0.f, 0.f};
#pragma unroll
        for (int ks = 0; ks < 32; ks++) {
            const int kk = ks * 16 + tig * 2;
            uint32_t ah[4], al[4];
            ah[0] = *(const uint32_t*)&Ahs[g8][kk];
            ah[1] = *(const uint32_t*)&Ahs[g8 + 8][kk];
            ah[2] = *(const uint32_t*)&Ahs[g8][kk + 8];
            ah[3] = *(const uint32_t*)&Ahs[g8 + 8][kk + 8];
            al[0] = *(const uint32_t*)&Ahs[g8][512 + kk];
            al[1] = *(const uint32_t*)&Ahs[g8 + 8][512 + kk];
            al[2] = *(const uint32_t*)&Ahs[g8][512 + kk + 8];
            al[3] = *(const uint32_t*)&Ahs[g8 + 8][512 + kk + 8];
            mma_bf16(acc, ah, bh[ks]);
            mma_bf16(acc, al, bh[ks]);
            mma_bf16(acc, ah, bl[ks]);
            mma_bf16(acc, al, bl[ks]);
        }
        gs[(c - g8 + tig * 2) * 20 + g8]          = acc[0];   // col wid*8+tig*2
        gs[(c - g8 + tig * 2 + 1) * 20 + g8]      = acc[1];
        gs[(c - g8 + tig * 2) * 20 + g8 + 8]      = acc[2];
        gs[(c - g8 + tig * 2 + 1) * 20 + g8 + 8]  = acc[3];
        __syncthreads();

        // pointwise LSTM cell: thread = (pb, pu)
        {
            const float pre0 = gin0 + gs[(0 * 16 + pu) * 20 + pb];
            const float pre1 = gin1 + gs[(1 * 16 + pu) * 20 + pb];
            const float pre2 = gin2 + gs[(2 * 16 + pu) * 20 + pb];
            const float pre3 = gin3 + gs[(3 * 16 + pu) * 20 + pb];
            const float iv = sigf(pre0);
            const float fv = sigf(pre1);
            const float gv = tanh_(pre2);
            const float ov = sigf(pre3);
            c_state = fv * c_state + iv * gv;
            const float hval = ov * tanh_(c_state);

            seqout[((size_t)bglob * kT + t) * kH + u0 + pu] = hval;
            const __nv_bfloat16 hh = __float2bfloat16_rn(hval);
            const __nv_bfloat16 hl = __float2bfloat16_rn(hval - __bfloat162float(hh));
            g_hbf[cur ^ 1][bglob][u0 + pu]       = hh;
            g_hbf[cur ^ 1][bglob][512 + u0 + pu] = hl;
            if (t == kT - 1) {
                hT[(size_t)bglob * kH + u0 + pu] = hval;
                cT[(size_t)bglob * kH + u0 + pu] = c_state;
            }
        }

        gbar_rel(t + 2, tid, bg);
    }
}

// ---------------- launch --------------------------------------------------------
extern "C" void kernel_launch(void* const* d_in, const int* in_sizes, int n_in,
                              void* d_out, int out_size)
{
    const float* x  = (const float*)d_in[0];
    const float* Wi = (const float*)d_in[1];
    const float* Wh = (const float*)d_in[2];
    const float* bi = (const float*)d_in[3];
    const float* bh = (const float*)d_in[4];

    float* out  = (float*)d_out;
    float* outs = out;
    float* hT   = out + (size_t)kB * kT * kH;
    float* cT   = hT + (size_t)2 * kB * kH;

    float* Gp;  cudaGetSymbolAddress((void**)&Gp,  g_G);
    float* h0p; cudaGetSymbolAddress((void**)&h0p, g_h0);
    __nv_bfloat16 *wih, *wil, *whh, *whl;
    cudaGetSymbolAddress((void**)&wih, g_WiTh);
    cudaGetSymbolAddress((void**)&wil, g_WiTl);
    cudaGetSymbolAddress((void**)&whh, g_WhTh);
    cudaGetSymbolAddress((void**)&whl, g_WhTl);

    const dim3 gSplit(64, 16);
    const dim3 gGemm(kG / 128, kM / 128);

    // ---- layer 0
    split_pair<<<gSplit, 256>>>(Wi, wih, wil);
    split_pair<<<gSplit, 256>>>(Wh, whh, whl);
    split_x<<<kM * kH / 1024, 256>>>(x);
    gemm_mma<<<gGemm, 256>>>(bi, bh, Gp);
    lstm_recur_mma<<<kCG * kBG, 256>>>(Gp, whh, whl, h0p, hT, cT);

    // ---- layer 1
    split_pair<<<gSplit, 256>>>(Wi + (size_t)kH * kG, wih, wil);
    split_pair<<<gSplit, 256>>>(Wh + (size_t)kH * kG, whh, whl);
    split_x<<<kM * kH / 1024, 256>>>(h0p);
    gemm_mma<<<gGemm, 256>>>(bi + kG, bh + kG, Gp);
    lstm_recur_mma<<<kCG * kBG, 256>>>(Gp, whh, whl,
                                       outs, hT + (size_t)kB * kH,
                                       cT + (size_t)kB * kH);
}

// round 9
// speedup vs baseline: 2.8632x; 1.0914x over previous
#include <cuda_runtime.h>
#include <cuda_bf16.h>
#include <cstdint>

typedef unsigned long long ull;

constexpr int kB = 64;      // batch
constexpr int kT = 256;     // time
constexpr int kH = 512;     // hidden
constexpr int kG = 2048;    // 4*H gate cols
constexpr int kM = kB * kT; // 16384 GEMM rows
constexpr int kCG = 32;     // column groups (16 hidden units each)
constexpr int kBG = 4;      // batch groups (16 batch elements each)
constexpr int kGrpCTA = kCG;

// ---------------- scratch ----------------------------------------------------
__device__ float  g_G[(size_t)kM * kG];            // input projections (128 MB)
__device__ float  g_h0[(size_t)kM * kH];           // layer-0 output sequence
__device__ __nv_bfloat16 g_As[(size_t)kM * 1024];  // A split hi|lo (32 MB)
__device__ __nv_bfloat16 g_WiTh[(size_t)kG * kH];  // Wi hi, transposed [N,K]
__device__ __nv_bfloat16 g_WiTl[(size_t)kG * kH];  // Wi lo
__device__ __nv_bfloat16 g_WhTh[(size_t)kG * kH];  // Wh hi, transposed [N,K]
__device__ __nv_bfloat16 g_WhTl[(size_t)kG * kH];  // Wh lo
__device__ __nv_bfloat16 g_hbf[2][kB][1024];       // ping-pong h, hi|lo per row
__device__ int g_cnt[kBG * 32];
__device__ int g_flg[kBG * 32];

// ---------------- helpers -----------------------------------------------------
__device__ __forceinline__ float sigf(float x) {
    x = fminf(fmaxf(x, -30.f), 30.f);
    return 1.f / (1.f + __expf(-x));
}
__device__ __forceinline__ float tanh_(float x) {
    x = fminf(fmaxf(x, -15.f), 15.f);
    float e = __expf(-2.f * x);
    return (1.f - e) / (1.f + e);
}

// mma.sync m16n8k16 bf16 (generic PTX -> compiles for compute_103)
__device__ __forceinline__ void mma_bf16(float* c, const uint32_t* a,
                                         const uint32_t* b) {
    asm volatile(
        "mma.sync.aligned.m16n8k16.row.col.f32.bf16.bf16.f32 "
        "{%0,%1,%2,%3}, {%4,%5,%6,%7}, {%8,%9}, {%0,%1,%2,%3};"
        : "+f"(c[0]), "+f"(c[1]), "+f"(c[2]), "+f"(c[3])
        : "r"(a[0]), "r"(a[1]), "r"(a[2]), "r"(a[3]), "r"(b[0]), "r"(b[1]));
}

// ldmatrix x4: loads the full m16k16 A fragment (a0..a3) in one op
__device__ __forceinline__ void ldmx4(uint32_t* r, uint32_t addr) {
    asm volatile("ldmatrix.sync.aligned.m8n8.x4.shared.b16 {%0,%1,%2,%3}, [%4];"
                 : "=r"(r[0]), "=r"(r[1]), "=r"(r[2]), "=r"(r[3]) : "r"(addr));
}
__device__ __forceinline__ uint32_t smem_u32(const void* p) {
    uint32_t a;
    asm("{ .reg .u64 t; cvta.to.shared.u64 t, %1; cvt.u32.u64 %0, t; }"
        : "=r"(a) : "l"(p));
    return a;
}

// ---------------- split/prep kernels -------------------------------------------
__global__ void __launch_bounds__(256)
split_x(const float* __restrict__ X)
{
    if (blockIdx.x == 0 && threadIdx.x < kBG) {
        g_cnt[threadIdx.x * 32] = 0;
        g_flg[threadIdx.x * 32] = 0;
    }
    size_t i = ((size_t)blockIdx.x * 256 + threadIdx.x) * 4;
    float4 v = *(const float4*)(X + i);
    size_t m = i >> 9;
    int k = (int)(i & 511);
    __nv_bfloat16 h0 = __float2bfloat16_rn(v.x);
    __nv_bfloat16 h1 = __float2bfloat16_rn(v.y);
    __nv_bfloat16 h2 = __float2bfloat16_rn(v.z);
    __nv_bfloat16 h3 = __float2bfloat16_rn(v.w);
    __nv_bfloat16 l0 = __float2bfloat16_rn(v.x - __bfloat162float(h0));
    __nv_bfloat16 l1 = __float2bfloat16_rn(v.y - __bfloat162float(h1));
    __nv_bfloat16 l2 = __float2bfloat16_rn(v.z - __bfloat162float(h2));
    __nv_bfloat16 l3 = __float2bfloat16_rn(v.w - __bfloat162float(h3));
    __nv_bfloat16* ph = g_As + m * 1024 + k;
    __nv_bfloat16* pl = ph + 512;
    *(__nv_bfloat162*)(ph)     = __nv_bfloat162(h0, h1);
    *(__nv_bfloat162*)(ph + 2) = __nv_bfloat162(h2, h3);
    *(__nv_bfloat162*)(pl)     = __nv_bfloat162(l0, l1);
    *(__nv_bfloat162*)(pl + 2) = __nv_bfloat162(l2, l3);
}

__global__ void __launch_bounds__(256)
split_pair(const float* __restrict__ W, __nv_bfloat16* __restrict__ dH,
           __nv_bfloat16* __restrict__ dL)
{
    __shared__ float tile[32][33];
    const int tx = threadIdx.x & 31;
    const int ty = threadIdx.x >> 5;
    const int n0 = blockIdx.x * 32;
    const int k0 = blockIdx.y * 32;
#pragma unroll
    for (int j = 0; j < 4; j++)
        tile[ty + j * 8][tx] = W[(size_t)(k0 + ty + j * 8) * kG + n0 + tx];
    __syncthreads();
#pragma unroll
    for (int j = 0; j < 4; j++) {
        const int n = n0 + ty + j * 8;
        const int k = k0 + tx;
        const float v = tile[tx][ty + j * 8];
        __nv_bfloat16 hi = __float2bfloat16_rn(v);
        __nv_bfloat16 lo = __float2bfloat16_rn(v - __bfloat162float(hi));
        dH[(size_t)n * kH + k] = hi;
        dL[(size_t)n * kH + k] = lo;
    }
}

// ---------------- HMMA input-projection GEMM (unchanged, passing) --------------
constexpr int kLds = 40;

__global__ void __launch_bounds__(256, 2)
gemm_mma(const float* __restrict__ bi, const float* __restrict__ bh,
         float* __restrict__ C)
{
    __shared__ __align__(16) __nv_bfloat16 Ah[128 * kLds];
    __shared__ __align__(16) __nv_bfloat16 Al[128 * kLds];
    __shared__ __align__(16) __nv_bfloat16 Bh[128 * kLds];
    __shared__ __align__(16) __nv_bfloat16 Bl[128 * kLds];

    const int tid  = threadIdx.x;
    const int wid  = tid >> 5;
    const int lane = tid & 31;
    const int g    = lane >> 2;
    const int tig  = lane & 3;
    const int n0 = blockIdx.x * 128;
    const int m0 = blockIdx.y * 128;
    const int wm = (wid >> 2) * 64;
    const int wn = (wid & 3) * 32;

    const int lr = tid >> 1;
    const int lh = tid & 1;

    float acc[4][4][4];
#pragma unroll
    for (int mf = 0; mf < 4; mf++)
#pragma unroll
        for (int nf = 0; nf < 4; nf++)
#pragma unroll
            for (int i = 0; i < 4; i++) acc[mf][nf][i] = 0.f;

    float2 bias2[4];
#pragma unroll
    for (int nf = 0; nf < 4; nf++) {
        const int n = n0 + wn + nf * 8 + tig * 2;
        bias2[nf].x = __ldg(bi + n) + __ldg(bh + n);
        bias2[nf].y = __ldg(bi + n + 1) + __ldg(bh + n + 1);
    }

    for (int kt = 0; kt < 16; kt++) {
        const int koff = kt * 32 + lh * 16;
        const __nv_bfloat16* pa = g_As   + (size_t)(m0 + lr) * 1024 + koff;
        const __nv_bfloat16* pl = pa + 512;
        const __nv_bfloat16* pb = g_WiTh + (size_t)(n0 + lr) * 512 + koff;
        const __nv_bfloat16* pc = g_WiTl + (size_t)(n0 + lr) * 512 + koff;
        uint4 vah0 = *(const uint4*)(pa);
        uint4 vah1 = *(const uint4*)(pa + 8);
        uint4 val0 = *(const uint4*)(pl);
        uint4 val1 = *(const uint4*)(pl + 8);
        uint4 vbh0 = *(const uint4*)(pb);
        uint4 vbh1 = *(const uint4*)(pb + 8);
        uint4 vbl0 = *(const uint4*)(pc);
        uint4 vbl1 = *(const uint4*)(pc + 8);
        __syncthreads();
        __nv_bfloat16* da = Ah + lr * kLds + lh * 16;
        __nv_bfloat16* dl = Al + lr * kLds + lh * 16;
        __nv_bfloat16* db = Bh + lr * kLds + lh * 16;
        __nv_bfloat16* dc = Bl + lr * kLds + lh * 16;
        *(uint4*)(da)     = vah0;
        *(uint4*)(da + 8) = vah1;
        *(uint4*)(dl)     = val0;
        *(uint4*)(dl + 8) = val1;
        *(uint4*)(db)     = vbh0;
        *(uint4*)(db + 8) = vbh1;
        *(uint4*)(dc)     = vbl0;
        *(uint4*)(dc + 8) = vbl1;
        __syncthreads();

        const uint32_t* Ah32 = (const uint32_t*)Ah;
        const uint32_t* Al32 = (const uint32_t*)Al;
        const uint32_t* Bh32 = (const uint32_t*)Bh;
        const uint32_t* Bl32 = (const uint32_t*)Bl;
        constexpr int L = kLds / 2;

#pragma unroll
        for (int ks = 0; ks < 2; ks++) {
            const int kb = ks * 8;
            uint32_t bhf[4][2], blf[4][2];
#pragma unroll
            for (int nf = 0; nf < 4; nf++) {
                const int rn = (wn + nf * 8 + g) * L + kb + tig;
                bhf[nf][0] = Bh32[rn];
                bhf[nf][1] = Bh32[rn + 4];
                blf[nf][0] = Bl32[rn];
                blf[nf][1] = Bl32[rn + 4];
            }
#pragma unroll
            for (int mf = 0; mf < 4; mf++) {
                const int r0 = (wm + mf * 16 + g) * L + kb + tig;
                const int r1 = r0 + 8 * L;
                uint32_t ah[4], al[4];
                ah[0] = Ah32[r0];     ah[1] = Ah32[r1];
                ah[2] = Ah32[r0 + 4]; ah[3] = Ah32[r1 + 4];
                al[0] = Al32[r0];     al[1] = Al32[r1];
                al[2] = Al32[r0 + 4]; al[3] = Al32[r1 + 4];
#pragma unroll
                for (int nf = 0; nf < 4; nf++) {
                    mma_bf16(acc[mf][nf], ah, bhf[nf]);
                    mma_bf16(acc[mf][nf], al, bhf[nf]);
                    mma_bf16(acc[mf][nf], ah, blf[nf]);
                }
            }
        }
    }

#pragma unroll
    for (int mf = 0; mf < 4; mf++) {
        const int m = m0 + wm + mf * 16 + g;
#pragma unroll
        for (int nf = 0; nf < 4; nf++) {
            const int n = n0 + wn + nf * 8 + tig * 2;
            float2 o0, o1;
            o0.x = acc[mf][nf][0] + bias2[nf].x;
            o0.y = acc[mf][nf][1] + bias2[nf].y;
            o1.x = acc[mf][nf][2] + bias2[nf].x;
            o1.y = acc[mf][nf][3] + bias2[nf].y;
            *(float2*)(C + (size_t)m * kG + n)       = o0;
            *(float2*)(C + (size_t)(m + 8) * kG + n) = o1;
        }
    }
}

// ---------------- scoped-atomics group barrier ---------------------------------
__device__ __forceinline__ void gbar_rel(int idx, int tid, int bg)
{
    __syncthreads();
    if (tid == 0) {
        int* cnt = &g_cnt[bg * 32];
        int* flg = &g_flg[bg * 32];
        int prev;
        asm volatile("atom.acq_rel.gpu.global.add.s32 %0, [%1], 1;"
                     : "=r"(prev) : "l"(cnt) : "memory");
        if (prev == idx * kGrpCTA - 1) {
            int dummy;
            asm volatile("atom.release.gpu.global.exch.b32 %0, [%1], %2;"
                         : "=r"(dummy) : "l"(flg), "r"(idx) : "memory");
        } else {
            int v;
            do {
                asm volatile("ld.acquire.gpu.global.s32 %0, [%1];"
                             : "=r"(v) : "l"(flg) : "memory");
            } while (v < idx);
        }
    }
    __syncthreads();
}

// ---------------- persistent HMMA LSTM recurrence ------------------------------
// As R8, but: A-fragments via ldmatrix.x4 (1 op for a0..a3) and FOUR independent
// accumulators (one per split term) to break the 128-MMA dependency chain.
__global__ void __launch_bounds__(256, 1)
lstm_recur_mma(const float* __restrict__ G,
               const __nv_bfloat16* __restrict__ WTh,
               const __nv_bfloat16* __restrict__ WTl,
               float* __restrict__ seqout, float* __restrict__ hT,
               float* __restrict__ cT)
{
    __shared__ __align__(16) __nv_bfloat16 Ahs[16][1032];  // [b][k hi | 512+k lo]
    __shared__ float gs[64 * 20];                          // [col][batch(pad 20)]

    const int tid = threadIdx.x;
    const int cg  = blockIdx.x >> 2;
    const int bg  = blockIdx.x & 3;
    const int u0  = cg * 16;

    const int wid  = tid >> 5;       // n-slice 0..7
    const int lane = tid & 31;
    const int g8   = lane >> 2;      // 0..7
    const int tig  = lane & 3;

    const int pb = tid >> 4;         // local batch 0..15
    const int pu = tid & 15;         // local unit 0..15
    const int bglob = bg * 16 + pb;

    // ldmatrix lane->address mapping for the 16x16 A tile:
    // lanes 0-7: rows 0-7 k0 | 8-15: rows 8-15 k0 | 16-23: rows 0-7 k8 | 24-31: rows 8-15 k8
    const int lrow = ((lane >> 3) & 1) * 8 + (lane & 7);
    const int lcol = (lane >> 4) * 8;
    const uint32_t lm_hi = smem_u32(&Ahs[lrow][lcol]);
    const uint32_t lm_lo = lm_hi + 1024;   // +512 bf16

    // ---- load Wh B-fragments into registers (col c, full K, hi+lo)
    const int c  = wid * 8 + g8;                       // 0..63
    const int ng = (c >> 4) * kH + u0 + (c & 15);      // global gate col
    uint32_t bh[32][2], bl[32][2];
#pragma unroll
    for (int ks = 0; ks < 32; ks++) {
        const int kk = ks * 16 + tig * 2;
        bh[ks][0] = *(const uint32_t*)(WTh + (size_t)ng * 512 + kk);
        bh[ks][1] = *(const uint32_t*)(WTh + (size_t)ng * 512 + kk + 8);
        bl[ks][0] = *(const uint32_t*)(WTl + (size_t)ng * 512 + kk);
        bl[ks][1] = *(const uint32_t*)(WTl + (size_t)ng * 512 + kk + 8);
    }

    g_hbf[0][bglob][u0 + pu]       = __float2bfloat16_rn(0.f);
    g_hbf[0][bglob][512 + u0 + pu] = __float2bfloat16_rn(0.f);
    float c_state = 0.f;

    gbar_rel(1, tid, bg);

    for (int t = 0; t < kT; t++) {
        const int cur = t & 1;

        // prefetch input projection
        const float* gp = G + ((size_t)bglob * kT + t) * kG + u0 + pu;
        const float gin0 = __ldcs(gp);
        const float gin1 = __ldcs(gp + kH);
        const float gin2 = __ldcs(gp + 2 * kH);
        const float gin3 = __ldcs(gp + 3 * kH);

        // stage h hi|lo: 16 rows x 1024 bf16 = 2048 uint4, 8 per thread
#pragma unroll
        for (int j = 0; j < 8; j++) {
            const int e = tid + j * 256;
            const int row = e >> 7;
            const int seg = e & 127;
            const uint4* src = (const uint4*)(&g_hbf[cur][bg * 16 + row][0]) + seg;
            uint4 v = __ldcg(src);
            *(uint4*)(&Ahs[row][seg * 8]) = v;
        }
        __syncthreads();

        // gate GEMM: 16x8 tile per warp, K=512, 4-term split, 4 parallel chains
        float a0[4] = {0.f, 0.f, 0.f, 0.f};
        float a1[4] = {0.f, 0.f, 0.f, 0.f};
        float a2[4] = {0.f, 0.f, 0.f, 0.f};
        float a3[4] = {0.f, 0.f, 0.f, 0.f};
#pragma unroll
        for (int ks = 0; ks < 32; ks++) {
            uint32_t ah[4], al[4];
            ldmx4(ah, lm_hi + ks * 32);
            ldmx4(al, lm_lo + ks * 32);
            mma_bf16(a0, ah, bh[ks]);
            mma_bf16(a1, al, bh[ks]);
            mma_bf16(a2, ah, bl[ks]);
            mma_bf16(a3, al, bl[ks]);
        }
        const int cbase = (c - g8 + tig * 2) * 20;
        gs[cbase + g8]           = a0[0] + a1[0] + a2[0] + a3[0];
        gs[cbase + 20 + g8]      = a0[1] + a1[1] + a2[1] + a3[1];
        gs[cbase + g8 + 8]       = a0[2] + a1[2] + a2[2] + a3[2];
        gs[cbase + 20 + g8 + 8]  = a0[3] + a1[3] + a2[3] + a3[3];
        __syncthreads();

        // pointwise LSTM cell: thread = (pb, pu)
        {
            const float pre0 = gin0 + gs[(0 * 16 + pu) * 20 + pb];
            const float pre1 = gin1 + gs[(1 * 16 + pu) * 20 + pb];
            const float pre2 = gin2 + gs[(2 * 16 + pu) * 20 + pb];
            const float pre3 = gin3 + gs[(3 * 16 + pu) * 20 + pb];
            const float iv = sigf(pre0);
            const float fv = sigf(pre1);
            const float gv = tanh_(pre2);
            const float ov = sigf(pre3);
            c_state = fv * c_state + iv * gv;
            const float hval = ov * tanh_(c_state);

            seqout[((size_t)bglob * kT + t) * kH + u0 + pu] = hval;
            const __nv_bfloat16 hh = __float2bfloat16_rn(hval);
            const __nv_bfloat16 hl = __float2bfloat16_rn(hval - __bfloat162float(hh));
            g_hbf[cur ^ 1][bglob][u0 + pu]       = hh;
            g_hbf[cur ^ 1][bglob][512 + u0 + pu] = hl;
            if (t == kT - 1) {
                hT[(size_t)bglob * kH + u0 + pu] = hval;
                cT[(size_t)bglob * kH + u0 + pu] = c_state;
            }
        }

        gbar_rel(t + 2, tid, bg);
    }
}

// ---------------- launch --------------------------------------------------------
extern "C" void kernel_launch(void* const* d_in, const int* in_sizes, int n_in,
                              void* d_out, int out_size)
{
    const float* x  = (const float*)d_in[0];
    const float* Wi = (const float*)d_in[1];
    const float* Wh = (const float*)d_in[2];
    const float* bi = (const float*)d_in[3];
    const float* bh = (const float*)d_in[4];

    float* out  = (float*)d_out;
    float* outs = out;
    float* hT   = out + (size_t)kB * kT * kH;
    float* cT   = hT + (size_t)2 * kB * kH;

    float* Gp;  cudaGetSymbolAddress((void**)&Gp,  g_G);
    float* h0p; cudaGetSymbolAddress((void**)&h0p, g_h0);
    __nv_bfloat16 *wih, *wil, *whh, *whl;
    cudaGetSymbolAddress((void**)&wih, g_WiTh);
    cudaGetSymbolAddress((void**)&wil, g_WiTl);
    cudaGetSymbolAddress((void**)&whh, g_WhTh);
    cudaGetSymbolAddress((void**)&whl, g_WhTl);

    const dim3 gSplit(64, 16);
    const dim3 gGemm(kG / 128, kM / 128);

    // ---- layer 0
    split_pair<<<gSplit, 256>>>(Wi, wih, wil);
    split_pair<<<gSplit, 256>>>(Wh, whh, whl);
    split_x<<<kM * kH / 1024, 256>>>(x);
    gemm_mma<<<gGemm, 256>>>(bi, bh, Gp);
    lstm_recur_mma<<<kCG * kBG, 256>>>(Gp, whh, whl, h0p, hT, cT);

    // ---- layer 1
    split_pair<<<gSplit, 256>>>(Wi + (size_t)kH * kG, wih, wil);
    split_pair<<<gSplit, 256>>>(Wh + (size_t)kH * kG, whh, whl);
    split_x<<<kM * kH / 1024, 256>>>(h0p);
    gemm_mma<<<gGemm, 256>>>(bi + kG, bh + kG, Gp);
    lstm_recur_mma<<<kCG * kBG, 256>>>(Gp, whh, whl,
                                       outs, hT + (size_t)kB * kH,
                                       cT + (size_t)kB * kH);
}

// round 10
// speedup vs baseline: 2.8911x; 1.0097x over previous
#include <cuda_runtime.h>
#include <cuda_bf16.h>
#include <cstdint>

typedef unsigned long long ull;

constexpr int kB = 64;      // batch
constexpr int kT = 256;     // time
constexpr int kH = 512;     // hidden
constexpr int kG = 2048;    // 4*H gate cols
constexpr int kM = kB * kT; // 16384 GEMM rows
constexpr int kCG = 32;     // column groups (16 hidden units each)
constexpr int kBG = 4;      // batch groups (16 batch elements each)
constexpr int kGrpCTA = kCG;
constexpr int kHRow = 1032;               // padded h row (bf16): hi[0..512)|lo[512..1024)|pad
constexpr int kHTileBytes = 16 * kHRow * 2;  // 33024

// ---------------- scratch ----------------------------------------------------
__device__ float  g_G[(size_t)kM * kG];            // input projections (128 MB)
__device__ float  g_h0[(size_t)kM * kH];           // layer-0 output sequence
__device__ __nv_bfloat16 g_As[(size_t)kM * 1024];  // A split hi|lo (32 MB)
__device__ __nv_bfloat16 g_WiTh[(size_t)kG * kH];  // Wi hi, transposed [N,K]
__device__ __nv_bfloat16 g_WiTl[(size_t)kG * kH];  // Wi lo
__device__ __nv_bfloat16 g_WhTh[(size_t)kG * kH];  // Wh hi, transposed [N,K]
__device__ __nv_bfloat16 g_WhTl[(size_t)kG * kH];  // Wh lo
__device__ __align__(256) __nv_bfloat16 g_hbf[2][kB][kHRow];  // ping-pong h
__device__ int g_cnt[kBG * 32];
__device__ int g_flg[kBG * 32];

// ---------------- helpers -----------------------------------------------------
__device__ __forceinline__ float sigf(float x) {
    x = fminf(fmaxf(x, -30.f), 30.f);
    return 1.f / (1.f + __expf(-x));
}
__device__ __forceinline__ float tanh_(float x) {
    x = fminf(fmaxf(x, -15.f), 15.f);
    float e = __expf(-2.f * x);
    return (1.f - e) / (1.f + e);
}

__device__ __forceinline__ void mma_bf16(float* c, const uint32_t* a,
                                         const uint32_t* b) {
    asm volatile(
        "mma.sync.aligned.m16n8k16.row.col.f32.bf16.bf16.f32 "
        "{%0,%1,%2,%3}, {%4,%5,%6,%7}, {%8,%9}, {%0,%1,%2,%3};"
        : "+f"(c[0]), "+f"(c[1]), "+f"(c[2]), "+f"(c[3])
        : "r"(a[0]), "r"(a[1]), "r"(a[2]), "r"(a[3]), "r"(b[0]), "r"(b[1]));
}
__device__ __forceinline__ void ldmx4(uint32_t* r, uint32_t addr) {
    asm volatile("ldmatrix.sync.aligned.m8n8.x4.shared.b16 {%0,%1,%2,%3}, [%4];"
                 : "=r"(r[0]), "=r"(r[1]), "=r"(r[2]), "=r"(r[3]) : "r"(addr));
}
__device__ __forceinline__ uint32_t smem_u32(const void* p) {
    uint32_t a;
    asm("{ .reg .u64 t; cvta.to.shared.u64 t, %1; cvt.u32.u64 %0, t; }"
        : "=r"(a) : "l"(p));
    return a;
}
__device__ __forceinline__ void mbar_init(uint32_t a, uint32_t cnt) {
    asm volatile("mbarrier.init.shared.b64 [%0], %1;" :: "r"(a), "r"(cnt) : "memory");
}
__device__ __forceinline__ void mbar_wait(uint32_t a, uint32_t parity) {
    asm volatile(
        "{\n\t.reg .pred P;\n\t"
        "WL_%=:\n\t"
        "mbarrier.try_wait.parity.acquire.cta.shared::cta.b64 P, [%0], %1, 0x989680;\n\t"
        "@P bra.uni WD_%=;\n\t"
        "bra.uni WL_%=;\n\t"
        "WD_%=:\n\t}"
        :: "r"(a), "r"(parity) : "memory");
}
__device__ __forceinline__ void bulk_g2s(uint32_t dst, const void* src,
                                         uint32_t bytes, uint32_t mbar) {
    asm volatile(
        "cp.async.bulk.shared::cluster.global.mbarrier::complete_tx::bytes "
        "[%0], [%1], %2, [%3];"
        :: "r"(dst), "l"(src), "r"(bytes), "r"(mbar) : "memory");
}
__device__ __forceinline__ void mbar_expect(uint32_t mbar, uint32_t bytes) {
    asm volatile("mbarrier.arrive.expect_tx.shared.b64 _, [%0], %1;"
                 :: "r"(mbar), "r"(bytes) : "memory");
}

// ---------------- split/prep kernels -------------------------------------------
__global__ void __launch_bounds__(256)
split_x(const float* __restrict__ X)
{
    if (blockIdx.x == 0 && threadIdx.x < kBG) {
        g_cnt[threadIdx.x * 32] = 0;
        g_flg[threadIdx.x * 32] = 0;
    }
    size_t i = ((size_t)blockIdx.x * 256 + threadIdx.x) * 4;
    float4 v = *(const float4*)(X + i);
    size_t m = i >> 9;
    int k = (int)(i & 511);
    __nv_bfloat16 h0 = __float2bfloat16_rn(v.x);
    __nv_bfloat16 h1 = __float2bfloat16_rn(v.y);
    __nv_bfloat16 h2 = __float2bfloat16_rn(v.z);
    __nv_bfloat16 h3 = __float2bfloat16_rn(v.w);
    __nv_bfloat16 l0 = __float2bfloat16_rn(v.x - __bfloat162float(h0));
    __nv_bfloat16 l1 = __float2bfloat16_rn(v.y - __bfloat162float(h1));
    __nv_bfloat16 l2 = __float2bfloat16_rn(v.z - __bfloat162float(h2));
    __nv_bfloat16 l3 = __float2bfloat16_rn(v.w - __bfloat162float(h3));
    __nv_bfloat16* ph = g_As + m * 1024 + k;
    __nv_bfloat16* pl = ph + 512;
    *(__nv_bfloat162*)(ph)     = __nv_bfloat162(h0, h1);
    *(__nv_bfloat162*)(ph + 2) = __nv_bfloat162(h2, h3);
    *(__nv_bfloat162*)(pl)     = __nv_bfloat162(l0, l1);
    *(__nv_bfloat162*)(pl + 2) = __nv_bfloat162(l2, l3);
}

__global__ void __launch_bounds__(256)
split_pair(const float* __restrict__ W, __nv_bfloat16* __restrict__ dH,
           __nv_bfloat16* __restrict__ dL)
{
    __shared__ float tile[32][33];
    const int tx = threadIdx.x & 31;
    const int ty = threadIdx.x >> 5;
    const int n0 = blockIdx.x * 32;
    const int k0 = blockIdx.y * 32;
#pragma unroll
    for (int j = 0; j < 4; j++)
        tile[ty + j * 8][tx] = W[(size_t)(k0 + ty + j * 8) * kG + n0 + tx];
    __syncthreads();
#pragma unroll
    for (int j = 0; j < 4; j++) {
        const int n = n0 + ty + j * 8;
        const int k = k0 + tx;
        const float v = tile[tx][ty + j * 8];
        __nv_bfloat16 hi = __float2bfloat16_rn(v);
        __nv_bfloat16 lo = __float2bfloat16_rn(v - __bfloat162float(hi));
        dH[(size_t)n * kH + k] = hi;
        dL[(size_t)n * kH + k] = lo;
    }
}

// ---------------- HMMA input-projection GEMM (unchanged, passing) --------------
constexpr int kLds = 40;

__global__ void __launch_bounds__(256, 2)
gemm_mma(const float* __restrict__ bi, const float* __restrict__ bh,
         float* __restrict__ C)
{
    __shared__ __align__(16) __nv_bfloat16 Ah[128 * kLds];
    __shared__ __align__(16) __nv_bfloat16 Al[128 * kLds];
    __shared__ __align__(16) __nv_bfloat16 Bh[128 * kLds];
    __shared__ __align__(16) __nv_bfloat16 Bl[128 * kLds];

    const int tid  = threadIdx.x;
    const int wid  = tid >> 5;
    const int lane = tid & 31;
    const int g    = lane >> 2;
    const int tig  = lane & 3;
    const int n0 = blockIdx.x * 128;
    const int m0 = blockIdx.y * 128;
    const int wm = (wid >> 2) * 64;
    const int wn = (wid & 3) * 32;

    const int lr = tid >> 1;
    const int lh = tid & 1;

    float acc[4][4][4];
#pragma unroll
    for (int mf = 0; mf < 4; mf++)
#pragma unroll
        for (int nf = 0; nf < 4; nf++)
#pragma unroll
            for (int i = 0; i < 4; i++) acc[mf][nf][i] = 0.f;

    float2 bias2[4];
#pragma unroll
    for (int nf = 0; nf < 4; nf++) {
        const int n = n0 + wn + nf * 8 + tig * 2;
        bias2[nf].x = __ldg(bi + n) + __ldg(bh + n);
        bias2[nf].y = __ldg(bi + n + 1) + __ldg(bh + n + 1);
    }

    for (int kt = 0; kt < 16; kt++) {
        const int koff = kt * 32 + lh * 16;
        const __nv_bfloat16* pa = g_As   + (size_t)(m0 + lr) * 1024 + koff;
        const __nv_bfloat16* pl = pa + 512;
        const __nv_bfloat16* pb = g_WiTh + (size_t)(n0 + lr) * 512 + koff;
        const __nv_bfloat16* pc = g_WiTl + (size_t)(n0 + lr) * 512 + koff;
        uint4 vah0 = *(const uint4*)(pa);
        uint4 vah1 = *(const uint4*)(pa + 8);
        uint4 val0 = *(const uint4*)(pl);
        uint4 val1 = *(const uint4*)(pl + 8);
        uint4 vbh0 = *(const uint4*)(pb);
        uint4 vbh1 = *(const uint4*)(pb + 8);
        uint4 vbl0 = *(const uint4*)(pc);
        uint4 vbl1 = *(const uint4*)(pc + 8);
        __syncthreads();
        __nv_bfloat16* da = Ah + lr * kLds + lh * 16;
        __nv_bfloat16* dl = Al + lr * kLds + lh * 16;
        __nv_bfloat16* db = Bh + lr * kLds + lh * 16;
        __nv_bfloat16* dc = Bl + lr * kLds + lh * 16;
        *(uint4*)(da)     = vah0;
        *(uint4*)(da + 8) = vah1;
        *(uint4*)(dl)     = val0;
        *(uint4*)(dl + 8) = val1;
        *(uint4*)(db)     = vbh0;
        *(uint4*)(db + 8) = vbh1;
        *(uint4*)(dc)     = vbl0;
        *(uint4*)(dc + 8) = vbl1;
        __syncthreads();

        const uint32_t* Ah32 = (const uint32_t*)Ah;
        const uint32_t* Al32 = (const uint32_t*)Al;
        const uint32_t* Bh32 = (const uint32_t*)Bh;
        const uint32_t* Bl32 = (const uint32_t*)Bl;
        constexpr int L = kLds / 2;

#pragma unroll
        for (int ks = 0; ks < 2; ks++) {
            const int kb = ks * 8;
            uint32_t bhf[4][2], blf[4][2];
#pragma unroll
            for (int nf = 0; nf < 4; nf++) {
                const int rn = (wn + nf * 8 + g) * L + kb + tig;
                bhf[nf][0] = Bh32[rn];
                bhf[nf][1] = Bh32[rn + 4];
                blf[nf][0] = Bl32[rn];
                blf[nf][1] = Bl32[rn + 4];
            }
#pragma unroll
            for (int mf = 0; mf < 4; mf++) {
                const int r0 = (wm + mf * 16 + g) * L + kb + tig;
                const int r1 = r0 + 8 * L;
                uint32_t ah[4], al[4];
                ah[0] = Ah32[r0];     ah[1] = Ah32[r1];
                ah[2] = Ah32[r0 + 4]; ah[3] = Ah32[r1 + 4];
                al[0] = Al32[r0];     al[1] = Al32[r1];
                al[2] = Al32[r0 + 4]; al[3] = Al32[r1 + 4];
#pragma unroll
                for (int nf = 0; nf < 4; nf++) {
                    mma_bf16(acc[mf][nf], ah, bhf[nf]);
                    mma_bf16(acc[mf][nf], al, bhf[nf]);
                    mma_bf16(acc[mf][nf], ah, blf[nf]);
                }
            }
        }
    }

#pragma unroll
    for (int mf = 0; mf < 4; mf++) {
        const int m = m0 + wm + mf * 16 + g;
#pragma unroll
        for (int nf = 0; nf < 4; nf++) {
            const int n = n0 + wn + nf * 8 + tig * 2;
            float2 o0, o1;
            o0.x = acc[mf][nf][0] + bias2[nf].x;
            o0.y = acc[mf][nf][1] + bias2[nf].y;
            o1.x = acc[mf][nf][2] + bias2[nf].x;
            o1.y = acc[mf][nf][3] + bias2[nf].y;
            *(float2*)(C + (size_t)m * kG + n)       = o0;
            *(float2*)(C + (size_t)(m + 8) * kG + n) = o1;
        }
    }
}

// ---------------- scoped-atomics group barrier ---------------------------------
__device__ __forceinline__ void gbar_rel(int idx, int tid, int bg)
{
    __syncthreads();
    if (tid == 0) {
        int* cnt = &g_cnt[bg * 32];
        int* flg = &g_flg[bg * 32];
        int prev;
        asm volatile("atom.acq_rel.gpu.global.add.s32 %0, [%1], 1;"
                     : "=r"(prev) : "l"(cnt) : "memory");
        if (prev == idx * kGrpCTA - 1) {
            int dummy;
            asm volatile("atom.release.gpu.global.exch.b32 %0, [%1], %2;"
                         : "=r"(dummy) : "l"(flg), "r"(idx) : "memory");
        } else {
            int v;
            do {
                asm volatile("ld.acquire.gpu.global.s32 %0, [%1];"
                             : "=r"(v) : "l"(flg) : "memory");
            } while (v < idx);
        }
    }
    __syncthreads();
}

// ---------------- persistent HMMA LSTM recurrence ------------------------------
// R9 + LSU diet: h staged by ONE cp.async.bulk (33KB) per step; G prefetched
// via 256 coalesced LDG.128 into SMEM; writeback gathered in SMEM and emitted
// as 128 STG.128; 3-term bf16 split (drop al*bl).
__global__ void __launch_bounds__(256, 1)
lstm_recur_mma(const float* __restrict__ G,
               const __nv_bfloat16* __restrict__ WTh,
               const __nv_bfloat16* __restrict__ WTl,
               float* __restrict__ seqout, float* __restrict__ hT,
               float* __restrict__ cT)
{
    __shared__ __align__(128) __nv_bfloat16 Ahs[16][kHRow];  // bulk-copied h tile
    __shared__ float gs[64 * 20];          // [col][batch pad20]
    __shared__ float Gs[16][68];           // staged input projections
    __shared__ float outF[16][16];         // h (fp32) for seqout
    __shared__ __nv_bfloat16 outB[16][32]; // h hi|lo for exchange
    __shared__ __align__(8) ull s_mbar;

    const int tid = threadIdx.x;
    const int cg  = blockIdx.x >> 2;
    const int bg  = blockIdx.x & 3;
    const int u0  = cg * 16;

    const int wid  = tid >> 5;
    const int lane = tid & 31;
    const int g8   = lane >> 2;
    const int tig  = lane & 3;

    const int pb = tid >> 4;
    const int pu = tid & 15;
    const int bglob = bg * 16 + pb;

    const uint32_t mbar = smem_u32(&s_mbar);
    const uint32_t ahsAddr = smem_u32(&Ahs[0][0]);

    // ldmatrix lane mapping (16x16 A tile)
    const int lrow = ((lane >> 3) & 1) * 8 + (lane & 7);
    const int lcol = (lane >> 4) * 8;
    const uint32_t lm_hi = smem_u32(&Ahs[lrow][lcol]);
    const uint32_t lm_lo = lm_hi + 1024;

    // ---- Wh B-fragments in registers (col c, full K, hi+lo)
    const int c  = wid * 8 + g8;
    const int ng = (c >> 4) * kH + u0 + (c & 15);
    uint32_t bfh[32][2], bfl[32][2];
#pragma unroll
    for (int ks = 0; ks < 32; ks++) {
        const int kk = ks * 16 + tig * 2;
        bfh[ks][0] = *(const uint32_t*)(WTh + (size_t)ng * 512 + kk);
        bfh[ks][1] = *(const uint32_t*)(WTh + (size_t)ng * 512 + kk + 8);
        bfl[ks][0] = *(const uint32_t*)(WTl + (size_t)ng * 512 + kk);
        bfl[ks][1] = *(const uint32_t*)(WTl + (size_t)ng * 512 + kk + 8);
    }

    // zero our slice of the h ping buffer (parity 0)
    g_hbf[0][bglob][u0 + pu]       = __float2bfloat16_rn(0.f);
    g_hbf[0][bglob][512 + u0 + pu] = __float2bfloat16_rn(0.f);
    float c_state = 0.f;
    if (tid == 0) mbar_init(mbar, 1);

    gbar_rel(1, tid, bg);

    for (int t = 0; t < kT; t++) {
        const int cur = t & 1;

        // one bulk copy stages the whole 16-row h tile (hi|lo) into SMEM
        if (tid == 0) {
            mbar_expect(mbar, kHTileBytes);
            bulk_g2s(ahsAddr, &g_hbf[cur][bg * 16][0], kHTileBytes, mbar);
        }

        // stage this step's input projections: 1 coalesced float4 per thread
        {
            const int b = tid >> 4, q = tid & 15;
            const int g = q >> 2, f = q & 3;
            const float* src = G + ((size_t)(bg * 16 + b) * kT + t) * kG
                             + g * kH + u0 + f * 4;
            float4 v = __ldcs((const float4*)src);
            *(float4*)&Gs[b][g * 16 + f * 4] = v;
        }

        mbar_wait(mbar, t & 1);

        // gate GEMM: 16x8 tile per warp, K=512, 3-term split, 3 parallel chains
        float a0[4] = {0.f, 0.f, 0.f, 0.f};
        float a1[4] = {0.f, 0.f, 0.f, 0.f};
        float a2[4] = {0.f, 0.f, 0.f, 0.f};
#pragma unroll
        for (int ks = 0; ks < 32; ks++) {
            uint32_t ah[4], al[4];
            ldmx4(ah, lm_hi + ks * 32);
            ldmx4(al, lm_lo + ks * 32);
            mma_bf16(a0, ah, bfh[ks]);
            mma_bf16(a1, al, bfh[ks]);
            mma_bf16(a2, ah, bfl[ks]);
        }
        const int cbase = (c - g8 + tig * 2) * 20;
        gs[cbase + g8]          = a0[0] + a1[0] + a2[0];
        gs[cbase + 20 + g8]     = a0[1] + a1[1] + a2[1];
        gs[cbase + g8 + 8]      = a0[2] + a1[2] + a2[2];
        gs[cbase + 20 + g8 + 8] = a0[3] + a1[3] + a2[3];
        __syncthreads();

        // pointwise LSTM cell: thread = (pb, pu); outputs gathered in SMEM
        {
            const float pre0 = Gs[pb][0 * 16 + pu] + gs[(0 * 16 + pu) * 20 + pb];
            const float pre1 = Gs[pb][1 * 16 + pu] + gs[(1 * 16 + pu) * 20 + pb];
            const float pre2 = Gs[pb][2 * 16 + pu] + gs[(2 * 16 + pu) * 20 + pb];
            const float pre3 = Gs[pb][3 * 16 + pu] + gs[(3 * 16 + pu) * 20 + pb];
            const float iv = sigf(pre0);
            const float fv = sigf(pre1);
            const float gv = tanh_(pre2);
            const float ov = sigf(pre3);
            c_state = fv * c_state + iv * gv;
            const float hval = ov * tanh_(c_state);

            outF[pb][pu] = hval;
            const __nv_bfloat16 hh = __float2bfloat16_rn(hval);
            const __nv_bfloat16 hl = __float2bfloat16_rn(hval - __bfloat162float(hh));
            outB[pb][pu]      = hh;
            outB[pb][16 + pu] = hl;
            if (t == kT - 1) {
                hT[(size_t)bglob * kH + u0 + pu] = hval;
                cT[(size_t)bglob * kH + u0 + pu] = c_state;
            }
        }
        __syncthreads();

        // gathered writeback: 64 threads, 128 STG.128 total
        if (tid < 64) {
            const int b = tid >> 2, f = tid & 3;
            const int bg16 = bg * 16 + b;
            // seqout: 16 floats per batch = 4 uint4
            *(uint4*)(seqout + ((size_t)bg16 * kT + t) * kH + u0 + f * 4) =
                *(const uint4*)&outF[b][f * 4];
            // h exchange: parts 0,1 = hi units 0-7 / 8-15; parts 2,3 = lo
            const int elem = (f < 2) ? (u0 + f * 8) : (512 + u0 + (f - 2) * 8);
            *(uint4*)(&g_hbf[cur ^ 1][bg16][elem]) = *(const uint4*)&outB[b][f * 8];
        }

        gbar_rel(t + 2, tid, bg);
    }
}

// ---------------- launch --------------------------------------------------------
extern "C" void kernel_launch(void* const* d_in, const int* in_sizes, int n_in,
                              void* d_out, int out_size)
{
    const float* x  = (const float*)d_in[0];
    const float* Wi = (const float*)d_in[1];
    const float* Wh = (const float*)d_in[2];
    const float* bi = (const float*)d_in[3];
    const float* bh = (const float*)d_in[4];

    float* out  = (float*)d_out;
    float* outs = out;
    float* hT   = out + (size_t)kB * kT * kH;
    float* cT   = hT + (size_t)2 * kB * kH;

    float* Gp;  cudaGetSymbolAddress((void**)&Gp,  g_G);
    float* h0p; cudaGetSymbolAddress((void**)&h0p, g_h0);
    __nv_bfloat16 *wih, *wil, *whh, *whl;
    cudaGetSymbolAddress((void**)&wih, g_WiTh);
    cudaGetSymbolAddress((void**)&wil, g_WiTl);
    cudaGetSymbolAddress((void**)&whh, g_WhTh);
    cudaGetSymbolAddress((void**)&whl, g_WhTl);

    const dim3 gSplit(64, 16);
    const dim3 gGemm(kG / 128, kM / 128);

    // ---- layer 0
    split_pair<<<gSplit, 256>>>(Wi, wih, wil);
    split_pair<<<gSplit, 256>>>(Wh, whh, whl);
    split_x<<<kM * kH / 1024, 256>>>(x);
    gemm_mma<<<gGemm, 256>>>(bi, bh, Gp);
    lstm_recur_mma<<<kCG * kBG, 256>>>(Gp, whh, whl, h0p, hT, cT);

    // ---- layer 1
    split_pair<<<gSplit, 256>>>(Wi + (size_t)kH * kG, wih, wil);
    split_pair<<<gSplit, 256>>>(Wh + (size_t)kH * kG, whh, whl);
    split_x<<<kM * kH / 1024, 256>>>(h0p);
    gemm_mma<<<gGemm, 256>>>(bi + kG, bh + kG, Gp);
    lstm_recur_mma<<<kCG * kBG, 256>>>(Gp, whh, whl,
                                       outs, hT + (size_t)kB * kH,
                                       cT + (size_t)kB * kH);
}

// round 11
// speedup vs baseline: 3.3315x; 1.1523x over previous
#include <cuda_runtime.h>
#include <cuda_bf16.h>
#include <cstdint>

typedef unsigned long long ull;

constexpr int kB = 64;      // batch
constexpr int kT = 256;     // time
constexpr int kH = 512;     // hidden
constexpr int kG = 2048;    // 4*H gate cols
constexpr int kM = kB * kT; // 16384 GEMM rows
constexpr int kCG = 32;     // column groups (16 hidden units each)
constexpr int kBG = 4;      // batch groups (16 batch elements each)
constexpr int kGrpCTA = kCG;
constexpr int kHRow = 1032;               // padded h row (bf16): hi|lo|pad
constexpr int kHTileBytes = 16 * kHRow * 2;  // 33024

// ---------------- scratch ----------------------------------------------------
__device__ float  g_G[(size_t)kM * kG];            // input projections (128 MB)
__device__ float  g_h0[(size_t)kM * kH];           // layer-0 output sequence
__device__ __nv_bfloat16 g_As[(size_t)kM * 1024];  // A split hi|lo (32 MB)
__device__ __nv_bfloat16 g_WiTh[(size_t)kG * kH];  // Wi hi, transposed [N,K]
__device__ __nv_bfloat16 g_WiTl[(size_t)kG * kH];  // Wi lo
__device__ __nv_bfloat16 g_WhTh[(size_t)kG * kH];  // Wh hi, transposed [N,K]
__device__ __nv_bfloat16 g_WhTl[(size_t)kG * kH];  // Wh lo
__device__ __align__(256) __nv_bfloat16 g_hbf[2][kB][kHRow];  // ping-pong h
__device__ int g_cnt[kBG * 32];                    // initial barrier
__device__ int g_flg[kBG * 32];
__device__ int g_hflag[kBG][32 * 32];              // per-producer step flags

// ---------------- helpers -----------------------------------------------------
__device__ __forceinline__ float sigf(float x) {
    x = fminf(fmaxf(x, -30.f), 30.f);
    return 1.f / (1.f + __expf(-x));
}
__device__ __forceinline__ float tanh_(float x) {
    x = fminf(fmaxf(x, -15.f), 15.f);
    float e = __expf(-2.f * x);
    return (1.f - e) / (1.f + e);
}

__device__ __forceinline__ void mma_bf16(float* c, const uint32_t* a,
                                         const uint32_t* b) {
    asm volatile(
        "mma.sync.aligned.m16n8k16.row.col.f32.bf16.bf16.f32 "
        "{%0,%1,%2,%3}, {%4,%5,%6,%7}, {%8,%9}, {%0,%1,%2,%3};"
        : "+f"(c[0]), "+f"(c[1]), "+f"(c[2]), "+f"(c[3])
        : "r"(a[0]), "r"(a[1]), "r"(a[2]), "r"(a[3]), "r"(b[0]), "r"(b[1]));
}
__device__ __forceinline__ void ldmx4(uint32_t* r, uint32_t addr) {
    asm volatile("ldmatrix.sync.aligned.m8n8.x4.shared.b16 {%0,%1,%2,%3}, [%4];"
                 : "=r"(r[0]), "=r"(r[1]), "=r"(r[2]), "=r"(r[3]) : "r"(addr));
}
__device__ __forceinline__ void ldmx2(uint32_t* r, uint32_t addr) {
    asm volatile("ldmatrix.sync.aligned.m8n8.x2.shared.b16 {%0,%1}, [%2];"
                 : "=r"(r[0]), "=r"(r[1]) : "r"(addr));
}
__device__ __forceinline__ uint32_t smem_u32(const void* p) {
    uint32_t a;
    asm("{ .reg .u64 t; cvta.to.shared.u64 t, %1; cvt.u32.u64 %0, t; }"
        : "=r"(a) : "l"(p));
    return a;
}
__device__ __forceinline__ void mbar_init(uint32_t a, uint32_t cnt) {
    asm volatile("mbarrier.init.shared.b64 [%0], %1;" :: "r"(a), "r"(cnt) : "memory");
}
__device__ __forceinline__ void mbar_wait(uint32_t a, uint32_t parity) {
    asm volatile(
        "{\n\t.reg .pred P;\n\t"
        "WL_%=:\n\t"
        "mbarrier.try_wait.parity.acquire.cta.shared::cta.b64 P, [%0], %1, 0x989680;\n\t"
        "@P bra.uni WD_%=;\n\t"
        "bra.uni WL_%=;\n\t"
        "WD_%=:\n\t}"
        :: "r"(a), "r"(parity) : "memory");
}
__device__ __forceinline__ void bulk_g2s(uint32_t dst, const void* src,
                                         uint32_t bytes, uint32_t mbar) {
    asm volatile(
        "cp.async.bulk.shared::cluster.global.mbarrier::complete_tx::bytes "
        "[%0], [%1], %2, [%3];"
        :: "r"(dst), "l"(src), "r"(bytes), "r"(mbar) : "memory");
}
__device__ __forceinline__ void mbar_expect(uint32_t mbar, uint32_t bytes) {
    asm volatile("mbarrier.arrive.expect_tx.shared.b64 _, [%0], %1;"
                 :: "r"(mbar), "r"(bytes) : "memory");
}

// ---------------- split/prep kernels -------------------------------------------
__global__ void __launch_bounds__(256)
split_x(const float* __restrict__ X)
{
    if (blockIdx.x == 0) {
        if (threadIdx.x < kBG) {
            g_cnt[threadIdx.x * 32] = 0;
            g_flg[threadIdx.x * 32] = 0;
        }
        for (int i = threadIdx.x; i < kBG * 32 * 32; i += 256)
            ((int*)g_hflag)[i] = 0;
    }
    size_t i = ((size_t)blockIdx.x * 256 + threadIdx.x) * 4;
    float4 v = *(const float4*)(X + i);
    size_t m = i >> 9;
    int k = (int)(i & 511);
    __nv_bfloat16 h0 = __float2bfloat16_rn(v.x);
    __nv_bfloat16 h1 = __float2bfloat16_rn(v.y);
    __nv_bfloat16 h2 = __float2bfloat16_rn(v.z);
    __nv_bfloat16 h3 = __float2bfloat16_rn(v.w);
    __nv_bfloat16 l0 = __float2bfloat16_rn(v.x - __bfloat162float(h0));
    __nv_bfloat16 l1 = __float2bfloat16_rn(v.y - __bfloat162float(h1));
    __nv_bfloat16 l2 = __float2bfloat16_rn(v.z - __bfloat162float(h2));
    __nv_bfloat16 l3 = __float2bfloat16_rn(v.w - __bfloat162float(h3));
    __nv_bfloat16* ph = g_As + m * 1024 + k;
    __nv_bfloat16* pl = ph + 512;
    *(__nv_bfloat162*)(ph)     = __nv_bfloat162(h0, h1);
    *(__nv_bfloat162*)(ph + 2) = __nv_bfloat162(h2, h3);
    *(__nv_bfloat162*)(pl)     = __nv_bfloat162(l0, l1);
    *(__nv_bfloat162*)(pl + 2) = __nv_bfloat162(l2, l3);
}

__global__ void __launch_bounds__(256)
split_pair(const float* __restrict__ W, __nv_bfloat16* __restrict__ dH,
           __nv_bfloat16* __restrict__ dL)
{
    __shared__ float tile[32][33];
    const int tx = threadIdx.x & 31;
    const int ty = threadIdx.x >> 5;
    const int n0 = blockIdx.x * 32;
    const int k0 = blockIdx.y * 32;
#pragma unroll
    for (int j = 0; j < 4; j++)
        tile[ty + j * 8][tx] = W[(size_t)(k0 + ty + j * 8) * kG + n0 + tx];
    __syncthreads();
#pragma unroll
    for (int j = 0; j < 4; j++) {
        const int n = n0 + ty + j * 8;
        const int k = k0 + tx;
        const float v = tile[tx][ty + j * 8];
        __nv_bfloat16 hi = __float2bfloat16_rn(v);
        __nv_bfloat16 lo = __float2bfloat16_rn(v - __bfloat162float(hi));
        dH[(size_t)n * kH + k] = hi;
        dL[(size_t)n * kH + k] = lo;
    }
}

// ---------------- HMMA input-projection GEMM (ldmatrix fragments) --------------
constexpr int kLds = 40;   // padded row (bf16); 80B row stride, ldmatrix-safe

__global__ void __launch_bounds__(256, 2)
gemm_mma(const float* __restrict__ bi, const float* __restrict__ bh,
         float* __restrict__ C)
{
    __shared__ __align__(16) __nv_bfloat16 Ah[128 * kLds];
    __shared__ __align__(16) __nv_bfloat16 Al[128 * kLds];
    __shared__ __align__(16) __nv_bfloat16 Bh[128 * kLds];
    __shared__ __align__(16) __nv_bfloat16 Bl[128 * kLds];

    const int tid  = threadIdx.x;
    const int wid  = tid >> 5;
    const int lane = tid & 31;
    const int g    = lane >> 2;
    const int tig  = lane & 3;
    const int n0 = blockIdx.x * 128;
    const int m0 = blockIdx.y * 128;
    const int wm = (wid >> 2) * 64;
    const int wn = (wid & 3) * 32;

    const int lr = tid >> 1;
    const int lh = tid & 1;

    // ldmatrix lane addressing
    const int lrow = ((lane >> 3) & 1) * 8 + (lane & 7);
    const int lcolB = (lane >> 4) * 16;           // byte offset in k16 segment (A)
    const uint32_t aBaseH = smem_u32(Ah) + ((wm + lrow) * kLds) * 2 + lcolB;
    const uint32_t aBaseL = smem_u32(Al) + ((wm + lrow) * kLds) * 2 + lcolB;
    const int brow = wn + (lane & 7);
    const int bcolB = ((lane >> 3) & 1) * 16;     // matrix1 = k+8
    const uint32_t bBaseH = smem_u32(Bh) + (brow * kLds) * 2 + bcolB;
    const uint32_t bBaseL = smem_u32(Bl) + (brow * kLds) * 2 + bcolB;

    float acc[4][4][4];
#pragma unroll
    for (int mf = 0; mf < 4; mf++)
#pragma unroll
        for (int nf = 0; nf < 4; nf++)
#pragma unroll
            for (int i = 0; i < 4; i++) acc[mf][nf][i] = 0.f;

    float2 bias2[4];
#pragma unroll
    for (int nf = 0; nf < 4; nf++) {
        const int n = n0 + wn + nf * 8 + tig * 2;
        bias2[nf].x = __ldg(bi + n) + __ldg(bh + n);
        bias2[nf].y = __ldg(bi + n + 1) + __ldg(bh + n + 1);
    }

    for (int kt = 0; kt < 16; kt++) {
        const int koff = kt * 32 + lh * 16;
        const __nv_bfloat16* pa = g_As   + (size_t)(m0 + lr) * 1024 + koff;
        const __nv_bfloat16* pl = pa + 512;
        const __nv_bfloat16* pb = g_WiTh + (size_t)(n0 + lr) * 512 + koff;
        const __nv_bfloat16* pc = g_WiTl + (size_t)(n0 + lr) * 512 + koff;
        uint4 vah0 = *(const uint4*)(pa);
        uint4 vah1 = *(const uint4*)(pa + 8);
        uint4 val0 = *(const uint4*)(pl);
        uint4 val1 = *(const uint4*)(pl + 8);
        uint4 vbh0 = *(const uint4*)(pb);
        uint4 vbh1 = *(const uint4*)(pb + 8);
        uint4 vbl0 = *(const uint4*)(pc);
        uint4 vbl1 = *(const uint4*)(pc + 8);
        __syncthreads();
        __nv_bfloat16* da = Ah + lr * kLds + lh * 16;
        __nv_bfloat16* dl = Al + lr * kLds + lh * 16;
        __nv_bfloat16* db = Bh + lr * kLds + lh * 16;
        __nv_bfloat16* dc = Bl + lr * kLds + lh * 16;
        *(uint4*)(da)     = vah0;
        *(uint4*)(da + 8) = vah1;
        *(uint4*)(dl)     = val0;
        *(uint4*)(dl + 8) = val1;
        *(uint4*)(db)     = vbh0;
        *(uint4*)(db + 8) = vbh1;
        *(uint4*)(dc)     = vbl0;
        *(uint4*)(dc + 8) = vbl1;
        __syncthreads();

#pragma unroll
        for (int ks = 0; ks < 2; ks++) {
            const int kOff = ks * 32;   // bytes: 16 bf16 per ks step
            uint32_t bhf[4][2], blf[4][2];
#pragma unroll
            for (int nf = 0; nf < 4; nf++) {
                ldmx2(bhf[nf], bBaseH + nf * 8 * kLds * 2 + kOff);
                ldmx2(blf[nf], bBaseL + nf * 8 * kLds * 2 + kOff);
            }
#pragma unroll
            for (int mf = 0; mf < 4; mf++) {
                uint32_t ah[4], al[4];
                ldmx4(ah, aBaseH + mf * 16 * kLds * 2 + kOff);
                ldmx4(al, aBaseL + mf * 16 * kLds * 2 + kOff);
#pragma unroll
                for (int nf = 0; nf < 4; nf++) {
                    mma_bf16(acc[mf][nf], ah, bhf[nf]);
                    mma_bf16(acc[mf][nf], al, bhf[nf]);
                    mma_bf16(acc[mf][nf], ah, blf[nf]);
                }
            }
        }
    }

#pragma unroll
    for (int mf = 0; mf < 4; mf++) {
        const int m = m0 + wm + mf * 16 + g;
#pragma unroll
        for (int nf = 0; nf < 4; nf++) {
            const int n = n0 + wn + nf * 8 + tig * 2;
            float2 o0, o1;
            o0.x = acc[mf][nf][0] + bias2[nf].x;
            o0.y = acc[mf][nf][1] + bias2[nf].y;
            o1.x = acc[mf][nf][2] + bias2[nf].x;
            o1.y = acc[mf][nf][3] + bias2[nf].y;
            *(float2*)(C + (size_t)m * kG + n)       = o0;
            *(float2*)(C + (size_t)(m + 8) * kG + n) = o1;
        }
    }
}

// ---------------- initial group barrier (once) ----------------------------------
__device__ __forceinline__ void gbar_rel(int idx, int tid, int bg)
{
    __syncthreads();
    if (tid == 0) {
        int* cnt = &g_cnt[bg * 32];
        int* flg = &g_flg[bg * 32];
        int prev;
        asm volatile("atom.acq_rel.gpu.global.add.s32 %0, [%1], 1;"
                     : "=r"(prev) : "l"(cnt) : "memory");
        if (prev == idx * kGrpCTA - 1) {
            int dummy;
            asm volatile("atom.release.gpu.global.exch.b32 %0, [%1], %2;"
                         : "=r"(dummy) : "l"(flg), "r"(idx) : "memory");
        } else {
            int v;
            do {
                asm volatile("ld.acquire.gpu.global.s32 %0, [%1];"
                             : "=r"(v) : "l"(flg) : "memory");
            } while (v < idx);
        }
    }
    __syncthreads();
}

// ---------------- persistent HMMA LSTM recurrence ------------------------------
// R10 + per-producer flag sync: no per-step counting barrier. Warp 0 polls the
// 32 producer flags in parallel (1 lane each) and issues the bulk h copy; other
// warps wait only on the mbarrier. Flag published via st.release.gpu after the
// h-exchange writeback (done by warp 0). Double buffering bounds skew to 1 step.
__global__ void __launch_bounds__(256, 1)
lstm_recur_mma(const float* __restrict__ G,
               const __nv_bfloat16* __restrict__ WTh,
               const __nv_bfloat16* __restrict__ WTl,
               float* __restrict__ seqout, float* __restrict__ hT,
               float* __restrict__ cT)
{
    __shared__ __align__(128) __nv_bfloat16 Ahs[16][kHRow];
    __shared__ float gs[64 * 20];
    __shared__ float Gs[16][68];
    __shared__ float outF[16][16];
    __shared__ __nv_bfloat16 outB[16][32];
    __shared__ __align__(8) ull s_mbar;

    const int tid = threadIdx.x;
    const int cg  = blockIdx.x >> 2;
    const int bg  = blockIdx.x & 3;
    const int u0  = cg * 16;

    const int wid  = tid >> 5;
    const int lane = tid & 31;
    const int g8   = lane >> 2;
    const int tig  = lane & 3;

    const int pb = tid >> 4;
    const int pu = tid & 15;
    const int bglob = bg * 16 + pb;

    const uint32_t mbar = smem_u32(&s_mbar);
    const uint32_t ahsAddr = smem_u32(&Ahs[0][0]);

    const int lrow = ((lane >> 3) & 1) * 8 + (lane & 7);
    const int lcol = (lane >> 4) * 8;
    const uint32_t lm_hi = smem_u32(&Ahs[lrow][lcol]);
    const uint32_t lm_lo = lm_hi + 1024;

    // Wh B-fragments in registers (col c, full K, hi+lo)
    const int c  = wid * 8 + g8;
    const int ng = (c >> 4) * kH + u0 + (c & 15);
    uint32_t bfh[32][2], bfl[32][2];
#pragma unroll
    for (int ks = 0; ks < 32; ks++) {
        const int kk = ks * 16 + tig * 2;
        bfh[ks][0] = *(const uint32_t*)(WTh + (size_t)ng * 512 + kk);
        bfh[ks][1] = *(const uint32_t*)(WTh + (size_t)ng * 512 + kk + 8);
        bfl[ks][0] = *(const uint32_t*)(WTl + (size_t)ng * 512 + kk);
        bfl[ks][1] = *(const uint32_t*)(WTl + (size_t)ng * 512 + kk + 8);
    }

    g_hbf[0][bglob][u0 + pu]       = __float2bfloat16_rn(0.f);
    g_hbf[0][bglob][512 + u0 + pu] = __float2bfloat16_rn(0.f);
    float c_state = 0.f;
    if (tid == 0) mbar_init(mbar, 1);

    gbar_rel(1, tid, bg);   // once: h(0) + flags visible everywhere

    for (int t = 0; t < kT; t++) {
        const int cur = t & 1;

        // stage this step's input projections (independent of h)
        {
            const int b = tid >> 4, q = tid & 15;
            const int gg = q >> 2, f = q & 3;
            const float* src = G + ((size_t)(bg * 16 + b) * kT + t) * kG
                             + gg * kH + u0 + f * 4;
            float4 v = __ldcs((const float4*)src);
            *(float4*)&Gs[b][gg * 16 + f * 4] = v;
        }

        // warp 0: parallel flag poll, then issue the bulk h copy
        if (wid == 0) {
            if (t > 0) {
                const int* fp = &g_hflag[bg][lane * 32];
                int v;
                do {
                    asm volatile("ld.acquire.gpu.global.s32 %0, [%1];"
                                 : "=r"(v) : "l"(fp) : "memory");
                } while (v < t);
            }
            __syncwarp();
            if (lane == 0) {
                mbar_expect(mbar, kHTileBytes);
                bulk_g2s(ahsAddr, &g_hbf[cur][bg * 16][0], kHTileBytes, mbar);
            }
        }
        mbar_wait(mbar, t & 1);

        // gate GEMM: 16x8 per warp, K=512, 3-term split, 3 parallel chains
        float a0[4] = {0.f, 0.f, 0.f, 0.f};
        float a1[4] = {0.f, 0.f, 0.f, 0.f};
        float a2[4] = {0.f, 0.f, 0.f, 0.f};
#pragma unroll
        for (int ks = 0; ks < 32; ks++) {
            uint32_t ah[4], al[4];
            ldmx4(ah, lm_hi + ks * 32);
            ldmx4(al, lm_lo + ks * 32);
            mma_bf16(a0, ah, bfh[ks]);
            mma_bf16(a1, al, bfh[ks]);
            mma_bf16(a2, ah, bfl[ks]);
        }
        const int cbase = (c - g8 + tig * 2) * 20;
        gs[cbase + g8]          = a0[0] + a1[0] + a2[0];
        gs[cbase + 20 + g8]     = a0[1] + a1[1] + a2[1];
        gs[cbase + g8 + 8]      = a0[2] + a1[2] + a2[2];
        gs[cbase + 20 + g8 + 8] = a0[3] + a1[3] + a2[3];
        __syncthreads();

        // pointwise LSTM cell
        {
            const float pre0 = Gs[pb][0 * 16 + pu] + gs[(0 * 16 + pu) * 20 + pb];
            const float pre1 = Gs[pb][1 * 16 + pu] + gs[(1 * 16 + pu) * 20 + pb];
            const float pre2 = Gs[pb][2 * 16 + pu] + gs[(2 * 16 + pu) * 20 + pb];
            const float pre3 = Gs[pb][3 * 16 + pu] + gs[(3 * 16 + pu) * 20 + pb];
            const float iv = sigf(pre0);
            const float fv = sigf(pre1);
            const float gv = tanh_(pre2);
            const float ov = sigf(pre3);
            c_state = fv * c_state + iv * gv;
            const float hval = ov * tanh_(c_state);

            outF[pb][pu] = hval;
            const __nv_bfloat16 hh = __float2bfloat16_rn(hval);
            const __nv_bfloat16 hl = __float2bfloat16_rn(hval - __bfloat162float(hh));
            outB[pb][pu]      = hh;
            outB[pb][16 + pu] = hl;
            if (t == kT - 1) {
                hT[(size_t)bglob * kH + u0 + pu] = hval;
                cT[(size_t)bglob * kH + u0 + pu] = c_state;
            }
        }
        __syncthreads();

        // warp 0: h-exchange writeback + flag publish; warps 1-2: seqout
        if (wid == 0) {
#pragma unroll
            for (int j = 0; j < 2; j++) {
                const int e = lane * 2 + j;        // 0..63
                const int b = e >> 2, f = e & 3;
                const int bg16 = bg * 16 + b;
                const int elem = (f < 2) ? (u0 + f * 8)
                                         : (512 + u0 + (f - 2) * 8);
                *(uint4*)(&g_hbf[cur ^ 1][bg16][elem]) =
                    *(const uint4*)&outB[b][f * 8];
            }
            __syncwarp();
            if (lane == 0) {
                asm volatile("st.release.gpu.global.s32 [%0], %1;"
                             :: "l"(&g_hflag[bg][cg * 32]), "r"(t + 1) : "memory");
            }
        } else if (wid < 3) {
            const int e = tid - 32;                // 0..63
            const int b = e >> 2, f = e & 3;
            *(uint4*)(seqout + ((size_t)(bg * 16 + b) * kT + t) * kH + u0 + f * 4) =
                *(const uint4*)&outF[b][f * 4];
        }
        // no CTA-wide barrier: Ahs/gs/outF reuse is protected by the next
        // step's mbar_wait + post-gs syncthreads (all threads pass through both)
    }
}

// ---------------- launch --------------------------------------------------------
extern "C" void kernel_launch(void* const* d_in, const int* in_sizes, int n_in,
                              void* d_out, int out_size)
{
    const float* x  = (const float*)d_in[0];
    const float* Wi = (const float*)d_in[1];
    const float* Wh = (const float*)d_in[2];
    const float* bi = (const float*)d_in[3];
    const float* bh = (const float*)d_in[4];

    float* out  = (float*)d_out;
    float* outs = out;
    float* hT   = out + (size_t)kB * kT * kH;
    float* cT   = hT + (size_t)2 * kB * kH;

    float* Gp;  cudaGetSymbolAddress((void**)&Gp,  g_G);
    float* h0p; cudaGetSymbolAddress((void**)&h0p, g_h0);
    __nv_bfloat16 *wih, *wil, *whh, *whl;
    cudaGetSymbolAddress((void**)&wih, g_WiTh);
    cudaGetSymbolAddress((void**)&wil, g_WiTl);
    cudaGetSymbolAddress((void**)&whh, g_WhTh);
    cudaGetSymbolAddress((void**)&whl, g_WhTl);

    const dim3 gSplit(64, 16);
    const dim3 gGemm(kG / 128, kM / 128);

    // ---- layer 0
    split_pair<<<gSplit, 256>>>(Wi, wih, wil);
    split_pair<<<gSplit, 256>>>(Wh, whh, whl);
    split_x<<<kM * kH / 1024, 256>>>(x);
    gemm_mma<<<gGemm, 256>>>(bi, bh, Gp);
    lstm_recur_mma<<<kCG * kBG, 256>>>(Gp, whh, whl, h0p, hT, cT);

    // ---- layer 1
    split_pair<<<gSplit, 256>>>(Wi + (size_t)kH * kG, wih, wil);
    split_pair<<<gSplit, 256>>>(Wh + (size_t)kH * kG, whh, whl);
    split_x<<<kM * kH / 1024, 256>>>(h0p);
    gemm_mma<<<gGemm, 256>>>(bi + kG, bh + kG, Gp);
    lstm_recur_mma<<<kCG * kBG, 256>>>(Gp, whh, whl,
                                       outs, hT + (size_t)kB * kH,
                                       cT + (size_t)kB * kH);
}

// round 12
// speedup vs baseline: 3.3460x; 1.0043x over previous
#include <cuda_runtime.h>
#include <cuda_bf16.h>
#include <cstdint>

typedef unsigned long long ull;

constexpr int kB = 64;      // batch
constexpr int kT = 256;     // time
constexpr int kH = 512;     // hidden
constexpr int kG = 2048;    // 4*H gate cols
constexpr int kM = kB * kT; // 16384 GEMM rows
constexpr int kCG = 32;     // column groups (16 hidden units each)
constexpr int kBG = 4;      // batch groups (16 batch elements each)
constexpr int kGrpCTA = kCG;
constexpr int kHRowHalf = 520;                    // hi 256 | lo 256 | pad 8
constexpr int kHalfBytes = 16 * kHRowHalf * 2;    // 16640

// ---------------- scratch ----------------------------------------------------
__device__ float  g_G[(size_t)kM * kG];            // input projections (128 MB)
__device__ float  g_h0[(size_t)kM * kH];           // layer-0 output sequence
__device__ __nv_bfloat16 g_As[(size_t)kM * 1024];  // A split hi|lo (32 MB)
__device__ __nv_bfloat16 g_WiTh[(size_t)kG * kH];  // Wi hi, transposed [N,K]
__device__ __nv_bfloat16 g_WiTl[(size_t)kG * kH];  // Wi lo
__device__ __nv_bfloat16 g_WhTh[(size_t)kG * kH];  // Wh hi, transposed [N,K]
__device__ __nv_bfloat16 g_WhTl[(size_t)kG * kH];  // Wh lo
// h exchange: [pingpong][k-half][batch][row(hi256|lo256|pad8)]
__device__ __align__(256) __nv_bfloat16 g_hbf2[2][2][kB][kHRowHalf];
__device__ int g_cnt[kBG * 32];                    // initial barrier
__device__ int g_flg[kBG * 32];
__device__ int g_hflag[kBG][32 * 32];              // per-producer step flags

// ---------------- helpers -----------------------------------------------------
__device__ __forceinline__ float sigf(float x) {
    x = fminf(fmaxf(x, -30.f), 30.f);
    return 1.f / (1.f + __expf(-x));
}
__device__ __forceinline__ float tanh_(float x) {
    x = fminf(fmaxf(x, -15.f), 15.f);
    float e = __expf(-2.f * x);
    return (1.f - e) / (1.f + e);
}

__device__ __forceinline__ void mma_bf16(float* c, const uint32_t* a,
                                         const uint32_t* b) {
    asm volatile(
        "mma.sync.aligned.m16n8k16.row.col.f32.bf16.bf16.f32 "
        "{%0,%1,%2,%3}, {%4,%5,%6,%7}, {%8,%9}, {%0,%1,%2,%3};"
        : "+f"(c[0]), "+f"(c[1]), "+f"(c[2]), "+f"(c[3])
        : "r"(a[0]), "r"(a[1]), "r"(a[2]), "r"(a[3]), "r"(b[0]), "r"(b[1]));
}
__device__ __forceinline__ void ldmx4(uint32_t* r, uint32_t addr) {
    asm volatile("ldmatrix.sync.aligned.m8n8.x4.shared.b16 {%0,%1,%2,%3}, [%4];"
                 : "=r"(r[0]), "=r"(r[1]), "=r"(r[2]), "=r"(r[3]) : "r"(addr));
}
__device__ __forceinline__ void ldmx2(uint32_t* r, uint32_t addr) {
    asm volatile("ldmatrix.sync.aligned.m8n8.x2.shared.b16 {%0,%1}, [%2];"
                 : "=r"(r[0]), "=r"(r[1]) : "r"(addr));
}
__device__ __forceinline__ uint32_t smem_u32(const void* p) {
    uint32_t a;
    asm("{ .reg .u64 t; cvta.to.shared.u64 t, %1; cvt.u32.u64 %0, t; }"
        : "=r"(a) : "l"(p));
    return a;
}
__device__ __forceinline__ void mbar_init(uint32_t a, uint32_t cnt) {
    asm volatile("mbarrier.init.shared.b64 [%0], %1;" :: "r"(a), "r"(cnt) : "memory");
}
__device__ __forceinline__ void mbar_wait(uint32_t a, uint32_t parity) {
    asm volatile(
        "{\n\t.reg .pred P;\n\t"
        "WL_%=:\n\t"
        "mbarrier.try_wait.parity.acquire.cta.shared::cta.b64 P, [%0], %1, 0x989680;\n\t"
        "@P bra.uni WD_%=;\n\t"
        "bra.uni WL_%=;\n\t"
        "WD_%=:\n\t}"
        :: "r"(a), "r"(parity) : "memory");
}
__device__ __forceinline__ void bulk_g2s(uint32_t dst, const void* src,
                                         uint32_t bytes, uint32_t mbar) {
    asm volatile(
        "cp.async.bulk.shared::cluster.global.mbarrier::complete_tx::bytes "
        "[%0], [%1], %2, [%3];"
        :: "r"(dst), "l"(src), "r"(bytes), "r"(mbar) : "memory");
}
__device__ __forceinline__ void mbar_expect(uint32_t mbar, uint32_t bytes) {
    asm volatile("mbarrier.arrive.expect_tx.shared.b64 _, [%0], %1;"
                 :: "r"(mbar), "r"(bytes) : "memory");
}

// ---------------- split/prep kernels -------------------------------------------
__global__ void __launch_bounds__(256)
split_x(const float* __restrict__ X)
{
    if (blockIdx.x == 0) {
        if (threadIdx.x < kBG) {
            g_cnt[threadIdx.x * 32] = 0;
            g_flg[threadIdx.x * 32] = 0;
        }
        for (int i = threadIdx.x; i < kBG * 32 * 32; i += 256)
            ((int*)g_hflag)[i] = 0;
    }
    size_t i = ((size_t)blockIdx.x * 256 + threadIdx.x) * 4;
    float4 v = *(const float4*)(X + i);
    size_t m = i >> 9;
    int k = (int)(i & 511);
    __nv_bfloat16 h0 = __float2bfloat16_rn(v.x);
    __nv_bfloat16 h1 = __float2bfloat16_rn(v.y);
    __nv_bfloat16 h2 = __float2bfloat16_rn(v.z);
    __nv_bfloat16 h3 = __float2bfloat16_rn(v.w);
    __nv_bfloat16 l0 = __float2bfloat16_rn(v.x - __bfloat162float(h0));
    __nv_bfloat16 l1 = __float2bfloat16_rn(v.y - __bfloat162float(h1));
    __nv_bfloat16 l2 = __float2bfloat16_rn(v.z - __bfloat162float(h2));
    __nv_bfloat16 l3 = __float2bfloat16_rn(v.w - __bfloat162float(h3));
    __nv_bfloat16* ph = g_As + m * 1024 + k;
    __nv_bfloat16* pl = ph + 512;
    *(__nv_bfloat162*)(ph)     = __nv_bfloat162(h0, h1);
    *(__nv_bfloat162*)(ph + 2) = __nv_bfloat162(h2, h3);
    *(__nv_bfloat162*)(pl)     = __nv_bfloat162(l0, l1);
    *(__nv_bfloat162*)(pl + 2) = __nv_bfloat162(l2, l3);
}

__global__ void __launch_bounds__(256)
split_pair(const float* __restrict__ W, __nv_bfloat16* __restrict__ dH,
           __nv_bfloat16* __restrict__ dL)
{
    __shared__ float tile[32][33];
    const int tx = threadIdx.x & 31;
    const int ty = threadIdx.x >> 5;
    const int n0 = blockIdx.x * 32;
    const int k0 = blockIdx.y * 32;
#pragma unroll
    for (int j = 0; j < 4; j++)
        tile[ty + j * 8][tx] = W[(size_t)(k0 + ty + j * 8) * kG + n0 + tx];
    __syncthreads();
#pragma unroll
    for (int j = 0; j < 4; j++) {
        const int n = n0 + ty + j * 8;
        const int k = k0 + tx;
        const float v = tile[tx][ty + j * 8];
        __nv_bfloat16 hi = __float2bfloat16_rn(v);
        __nv_bfloat16 lo = __float2bfloat16_rn(v - __bfloat162float(hi));
        dH[(size_t)n * kH + k] = hi;
        dL[(size_t)n * kH + k] = lo;
    }
}

// ---------------- HMMA input-projection GEMM (unchanged from R11) --------------
constexpr int kLds = 40;

__global__ void __launch_bounds__(256, 2)
gemm_mma(const float* __restrict__ bi, const float* __restrict__ bh,
         float* __restrict__ C)
{
    __shared__ __align__(16) __nv_bfloat16 Ah[128 * kLds];
    __shared__ __align__(16) __nv_bfloat16 Al[128 * kLds];
    __shared__ __align__(16) __nv_bfloat16 Bh[128 * kLds];
    __shared__ __align__(16) __nv_bfloat16 Bl[128 * kLds];

    const int tid  = threadIdx.x;
    const int wid  = tid >> 5;
    const int lane = tid & 31;
    const int g    = lane >> 2;
    const int tig  = lane & 3;
    const int n0 = blockIdx.x * 128;
    const int m0 = blockIdx.y * 128;
    const int wm = (wid >> 2) * 64;
    const int wn = (wid & 3) * 32;

    const int lr = tid >> 1;
    const int lh = tid & 1;

    const int lrow = ((lane >> 3) & 1) * 8 + (lane & 7);
    const int lcolB = (lane >> 4) * 16;
    const uint32_t aBaseH = smem_u32(Ah) + ((wm + lrow) * kLds) * 2 + lcolB;
    const uint32_t aBaseL = smem_u32(Al) + ((wm + lrow) * kLds) * 2 + lcolB;
    const int brow = wn + (lane & 7);
    const int bcolB = ((lane >> 3) & 1) * 16;
    const uint32_t bBaseH = smem_u32(Bh) + (brow * kLds) * 2 + bcolB;
    const uint32_t bBaseL = smem_u32(Bl) + (brow * kLds) * 2 + bcolB;

    float acc[4][4][4];
#pragma unroll
    for (int mf = 0; mf < 4; mf++)
#pragma unroll
        for (int nf = 0; nf < 4; nf++)
#pragma unroll
            for (int i = 0; i < 4; i++) acc[mf][nf][i] = 0.f;

    float2 bias2[4];
#pragma unroll
    for (int nf = 0; nf < 4; nf++) {
        const int n = n0 + wn + nf * 8 + tig * 2;
        bias2[nf].x = __ldg(bi + n) + __ldg(bh + n);
        bias2[nf].y = __ldg(bi + n + 1) + __ldg(bh + n + 1);
    }

    for (int kt = 0; kt < 16; kt++) {
        const int koff = kt * 32 + lh * 16;
        const __nv_bfloat16* pa = g_As   + (size_t)(m0 + lr) * 1024 + koff;
        const __nv_bfloat16* pl = pa + 512;
        const __nv_bfloat16* pb = g_WiTh + (size_t)(n0 + lr) * 512 + koff;
        const __nv_bfloat16* pc = g_WiTl + (size_t)(n0 + lr) * 512 + koff;
        uint4 vah0 = *(const uint4*)(pa);
        uint4 vah1 = *(const uint4*)(pa + 8);
        uint4 val0 = *(const uint4*)(pl);
        uint4 val1 = *(const uint4*)(pl + 8);
        uint4 vbh0 = *(const uint4*)(pb);
        uint4 vbh1 = *(const uint4*)(pb + 8);
        uint4 vbl0 = *(const uint4*)(pc);
        uint4 vbl1 = *(const uint4*)(pc + 8);
        __syncthreads();
        __nv_bfloat16* da = Ah + lr * kLds + lh * 16;
        __nv_bfloat16* dl = Al + lr * kLds + lh * 16;
        __nv_bfloat16* db = Bh + lr * kLds + lh * 16;
        __nv_bfloat16* dc = Bl + lr * kLds + lh * 16;
        *(uint4*)(da)     = vah0;
        *(uint4*)(da + 8) = vah1;
        *(uint4*)(dl)     = val0;
        *(uint4*)(dl + 8) = val1;
        *(uint4*)(db)     = vbh0;
        *(uint4*)(db + 8) = vbh1;
        *(uint4*)(dc)     = vbl0;
        *(uint4*)(dc + 8) = vbl1;
        __syncthreads();

#pragma unroll
        for (int ks = 0; ks < 2; ks++) {
            const int kOff = ks * 32;
            uint32_t bhf[4][2], blf[4][2];
#pragma unroll
            for (int nf = 0; nf < 4; nf++) {
                ldmx2(bhf[nf], bBaseH + nf * 8 * kLds * 2 + kOff);
                ldmx2(blf[nf], bBaseL + nf * 8 * kLds * 2 + kOff);
            }
#pragma unroll
            for (int mf = 0; mf < 4; mf++) {
                uint32_t ah[4], al[4];
                ldmx4(ah, aBaseH + mf * 16 * kLds * 2 + kOff);
                ldmx4(al, aBaseL + mf * 16 * kLds * 2 + kOff);
#pragma unroll
                for (int nf = 0; nf < 4; nf++) {
                    mma_bf16(acc[mf][nf], ah, bhf[nf]);
                    mma_bf16(acc[mf][nf], al, bhf[nf]);
                    mma_bf16(acc[mf][nf], ah, blf[nf]);
                }
            }
        }
    }

#pragma unroll
    for (int mf = 0; mf < 4; mf++) {
        const int m = m0 + wm + mf * 16 + g;
#pragma unroll
        for (int nf = 0; nf < 4; nf++) {
            const int n = n0 + wn + nf * 8 + tig * 2;
            float2 o0, o1;
            o0.x = acc[mf][nf][0] + bias2[nf].x;
            o0.y = acc[mf][nf][1] + bias2[nf].y;
            o1.x = acc[mf][nf][2] + bias2[nf].x;
            o1.y = acc[mf][nf][3] + bias2[nf].y;
            *(float2*)(C + (size_t)m * kG + n)       = o0;
            *(float2*)(C + (size_t)(m + 8) * kG + n) = o1;
        }
    }
}

// ---------------- initial group barrier (once) ----------------------------------
__device__ __forceinline__ void gbar_rel(int idx, int tid, int bg)
{
    __syncthreads();
    if (tid == 0) {
        int* cnt = &g_cnt[bg * 32];
        int* flg = &g_flg[bg * 32];
        int prev;
        asm volatile("atom.acq_rel.gpu.global.add.s32 %0, [%1], 1;"
                     : "=r"(prev) : "l"(cnt) : "memory");
        if (prev == idx * kGrpCTA - 1) {
            int dummy;
            asm volatile("atom.release.gpu.global.exch.b32 %0, [%1], %2;"
                         : "=r"(dummy) : "l"(flg), "r"(idx) : "memory");
        } else {
            int v;
            do {
                asm volatile("ld.acquire.gpu.global.s32 %0, [%1];"
                             : "=r"(v) : "l"(flg) : "memory");
            } while (v < idx);
        }
    }
    __syncthreads();
}

// ---------------- persistent HMMA LSTM recurrence ------------------------------
// R11 + split-K h exchange: two half-K buffers, two bulk copies, two mbarriers.
// MMA ks 0-15 starts as soon as producers 0-15 have published (copy B overlaps).
__global__ void __launch_bounds__(256, 1)
lstm_recur_mma(const float* __restrict__ G,
               const __nv_bfloat16* __restrict__ WTh,
               const __nv_bfloat16* __restrict__ WTl,
               float* __restrict__ seqout, float* __restrict__ hT,
               float* __restrict__ cT)
{
    __shared__ __align__(128) __nv_bfloat16 Ahs0[16][kHRowHalf];  // k 0..255
    __shared__ __align__(128) __nv_bfloat16 Ahs1[16][kHRowHalf];  // k 256..511
    __shared__ float gs[64 * 20];
    __shared__ float Gs[16][68];
    __shared__ float outF[16][16];
    __shared__ __nv_bfloat16 outB[16][32];
    __shared__ __align__(8) ull s_mbar[2];

    const int tid = threadIdx.x;
    const int cg  = blockIdx.x >> 2;
    const int bg  = blockIdx.x & 3;
    const int u0  = cg * 16;

    const int wid  = tid >> 5;
    const int lane = tid & 31;
    const int g8   = lane >> 2;
    const int tig  = lane & 3;

    const int pb = tid >> 4;
    const int pu = tid & 15;
    const int bglob = bg * 16 + pb;

    const uint32_t mbarA = smem_u32(&s_mbar[0]);
    const uint32_t mbarB = smem_u32(&s_mbar[1]);
    const uint32_t ahs0Addr = smem_u32(&Ahs0[0][0]);
    const uint32_t ahs1Addr = smem_u32(&Ahs1[0][0]);

    // ldmatrix lane mapping (16x16 A tile); lo half at +256 elems (+512B)
    const int lrow = ((lane >> 3) & 1) * 8 + (lane & 7);
    const int lcol = (lane >> 4) * 8;
    const uint32_t lm0 = smem_u32(&Ahs0[lrow][lcol]);
    const uint32_t lm1 = smem_u32(&Ahs1[lrow][lcol]);

    // Wh B-fragments in registers (col c, full K, hi+lo)
    const int c  = wid * 8 + g8;
    const int ng = (c >> 4) * kH + u0 + (c & 15);
    uint32_t bfh[32][2], bfl[32][2];
#pragma unroll
    for (int ks = 0; ks < 32; ks++) {
        const int kk = ks * 16 + tig * 2;
        bfh[ks][0] = *(const uint32_t*)(WTh + (size_t)ng * 512 + kk);
        bfh[ks][1] = *(const uint32_t*)(WTh + (size_t)ng * 512 + kk + 8);
        bfl[ks][0] = *(const uint32_t*)(WTl + (size_t)ng * 512 + kk);
        bfl[ks][1] = *(const uint32_t*)(WTl + (size_t)ng * 512 + kk + 8);
    }

    // zero our slice of the h ping buffers (parity 0): our half, cols of cg
    {
        const int half = cg >> 4;
        const int cb = (cg & 15) * 16;
        g_hbf2[0][half][bglob][cb + pu]       = __float2bfloat16_rn(0.f);
        g_hbf2[0][half][bglob][256 + cb + pu] = __float2bfloat16_rn(0.f);
    }
    float c_state = 0.f;
    if (tid == 0) { mbar_init(mbarA, 1); mbar_init(mbarB, 1); }

    gbar_rel(1, tid, bg);   // once: h(0) + flags visible everywhere

    for (int t = 0; t < kT; t++) {
        const int cur = t & 1;

        // stage this step's input projections (independent of h)
        {
            const int b = tid >> 4, q = tid & 15;
            const int gg = q >> 2, f = q & 3;
            const float* src = G + ((size_t)(bg * 16 + b) * kT + t) * kG
                             + gg * kH + u0 + f * 4;
            float4 v = __ldcs((const float4*)src);
            *(float4*)&Gs[b][gg * 16 + f * 4] = v;
        }

        // warp 0: poll all 32 producer flags; issue each half's copy the
        // moment its 16 producers are done
        if (wid == 0) {
            const int* fp = &g_hflag[bg][lane * 32];
            bool issuedA = false, issuedB = false;
            do {
                int v;
                asm volatile("ld.acquire.gpu.global.s32 %0, [%1];"
                             : "=r"(v) : "l"(fp) : "memory");
                const unsigned m = __ballot_sync(0xFFFFFFFFu, v >= t);
                if (!issuedA && (m & 0xFFFFu) == 0xFFFFu) {
                    if (lane == 0) {
                        mbar_expect(mbarA, kHalfBytes);
                        bulk_g2s(ahs0Addr, &g_hbf2[cur][0][bg * 16][0],
                                 kHalfBytes, mbarA);
                    }
                    issuedA = true;
                }
                if (!issuedB && (m >> 16) == 0xFFFFu) {
                    if (lane == 16) {
                        mbar_expect(mbarB, kHalfBytes);
                        bulk_g2s(ahs1Addr, &g_hbf2[cur][1][bg * 16][0],
                                 kHalfBytes, mbarB);
                    }
                    issuedB = true;
                }
            } while (!(issuedA && issuedB));
        }

        // gate GEMM: 16x8 per warp, K=512, 3-term split, 3 parallel chains.
        // First half runs while the second half's copy is in flight.
        float a0[4] = {0.f, 0.f, 0.f, 0.f};
        float a1[4] = {0.f, 0.f, 0.f, 0.f};
        float a2[4] = {0.f, 0.f, 0.f, 0.f};
        mbar_wait(mbarA, t & 1);
#pragma unroll
        for (int ks = 0; ks < 16; ks++) {
            uint32_t ah[4], al[4];
            ldmx4(ah, lm0 + ks * 32);
            ldmx4(al, lm0 + 512 + ks * 32);
            mma_bf16(a0, ah, bfh[ks]);
            mma_bf16(a1, al, bfh[ks]);
            mma_bf16(a2, ah, bfl[ks]);
        }
        mbar_wait(mbarB, t & 1);
#pragma unroll
        for (int ks = 0; ks < 16; ks++) {
            uint32_t ah[4], al[4];
            ldmx4(ah, lm1 + ks * 32);
            ldmx4(al, lm1 + 512 + ks * 32);
            mma_bf16(a0, ah, bfh[16 + ks]);
            mma_bf16(a1, al, bfh[16 + ks]);
            mma_bf16(a2, ah, bfl[16 + ks]);
        }
        const int cbase = (c - g8 + tig * 2) * 20;
        gs[cbase + g8]          = a0[0] + a1[0] + a2[0];
        gs[cbase + 20 + g8]     = a0[1] + a1[1] + a2[1];
        gs[cbase + g8 + 8]      = a0[2] + a1[2] + a2[2];
        gs[cbase + 20 + g8 + 8] = a0[3] + a1[3] + a2[3];
        __syncthreads();

        // pointwise LSTM cell
        {
            const float pre0 = Gs[pb][0 * 16 + pu] + gs[(0 * 16 + pu) * 20 + pb];
            const float pre1 = Gs[pb][1 * 16 + pu] + gs[(1 * 16 + pu) * 20 + pb];
            const float pre2 = Gs[pb][2 * 16 + pu] + gs[(2 * 16 + pu) * 20 + pb];
            const float pre3 = Gs[pb][3 * 16 + pu] + gs[(3 * 16 + pu) * 20 + pb];
            const float iv = sigf(pre0);
            const float fv = sigf(pre1);
            const float gv = tanh_(pre2);
            const float ov = sigf(pre3);
            c_state = fv * c_state + iv * gv;
            const float hval = ov * tanh_(c_state);

            outF[pb][pu] = hval;
            const __nv_bfloat16 hh = __float2bfloat16_rn(hval);
            const __nv_bfloat16 hl = __float2bfloat16_rn(hval - __bfloat162float(hh));
            outB[pb][pu]      = hh;
            outB[pb][16 + pu] = hl;
            if (t == kT - 1) {
                hT[(size_t)bglob * kH + u0 + pu] = hval;
                cT[(size_t)bglob * kH + u0 + pu] = c_state;
            }
        }
        __syncthreads();

        // warp 0: h-exchange writeback to our half-buffer + flag publish
        if (wid == 0) {
            const int half = cg >> 4;
            const int cb = (cg & 15) * 16;
#pragma unroll
            for (int j = 0; j < 2; j++) {
                const int e = lane * 2 + j;        // 0..63
                const int b = e >> 2, f = e & 3;
                const int col = (f < 2) ? (cb + f * 8)
                                        : (256 + cb + (f - 2) * 8);
                *(uint4*)(&g_hbf2[cur ^ 1][half][bg * 16 + b][col]) =
                    *(const uint4*)&outB[b][f * 8];
            }
            __syncwarp();
            if (lane == 0) {
                asm volatile("st.release.gpu.global.s32 [%0], %1;"
                             :: "l"(&g_hflag[bg][cg * 32]), "r"(t + 1) : "memory");
            }
        } else if (wid < 3) {
            const int e = tid - 32;                // 0..63
            const int b = e >> 2, f = e & 3;
            *(uint4*)(seqout + ((size_t)(bg * 16 + b) * kT + t) * kH + u0 + f * 4) =
                *(const uint4*)&outF[b][f * 4];
        }
        // SMEM reuse protected by the next step's mbar waits + post-gs sync
    }
}

// ---------------- launch --------------------------------------------------------
extern "C" void kernel_launch(void* const* d_in, const int* in_sizes, int n_in,
                              void* d_out, int out_size)
{
    const float* x  = (const float*)d_in[0];
    const float* Wi = (const float*)d_in[1];
    const float* Wh = (const float*)d_in[2];
    const float* bi = (const float*)d_in[3];
    const float* bh = (const float*)d_in[4];

    float* out  = (float*)d_out;
    float* outs = out;
    float* hT   = out + (size_t)kB * kT * kH;
    float* cT   = hT + (size_t)2 * kB * kH;

    float* Gp;  cudaGetSymbolAddress((void**)&Gp,  g_G);
    float* h0p; cudaGetSymbolAddress((void**)&h0p, g_h0);
    __nv_bfloat16 *wih, *wil, *whh, *whl;
    cudaGetSymbolAddress((void**)&wih, g_WiTh);
    cudaGetSymbolAddress((void**)&wil, g_WiTl);
    cudaGetSymbolAddress((void**)&whh, g_WhTh);
    cudaGetSymbolAddress((void**)&whl, g_WhTl);

    const dim3 gSplit(64, 16);
    const dim3 gGemm(kG / 128, kM / 128);

    // ---- layer 0
    split_pair<<<gSplit, 256>>>(Wi, wih, wil);
    split_pair<<<gSplit, 256>>>(Wh, whh, whl);
    split_x<<<kM * kH / 1024, 256>>>(x);
    gemm_mma<<<gGemm, 256>>>(bi, bh, Gp);
    lstm_recur_mma<<<kCG * kBG, 256>>>(Gp, whh, whl, h0p, hT, cT);

    // ---- layer 1
    split_pair<<<gSplit, 256>>>(Wi + (size_t)kH * kG, wih, wil);
    split_pair<<<gSplit, 256>>>(Wh + (size_t)kH * kG, whh, whl);
    split_x<<<kM * kH / 1024, 256>>>(h0p);
    gemm_mma<<<gGemm, 256>>>(bi + kG, bh + kG, Gp);
    lstm_recur_mma<<<kCG * kBG, 256>>>(Gp, whh, whl,
                                       outs, hT + (size_t)kB * kH,
                                       cT + (size_t)kB * kH);
}

// round 13
// speedup vs baseline: 3.5566x; 1.0629x over previous
#include <cuda_runtime.h>
#include <cuda_bf16.h>
#include <cstdint>

typedef unsigned long long ull;

constexpr int kB = 64;      // batch
constexpr int kT = 256;     // time
constexpr int kH = 512;     // hidden
constexpr int kG = 2048;    // 4*H gate cols
constexpr int kM = kB * kT; // 16384 GEMM rows
constexpr int kCG = 32;     // column groups (16 hidden units each)
constexpr int kBG = 4;      // batch groups (16 batch elements each)
constexpr int kGrpCTA = kCG;
constexpr int kHRowHalf = 520;                    // hi 256 | lo 256 | pad 8
constexpr int kHalfBytes = 16 * kHRowHalf * 2;    // 16640

// ---------------- scratch ----------------------------------------------------
__device__ float  g_G[(size_t)kM * kG];            // input projections (128 MB)
__device__ float  g_h0[(size_t)kM * kH];           // layer-0 output sequence
__device__ __nv_bfloat16 g_As[(size_t)kM * 1024];  // A split hi|lo (32 MB)
__device__ __nv_bfloat16 g_WiTh[(size_t)kG * kH];  // Wi hi, transposed [N,K]
__device__ __nv_bfloat16 g_WiTl[(size_t)kG * kH];  // Wi lo
__device__ __nv_bfloat16 g_WhTh[(size_t)kG * kH];  // Wh hi, transposed [N,K]
__device__ __nv_bfloat16 g_WhTl[(size_t)kG * kH];  // Wh lo
// h exchange: [pingpong][k-half][batch][row(hi256|lo256|pad8)]
__device__ __align__(256) __nv_bfloat16 g_hbf2[2][2][kB][kHRowHalf];
__device__ int g_cnt[kBG * 32];                    // initial barrier
__device__ int g_flg[kBG * 32];
__device__ int g_hflag[kBG][32 * 32];              // per-producer step flags

// ---------------- helpers -----------------------------------------------------
__device__ __forceinline__ float tanh_hw(float x) {
    float t;
    asm("tanh.approx.f32 %0, %1;" : "=f"(t) : "f"(x));
    return t;
}
__device__ __forceinline__ float sigf(float x) {
    return fmaf(tanh_hw(0.5f * x), 0.5f, 0.5f);
}
__device__ __forceinline__ float tanh_(float x) {
    return tanh_hw(x);
}

__device__ __forceinline__ void mma_bf16(float* c, const uint32_t* a,
                                         const uint32_t* b) {
    asm volatile(
        "mma.sync.aligned.m16n8k16.row.col.f32.bf16.bf16.f32 "
        "{%0,%1,%2,%3}, {%4,%5,%6,%7}, {%8,%9}, {%0,%1,%2,%3};"
        : "+f"(c[0]), "+f"(c[1]), "+f"(c[2]), "+f"(c[3])
        : "r"(a[0]), "r"(a[1]), "r"(a[2]), "r"(a[3]), "r"(b[0]), "r"(b[1]));
}
__device__ __forceinline__ void ldmx4(uint32_t* r, uint32_t addr) {
    asm volatile("ldmatrix.sync.aligned.m8n8.x4.shared.b16 {%0,%1,%2,%3}, [%4];"
                 : "=r"(r[0]), "=r"(r[1]), "=r"(r[2]), "=r"(r[3]) : "r"(addr));
}
__device__ __forceinline__ void ldmx2(uint32_t* r, uint32_t addr) {
    asm volatile("ldmatrix.sync.aligned.m8n8.x2.shared.b16 {%0,%1}, [%2];"
                 : "=r"(r[0]), "=r"(r[1]) : "r"(addr));
}
__device__ __forceinline__ uint32_t smem_u32(const void* p) {
    uint32_t a;
    asm("{ .reg .u64 t; cvta.to.shared.u64 t, %1; cvt.u32.u64 %0, t; }"
        : "=r"(a) : "l"(p));
    return a;
}
__device__ __forceinline__ void mbar_init(uint32_t a, uint32_t cnt) {
    asm volatile("mbarrier.init.shared.b64 [%0], %1;" :: "r"(a), "r"(cnt) : "memory");
}
__device__ __forceinline__ void mbar_wait(uint32_t a, uint32_t parity) {
    asm volatile(
        "{\n\t.reg .pred P;\n\t"
        "WL_%=:\n\t"
        "mbarrier.try_wait.parity.acquire.cta.shared::cta.b64 P, [%0], %1, 0x989680;\n\t"
        "@P bra.uni WD_%=;\n\t"
        "bra.uni WL_%=;\n\t"
        "WD_%=:\n\t}"
        :: "r"(a), "r"(parity) : "memory");
}
__device__ __forceinline__ void bulk_g2s(uint32_t dst, const void* src,
                                         uint32_t bytes, uint32_t mbar) {
    asm volatile(
        "cp.async.bulk.shared::cluster.global.mbarrier::complete_tx::bytes "
        "[%0], [%1], %2, [%3];"
        :: "r"(dst), "l"(src), "r"(bytes), "r"(mbar) : "memory");
}
__device__ __forceinline__ void mbar_expect(uint32_t mbar, uint32_t bytes) {
    asm volatile("mbarrier.arrive.expect_tx.shared.b64 _, [%0], %1;"
                 :: "r"(mbar), "r"(bytes) : "memory");
}

// ---------------- split/prep kernels -------------------------------------------
__global__ void __launch_bounds__(256)
split_x(const float* __restrict__ X)
{
    if (blockIdx.x == 0) {
        if (threadIdx.x < kBG) {
            g_cnt[threadIdx.x * 32] = 0;
            g_flg[threadIdx.x * 32] = 0;
        }
        for (int i = threadIdx.x; i < kBG * 32 * 32; i += 256)
            ((int*)g_hflag)[i] = 0;
    }
    size_t i = ((size_t)blockIdx.x * 256 + threadIdx.x) * 4;
    float4 v = *(const float4*)(X + i);
    size_t m = i >> 9;
    int k = (int)(i & 511);
    __nv_bfloat16 h0 = __float2bfloat16_rn(v.x);
    __nv_bfloat16 h1 = __float2bfloat16_rn(v.y);
    __nv_bfloat16 h2 = __float2bfloat16_rn(v.z);
    __nv_bfloat16 h3 = __float2bfloat16_rn(v.w);
    __nv_bfloat16 l0 = __float2bfloat16_rn(v.x - __bfloat162float(h0));
    __nv_bfloat16 l1 = __float2bfloat16_rn(v.y - __bfloat162float(h1));
    __nv_bfloat16 l2 = __float2bfloat16_rn(v.z - __bfloat162float(h2));
    __nv_bfloat16 l3 = __float2bfloat16_rn(v.w - __bfloat162float(h3));
    __nv_bfloat16* ph = g_As + m * 1024 + k;
    __nv_bfloat16* pl = ph + 512;
    *(__nv_bfloat162*)(ph)     = __nv_bfloat162(h0, h1);
    *(__nv_bfloat162*)(ph + 2) = __nv_bfloat162(h2, h3);
    *(__nv_bfloat162*)(pl)     = __nv_bfloat162(l0, l1);
    *(__nv_bfloat162*)(pl + 2) = __nv_bfloat162(l2, l3);
}

__global__ void __launch_bounds__(256)
split_pair(const float* __restrict__ W, __nv_bfloat16* __restrict__ dH,
           __nv_bfloat16* __restrict__ dL)
{
    __shared__ float tile[32][33];
    const int tx = threadIdx.x & 31;
    const int ty = threadIdx.x >> 5;
    const int n0 = blockIdx.x * 32;
    const int k0 = blockIdx.y * 32;
#pragma unroll
    for (int j = 0; j < 4; j++)
        tile[ty + j * 8][tx] = W[(size_t)(k0 + ty + j * 8) * kG + n0 + tx];
    __syncthreads();
#pragma unroll
    for (int j = 0; j < 4; j++) {
        const int n = n0 + ty + j * 8;
        const int k = k0 + tx;
        const float v = tile[tx][ty + j * 8];
        __nv_bfloat16 hi = __float2bfloat16_rn(v);
        __nv_bfloat16 lo = __float2bfloat16_rn(v - __bfloat162float(hi));
        dH[(size_t)n * kH + k] = hi;
        dL[(size_t)n * kH + k] = lo;
    }
}

// ---------------- HMMA input-projection GEMM (unchanged, passing) --------------
constexpr int kLds = 40;

__global__ void __launch_bounds__(256, 2)
gemm_mma(const float* __restrict__ bi, const float* __restrict__ bh,
         float* __restrict__ C)
{
    __shared__ __align__(16) __nv_bfloat16 Ah[128 * kLds];
    __shared__ __align__(16) __nv_bfloat16 Al[128 * kLds];
    __shared__ __align__(16) __nv_bfloat16 Bh[128 * kLds];
    __shared__ __align__(16) __nv_bfloat16 Bl[128 * kLds];

    const int tid  = threadIdx.x;
    const int wid  = tid >> 5;
    const int lane = tid & 31;
    const int g    = lane >> 2;
    const int tig  = lane & 3;
    const int n0 = blockIdx.x * 128;
    const int m0 = blockIdx.y * 128;
    const int wm = (wid >> 2) * 64;
    const int wn = (wid & 3) * 32;

    const int lr = tid >> 1;
    const int lh = tid & 1;

    const int lrow = ((lane >> 3) & 1) * 8 + (lane & 7);
    const int lcolB = (lane >> 4) * 16;
    const uint32_t aBaseH = smem_u32(Ah) + ((wm + lrow) * kLds) * 2 + lcolB;
    const uint32_t aBaseL = smem_u32(Al) + ((wm + lrow) * kLds) * 2 + lcolB;
    const int brow = wn + (lane & 7);
    const int bcolB = ((lane >> 3) & 1) * 16;
    const uint32_t bBaseH = smem_u32(Bh) + (brow * kLds) * 2 + bcolB;
    const uint32_t bBaseL = smem_u32(Bl) + (brow * kLds) * 2 + bcolB;

    float acc[4][4][4];
#pragma unroll
    for (int mf = 0; mf < 4; mf++)
#pragma unroll
        for (int nf = 0; nf < 4; nf++)
#pragma unroll
            for (int i = 0; i < 4; i++) acc[mf][nf][i] = 0.f;

    float2 bias2[4];
#pragma unroll
    for (int nf = 0; nf < 4; nf++) {
        const int n = n0 + wn + nf * 8 + tig * 2;
        bias2[nf].x = __ldg(bi + n) + __ldg(bh + n);
        bias2[nf].y = __ldg(bi + n + 1) + __ldg(bh + n + 1);
    }

    for (int kt = 0; kt < 16; kt++) {
        const int koff = kt * 32 + lh * 16;
        const __nv_bfloat16* pa = g_As   + (size_t)(m0 + lr) * 1024 + koff;
        const __nv_bfloat16* pl = pa + 512;
        const __nv_bfloat16* pb = g_WiTh + (size_t)(n0 + lr) * 512 + koff;
        const __nv_bfloat16* pc = g_WiTl + (size_t)(n0 + lr) * 512 + koff;
        uint4 vah0 = *(const uint4*)(pa);
        uint4 vah1 = *(const uint4*)(pa + 8);
        uint4 val0 = *(const uint4*)(pl);
        uint4 val1 = *(const uint4*)(pl + 8);
        uint4 vbh0 = *(const uint4*)(pb);
        uint4 vbh1 = *(const uint4*)(pb + 8);
        uint4 vbl0 = *(const uint4*)(pc);
        uint4 vbl1 = *(const uint4*)(pc + 8);
        __syncthreads();
        __nv_bfloat16* da = Ah + lr * kLds + lh * 16;
        __nv_bfloat16* dl = Al + lr * kLds + lh * 16;
        __nv_bfloat16* db = Bh + lr * kLds + lh * 16;
        __nv_bfloat16* dc = Bl + lr * kLds + lh * 16;
        *(uint4*)(da)     = vah0;
        *(uint4*)(da + 8) = vah1;
        *(uint4*)(dl)     = val0;
        *(uint4*)(dl + 8) = val1;
        *(uint4*)(db)     = vbh0;
        *(uint4*)(db + 8) = vbh1;
        *(uint4*)(dc)     = vbl0;
        *(uint4*)(dc + 8) = vbl1;
        __syncthreads();

#pragma unroll
        for (int ks = 0; ks < 2; ks++) {
            const int kOff = ks * 32;
            uint32_t bhf[4][2], blf[4][2];
#pragma unroll
            for (int nf = 0; nf < 4; nf++) {
                ldmx2(bhf[nf], bBaseH + nf * 8 * kLds * 2 + kOff);
                ldmx2(blf[nf], bBaseL + nf * 8 * kLds * 2 + kOff);
            }
#pragma unroll
            for (int mf = 0; mf < 4; mf++) {
                uint32_t ah[4], al[4];
                ldmx4(ah, aBaseH + mf * 16 * kLds * 2 + kOff);
                ldmx4(al, aBaseL + mf * 16 * kLds * 2 + kOff);
#pragma unroll
                for (int nf = 0; nf < 4; nf++) {
                    mma_bf16(acc[mf][nf], ah, bhf[nf]);
                    mma_bf16(acc[mf][nf], al, bhf[nf]);
                    mma_bf16(acc[mf][nf], ah, blf[nf]);
                }
            }
        }
    }

#pragma unroll
    for (int mf = 0; mf < 4; mf++) {
        const int m = m0 + wm + mf * 16 + g;
#pragma unroll
        for (int nf = 0; nf < 4; nf++) {
            const int n = n0 + wn + nf * 8 + tig * 2;
            float2 o0, o1;
            o0.x = acc[mf][nf][0] + bias2[nf].x;
            o0.y = acc[mf][nf][1] + bias2[nf].y;
            o1.x = acc[mf][nf][2] + bias2[nf].x;
            o1.y = acc[mf][nf][3] + bias2[nf].y;
            *(float2*)(C + (size_t)m * kG + n)       = o0;
            *(float2*)(C + (size_t)(m + 8) * kG + n) = o1;
        }
    }
}

// ---------------- initial group barrier (once) ----------------------------------
__device__ __forceinline__ void gbar_rel(int idx, int tid, int bg)
{
    __syncthreads();
    if (tid == 0) {
        int* cnt = &g_cnt[bg * 32];
        int* flg = &g_flg[bg * 32];
        int prev;
        asm volatile("atom.acq_rel.gpu.global.add.s32 %0, [%1], 1;"
                     : "=r"(prev) : "l"(cnt) : "memory");
        if (prev == idx * kGrpCTA - 1) {
            int dummy;
            asm volatile("atom.release.gpu.global.exch.b32 %0, [%1], %2;"
                         : "=r"(dummy) : "l"(flg), "r"(idx) : "memory");
        } else {
            int v;
            do {
                asm volatile("ld.acquire.gpu.global.s32 %0, [%1];"
                             : "=r"(v) : "l"(flg) : "memory");
            } while (v < idx);
        }
    }
    __syncthreads();
}

// ---------------- persistent HMMA LSTM recurrence ------------------------------
// R12 + MUFU.TANH pointwise + per-half accumulator chains (16-link chains).
__global__ void __launch_bounds__(256, 1)
lstm_recur_mma(const float* __restrict__ G,
               const __nv_bfloat16* __restrict__ WTh,
               const __nv_bfloat16* __restrict__ WTl,
               float* __restrict__ seqout, float* __restrict__ hT,
               float* __restrict__ cT)
{
    __shared__ __align__(128) __nv_bfloat16 Ahs0[16][kHRowHalf];  // k 0..255
    __shared__ __align__(128) __nv_bfloat16 Ahs1[16][kHRowHalf];  // k 256..511
    __shared__ float gs[64 * 20];
    __shared__ float Gs[16][68];
    __shared__ float outF[16][16];
    __shared__ __nv_bfloat16 outB[16][32];
    __shared__ __align__(8) ull s_mbar[2];

    const int tid = threadIdx.x;
    const int cg  = blockIdx.x >> 2;
    const int bg  = blockIdx.x & 3;
    const int u0  = cg * 16;

    const int wid  = tid >> 5;
    const int lane = tid & 31;
    const int g8   = lane >> 2;
    const int tig  = lane & 3;

    const int pb = tid >> 4;
    const int pu = tid & 15;
    const int bglob = bg * 16 + pb;

    const uint32_t mbarA = smem_u32(&s_mbar[0]);
    const uint32_t mbarB = smem_u32(&s_mbar[1]);
    const uint32_t ahs0Addr = smem_u32(&Ahs0[0][0]);
    const uint32_t ahs1Addr = smem_u32(&Ahs1[0][0]);

    const int lrow = ((lane >> 3) & 1) * 8 + (lane & 7);
    const int lcol = (lane >> 4) * 8;
    const uint32_t lm0 = smem_u32(&Ahs0[lrow][lcol]);
    const uint32_t lm1 = smem_u32(&Ahs1[lrow][lcol]);

    // Wh B-fragments in registers (col c, full K, hi+lo)
    const int c  = wid * 8 + g8;
    const int ng = (c >> 4) * kH + u0 + (c & 15);
    uint32_t bfh[32][2], bfl[32][2];
#pragma unroll
    for (int ks = 0; ks < 32; ks++) {
        const int kk = ks * 16 + tig * 2;
        bfh[ks][0] = *(const uint32_t*)(WTh + (size_t)ng * 512 + kk);
        bfh[ks][1] = *(const uint32_t*)(WTh + (size_t)ng * 512 + kk + 8);
        bfl[ks][0] = *(const uint32_t*)(WTl + (size_t)ng * 512 + kk);
        bfl[ks][1] = *(const uint32_t*)(WTl + (size_t)ng * 512 + kk + 8);
    }

    // zero our slice of the h ping buffers (parity 0)
    {
        const int half = cg >> 4;
        const int cb = (cg & 15) * 16;
        g_hbf2[0][half][bglob][cb + pu]       = __float2bfloat16_rn(0.f);
        g_hbf2[0][half][bglob][256 + cb + pu] = __float2bfloat16_rn(0.f);
    }
    float c_state = 0.f;
    if (tid == 0) { mbar_init(mbarA, 1); mbar_init(mbarB, 1); }

    gbar_rel(1, tid, bg);   // once: h(0) + flags visible everywhere

    for (int t = 0; t < kT; t++) {
        const int cur = t & 1;

        // stage this step's input projections (independent of h)
        {
            const int b = tid >> 4, q = tid & 15;
            const int gg = q >> 2, f = q & 3;
            const float* src = G + ((size_t)(bg * 16 + b) * kT + t) * kG
                             + gg * kH + u0 + f * 4;
            float4 v = __ldcs((const float4*)src);
            *(float4*)&Gs[b][gg * 16 + f * 4] = v;
        }

        // warp 0: poll all 32 producer flags; issue each half's copy the
        // moment its 16 producers are done
        if (wid == 0) {
            const int* fp = &g_hflag[bg][lane * 32];
            bool issuedA = false, issuedB = false;
            do {
                int v;
                asm volatile("ld.acquire.gpu.global.s32 %0, [%1];"
                             : "=r"(v) : "l"(fp) : "memory");
                const unsigned m = __ballot_sync(0xFFFFFFFFu, v >= t);
                if (!issuedA && (m & 0xFFFFu) == 0xFFFFu) {
                    if (lane == 0) {
                        mbar_expect(mbarA, kHalfBytes);
                        bulk_g2s(ahs0Addr, &g_hbf2[cur][0][bg * 16][0],
                                 kHalfBytes, mbarA);
                    }
                    issuedA = true;
                }
                if (!issuedB && (m >> 16) == 0xFFFFu) {
                    if (lane == 16) {
                        mbar_expect(mbarB, kHalfBytes);
                        bulk_g2s(ahs1Addr, &g_hbf2[cur][1][bg * 16][0],
                                 kHalfBytes, mbarB);
                    }
                    issuedB = true;
                }
            } while (!(issuedA && issuedB));
        }

        // gate GEMM: 16x8 per warp, K=512, 3-term split.
        // Separate accumulator sets per K-half -> 16-link chains.
        float a0[4] = {0.f, 0.f, 0.f, 0.f};
        float a1[4] = {0.f, 0.f, 0.f, 0.f};
        float a2[4] = {0.f, 0.f, 0.f, 0.f};
        float b0[4] = {0.f, 0.f, 0.f, 0.f};
        float b1[4] = {0.f, 0.f, 0.f, 0.f};
        float b2[4] = {0.f, 0.f, 0.f, 0.f};
        mbar_wait(mbarA, t & 1);
#pragma unroll
        for (int ks = 0; ks < 16; ks++) {
            uint32_t ah[4], al[4];
            ldmx4(ah, lm0 + ks * 32);
            ldmx4(al, lm0 + 512 + ks * 32);
            mma_bf16(a0, ah, bfh[ks]);
            mma_bf16(a1, al, bfh[ks]);
            mma_bf16(a2, ah, bfl[ks]);
        }
        mbar_wait(mbarB, t & 1);
#pragma unroll
        for (int ks = 0; ks < 16; ks++) {
            uint32_t ah[4], al[4];
            ldmx4(ah, lm1 + ks * 32);
            ldmx4(al, lm1 + 512 + ks * 32);
            mma_bf16(b0, ah, bfh[16 + ks]);
            mma_bf16(b1, al, bfh[16 + ks]);
            mma_bf16(b2, ah, bfl[16 + ks]);
        }
        const int cbase = (c - g8 + tig * 2) * 20;
        gs[cbase + g8]          = (a0[0] + a1[0]) + (a2[0] + b0[0]) + (b1[0] + b2[0]);
        gs[cbase + 20 + g8]     = (a0[1] + a1[1]) + (a2[1] + b0[1]) + (b1[1] + b2[1]);
        gs[cbase + g8 + 8]      = (a0[2] + a1[2]) + (a2[2] + b0[2]) + (b1[2] + b2[2]);
        gs[cbase + 20 + g8 + 8] = (a0[3] + a1[3]) + (a2[3] + b0[3]) + (b1[3] + b2[3]);
        __syncthreads();

        // pointwise LSTM cell (MUFU.TANH)
        {
            const float pre0 = Gs[pb][0 * 16 + pu] + gs[(0 * 16 + pu) * 20 + pb];
            const float pre1 = Gs[pb][1 * 16 + pu] + gs[(1 * 16 + pu) * 20 + pb];
            const float pre2 = Gs[pb][2 * 16 + pu] + gs[(2 * 16 + pu) * 20 + pb];
            const float pre3 = Gs[pb][3 * 16 + pu] + gs[(3 * 16 + pu) * 20 + pb];
            const float iv = sigf(pre0);
            const float fv = sigf(pre1);
            const float gv = tanh_(pre2);
            const float ov = sigf(pre3);
            c_state = fv * c_state + iv * gv;
            const float hval = ov * tanh_(c_state);

            outF[pb][pu] = hval;
            const __nv_bfloat16 hh = __float2bfloat16_rn(hval);
            const __nv_bfloat16 hl = __float2bfloat16_rn(hval - __bfloat162float(hh));
            outB[pb][pu]      = hh;
            outB[pb][16 + pu] = hl;
            if (t == kT - 1) {
                hT[(size_t)bglob * kH + u0 + pu] = hval;
                cT[(size_t)bglob * kH + u0 + pu] = c_state;
            }
        }
        __syncthreads();

        // warp 0: h-exchange writeback to our half-buffer + flag publish
        if (wid == 0) {
            const int half = cg >> 4;
            const int cb = (cg & 15) * 16;
#pragma unroll
            for (int j = 0; j < 2; j++) {
                const int e = lane * 2 + j;        // 0..63
                const int b = e >> 2, f = e & 3;
                const int col = (f < 2) ? (cb + f * 8)
                                        : (256 + cb + (f - 2) * 8);
                *(uint4*)(&g_hbf2[cur ^ 1][half][bg * 16 + b][col]) =
                    *(const uint4*)&outB[b][f * 8];
            }
            __syncwarp();
            if (lane == 0) {
                asm volatile("st.release.gpu.global.s32 [%0], %1;"
                             :: "l"(&g_hflag[bg][cg * 32]), "r"(t + 1) : "memory");
            }
        } else if (wid < 3) {
            const int e = tid - 32;                // 0..63
            const int b = e >> 2, f = e & 3;
            *(uint4*)(seqout + ((size_t)(bg * 16 + b) * kT + t) * kH + u0 + f * 4) =
                *(const uint4*)&outF[b][f * 4];
        }
        // SMEM reuse protected by the next step's mbar waits + post-gs sync
    }
}

// ---------------- launch --------------------------------------------------------
extern "C" void kernel_launch(void* const* d_in, const int* in_sizes, int n_in,
                              void* d_out, int out_size)
{
    const float* x  = (const float*)d_in[0];
    const float* Wi = (const float*)d_in[1];
    const float* Wh = (const float*)d_in[2];
    const float* bi = (const float*)d_in[3];
    const float* bh = (const float*)d_in[4];

    float* out  = (float*)d_out;
    float* outs = out;
    float* hT   = out + (size_t)kB * kT * kH;
    float* cT   = hT + (size_t)2 * kB * kH;

    float* Gp;  cudaGetSymbolAddress((void**)&Gp,  g_G);
    float* h0p; cudaGetSymbolAddress((void**)&h0p, g_h0);
    __nv_bfloat16 *wih, *wil, *whh, *whl;
    cudaGetSymbolAddress((void**)&wih, g_WiTh);
    cudaGetSymbolAddress((void**)&wil, g_WiTl);
    cudaGetSymbolAddress((void**)&whh, g_WhTh);
    cudaGetSymbolAddress((void**)&whl, g_WhTl);

    const dim3 gSplit(64, 16);
    const dim3 gGemm(kG / 128, kM / 128);

    // ---- layer 0
    split_pair<<<gSplit, 256>>>(Wi, wih, wil);
    split_pair<<<gSplit, 256>>>(Wh, whh, whl);
    split_x<<<kM * kH / 1024, 256>>>(x);
    gemm_mma<<<gGemm, 256>>>(bi, bh, Gp);
    lstm_recur_mma<<<kCG * kBG, 256>>>(Gp, whh, whl, h0p, hT, cT);

    // ---- layer 1
    split_pair<<<gSplit, 256>>>(Wi + (size_t)kH * kG, wih, wil);
    split_pair<<<gSplit, 256>>>(Wh + (size_t)kH * kG, whh, whl);
    split_x<<<kM * kH / 1024, 256>>>(h0p);
    gemm_mma<<<gGemm, 256>>>(bi + kG, bh + kG, Gp);
    lstm_recur_mma<<<kCG * kBG, 256>>>(Gp, whh, whl,
                                       outs, hT + (size_t)kB * kH,
                                       cT + (size_t)kB * kH);
}

// round 14
// speedup vs baseline: 3.5718x; 1.0043x over previous
#include <cuda_runtime.h>
#include <cuda_bf16.h>
#include <cstdint>

typedef unsigned long long ull;

constexpr int kB = 64;      // batch
constexpr int kT = 256;     // time
constexpr int kH = 512;     // hidden
constexpr int kG = 2048;    // 4*H gate cols
constexpr int kM = kB * kT; // 16384 GEMM rows
constexpr int kCG = 32;     // column groups (16 hidden units each)
constexpr int kBG = 4;      // batch groups (16 batch elements each)
constexpr int kGrpCTA = kCG;
constexpr int kHRowHalf = 520;                    // hi 256 | lo 256 | pad 8
constexpr int kHalfBytes = 16 * kHRowHalf * 2;    // 16640

// ---------------- scratch ----------------------------------------------------
__device__ float  g_G[(size_t)kM * kG];            // input projections (128 MB)
__device__ __nv_bfloat16 g_As[(size_t)kM * 1024];  // A split hi|lo (32 MB)
__device__ __nv_bfloat16 g_WiTh[(size_t)kG * kH];  // Wi hi, transposed [N,K]
__device__ __nv_bfloat16 g_WiTl[(size_t)kG * kH];  // Wi lo
__device__ __nv_bfloat16 g_WhTh[(size_t)kG * kH];  // Wh hi, transposed [N,K]
__device__ __nv_bfloat16 g_WhTl[(size_t)kG * kH];  // Wh lo
// h exchange: [pingpong][k-half][batch][row(hi256|lo256|pad8)]
__device__ __align__(256) __nv_bfloat16 g_hbf2[2][2][kB][kHRowHalf];
__device__ int g_cnt[kBG * 32];                    // initial barrier
__device__ int g_flg[kBG * 32];
__device__ int g_hflag[kBG][32 * 32];              // per-producer step flags

// ---------------- helpers -----------------------------------------------------
__device__ __forceinline__ float tanh_hw(float x) {
    float t;
    asm("tanh.approx.f32 %0, %1;" : "=f"(t) : "f"(x));
    return t;
}
__device__ __forceinline__ float sigf(float x) {
    return fmaf(tanh_hw(0.5f * x), 0.5f, 0.5f);
}

__device__ __forceinline__ void mma_bf16(float* c, const uint32_t* a,
                                         const uint32_t* b) {
    asm volatile(
        "mma.sync.aligned.m16n8k16.row.col.f32.bf16.bf16.f32 "
        "{%0,%1,%2,%3}, {%4,%5,%6,%7}, {%8,%9}, {%0,%1,%2,%3};"
        : "+f"(c[0]), "+f"(c[1]), "+f"(c[2]), "+f"(c[3])
        : "r"(a[0]), "r"(a[1]), "r"(a[2]), "r"(a[3]), "r"(b[0]), "r"(b[1]));
}
__device__ __forceinline__ void ldmx4(uint32_t* r, uint32_t addr) {
    asm volatile("ldmatrix.sync.aligned.m8n8.x4.shared.b16 {%0,%1,%2,%3}, [%4];"
                 : "=r"(r[0]), "=r"(r[1]), "=r"(r[2]), "=r"(r[3]) : "r"(addr));
}
__device__ __forceinline__ void ldmx2(uint32_t* r, uint32_t addr) {
    asm volatile("ldmatrix.sync.aligned.m8n8.x2.shared.b16 {%0,%1}, [%2];"
                 : "=r"(r[0]), "=r"(r[1]) : "r"(addr));
}
__device__ __forceinline__ uint32_t smem_u32(const void* p) {
    uint32_t a;
    asm("{ .reg .u64 t; cvta.to.shared.u64 t, %1; cvt.u32.u64 %0, t; }"
        : "=r"(a) : "l"(p));
    return a;
}
__device__ __forceinline__ void mbar_init(uint32_t a, uint32_t cnt) {
    asm volatile("mbarrier.init.shared.b64 [%0], %1;" :: "r"(a), "r"(cnt) : "memory");
}
__device__ __forceinline__ void mbar_wait(uint32_t a, uint32_t parity) {
    asm volatile(
        "{\n\t.reg .pred P;\n\t"
        "WL_%=:\n\t"
        "mbarrier.try_wait.parity.acquire.cta.shared::cta.b64 P, [%0], %1, 0x989680;\n\t"
        "@P bra.uni WD_%=;\n\t"
        "bra.uni WL_%=;\n\t"
        "WD_%=:\n\t}"
        :: "r"(a), "r"(parity) : "memory");
}
__device__ __forceinline__ void bulk_g2s(uint32_t dst, const void* src,
                                         uint32_t bytes, uint32_t mbar) {
    asm volatile(
        "cp.async.bulk.shared::cluster.global.mbarrier::complete_tx::bytes "
        "[%0], [%1], %2, [%3];"
        :: "r"(dst), "l"(src), "r"(bytes), "r"(mbar) : "memory");
}
__device__ __forceinline__ void mbar_expect(uint32_t mbar, uint32_t bytes) {
    asm volatile("mbarrier.arrive.expect_tx.shared.b64 _, [%0], %1;"
                 :: "r"(mbar), "r"(bytes) : "memory");
}
__device__ __forceinline__ void cpasync16(uint32_t dst, const void* src) {
    asm volatile("cp.async.cg.shared.global [%0], [%1], 16;"
                 :: "r"(dst), "l"(src) : "memory");
}

// ---------------- split/prep kernels -------------------------------------------
__global__ void __launch_bounds__(256)
split_x(const float* __restrict__ X)
{
    if (blockIdx.x == 0) {
        if (threadIdx.x < kBG) {
            g_cnt[threadIdx.x * 32] = 0;
            g_flg[threadIdx.x * 32] = 0;
        }
        for (int i = threadIdx.x; i < kBG * 32 * 32; i += 256)
            ((int*)g_hflag)[i] = 0;
    }
    size_t i = ((size_t)blockIdx.x * 256 + threadIdx.x) * 4;
    float4 v = *(const float4*)(X + i);
    size_t m = i >> 9;
    int k = (int)(i & 511);
    __nv_bfloat16 h0 = __float2bfloat16_rn(v.x);
    __nv_bfloat16 h1 = __float2bfloat16_rn(v.y);
    __nv_bfloat16 h2 = __float2bfloat16_rn(v.z);
    __nv_bfloat16 h3 = __float2bfloat16_rn(v.w);
    __nv_bfloat16 l0 = __float2bfloat16_rn(v.x - __bfloat162float(h0));
    __nv_bfloat16 l1 = __float2bfloat16_rn(v.y - __bfloat162float(h1));
    __nv_bfloat16 l2 = __float2bfloat16_rn(v.z - __bfloat162float(h2));
    __nv_bfloat16 l3 = __float2bfloat16_rn(v.w - __bfloat162float(h3));
    __nv_bfloat16* ph = g_As + m * 1024 + k;
    __nv_bfloat16* pl = ph + 512;
    *(__nv_bfloat162*)(ph)     = __nv_bfloat162(h0, h1);
    *(__nv_bfloat162*)(ph + 2) = __nv_bfloat162(h2, h3);
    *(__nv_bfloat162*)(pl)     = __nv_bfloat162(l0, l1);
    *(__nv_bfloat162*)(pl + 2) = __nv_bfloat162(l2, l3);
}

__global__ void __launch_bounds__(256)
split_pair(const float* __restrict__ W, __nv_bfloat16* __restrict__ dH,
           __nv_bfloat16* __restrict__ dL)
{
    __shared__ float tile[32][33];
    const int tx = threadIdx.x & 31;
    const int ty = threadIdx.x >> 5;
    const int n0 = blockIdx.x * 32;
    const int k0 = blockIdx.y * 32;
#pragma unroll
    for (int j = 0; j < 4; j++)
        tile[ty + j * 8][tx] = W[(size_t)(k0 + ty + j * 8) * kG + n0 + tx];
    __syncthreads();
#pragma unroll
    for (int j = 0; j < 4; j++) {
        const int n = n0 + ty + j * 8;
        const int k = k0 + tx;
        const float v = tile[tx][ty + j * 8];
        __nv_bfloat16 hi = __float2bfloat16_rn(v);
        __nv_bfloat16 lo = __float2bfloat16_rn(v - __bfloat162float(hi));
        dH[(size_t)n * kH + k] = hi;
        dL[(size_t)n * kH + k] = lo;
    }
}

// ---------------- HMMA input-projection GEMM: 2-stage cp.async pipeline --------
constexpr int kLds = 40;                         // padded row (bf16)
constexpr int kTileBytes = 128 * kLds * 2;       // 10240 per tile
constexpr int kStageBytes = 4 * kTileBytes;      // Ah|Al|Bh|Bl
constexpr int kGemmSmem = 2 * kStageBytes;       // 81920

extern __shared__ __align__(16) char g_dsm[];

__global__ void __launch_bounds__(256, 2)
gemm_mma(const float* __restrict__ bi, const float* __restrict__ bh,
         float* __restrict__ C)
{
    const uint32_t smemBase = smem_u32(g_dsm);

    const int tid  = threadIdx.x;
    const int wid  = tid >> 5;
    const int lane = tid & 31;
    const int g    = lane >> 2;
    const int tig  = lane & 3;
    const int n0 = blockIdx.x * 128;
    const int m0 = blockIdx.y * 128;
    const int wm = (wid >> 2) * 64;
    const int wn = (wid & 3) * 32;

    const int lr = tid >> 1;            // staging row
    const int lh = tid & 1;             // 16-elem half

    // fragment lane addressing (within a stage; tiles at +0,+1,+2,+3 x kTileBytes)
    const int lrow = ((lane >> 3) & 1) * 8 + (lane & 7);
    const int lcolB = (lane >> 4) * 16;
    const uint32_t aOffH = ((wm + lrow) * kLds) * 2 + lcolB;
    const int brow = wn + (lane & 7);
    const int bcolB = ((lane >> 3) & 1) * 16;
    const uint32_t bOffH = (brow * kLds) * 2 + bcolB;

    // staging destination offset within a tile
    const uint32_t stDst = (lr * kLds + lh * 16) * 2;

    // global sources (per k-tile kt: advance 32 elements)
    const __nv_bfloat16* srcAh = g_As   + (size_t)(m0 + lr) * 1024 + lh * 16;
    const __nv_bfloat16* srcAl = srcAh + 512;
    const __nv_bfloat16* srcBh = g_WiTh + (size_t)(n0 + lr) * 512 + lh * 16;
    const __nv_bfloat16* srcBl = g_WiTl + (size_t)(n0 + lr) * 512 + lh * 16;

    auto issue = [&](int kt, int s) {
        const uint32_t sb = smemBase + s * kStageBytes + stDst;
        const int ko = kt * 32;
        cpasync16(sb,                      srcAh + ko);
        cpasync16(sb + 16,                 srcAh + ko + 8);
        cpasync16(sb + kTileBytes,         srcAl + ko);
        cpasync16(sb + kTileBytes + 16,    srcAl + ko + 8);
        cpasync16(sb + 2 * kTileBytes,     srcBh + ko);
        cpasync16(sb + 2 * kTileBytes + 16, srcBh + ko + 8);
        cpasync16(sb + 3 * kTileBytes,     srcBl + ko);
        cpasync16(sb + 3 * kTileBytes + 16, srcBl + ko + 8);
        asm volatile("cp.async.commit_group;" ::: "memory");
    };

    float acc[4][4][4];
#pragma unroll
    for (int mf = 0; mf < 4; mf++)
#pragma unroll
        for (int nf = 0; nf < 4; nf++)
#pragma unroll
            for (int i = 0; i < 4; i++) acc[mf][nf][i] = 0.f;

    float2 bias2[4];
#pragma unroll
    for (int nf = 0; nf < 4; nf++) {
        const int n = n0 + wn + nf * 8 + tig * 2;
        bias2[nf].x = __ldg(bi + n) + __ldg(bh + n);
        bias2[nf].y = __ldg(bi + n + 1) + __ldg(bh + n + 1);
    }

    issue(0, 0);

    for (int kt = 0; kt < 16; kt++) {
        const int s = kt & 1;
        if (kt < 15) {
            issue(kt + 1, s ^ 1);
            asm volatile("cp.async.wait_group 1;" ::: "memory");
        } else {
            asm volatile("cp.async.wait_group 0;" ::: "memory");
        }
        __syncthreads();

        const uint32_t stage = smemBase + s * kStageBytes;
        const uint32_t aH = stage + aOffH;
        const uint32_t aL = aH + kTileBytes;
        const uint32_t bH = stage + 2 * kTileBytes + bOffH;
        const uint32_t bL = bH + kTileBytes;

#pragma unroll
        for (int ks = 0; ks < 2; ks++) {
            const int kOff = ks * 32;
            uint32_t bhf[4][2], blf[4][2];
#pragma unroll
            for (int nf = 0; nf < 4; nf++) {
                ldmx2(bhf[nf], bH + nf * 8 * kLds * 2 + kOff);
                ldmx2(blf[nf], bL + nf * 8 * kLds * 2 + kOff);
            }
#pragma unroll
            for (int mf = 0; mf < 4; mf++) {
                uint32_t ah[4], al[4];
                ldmx4(ah, aH + mf * 16 * kLds * 2 + kOff);
                ldmx4(al, aL + mf * 16 * kLds * 2 + kOff);
#pragma unroll
                for (int nf = 0; nf < 4; nf++) {
                    mma_bf16(acc[mf][nf], ah, bhf[nf]);
                    mma_bf16(acc[mf][nf], al, bhf[nf]);
                    mma_bf16(acc[mf][nf], ah, blf[nf]);
                }
            }
        }
        __syncthreads();
    }

#pragma unroll
    for (int mf = 0; mf < 4; mf++) {
        const int m = m0 + wm + mf * 16 + g;
#pragma unroll
        for (int nf = 0; nf < 4; nf++) {
            const int n = n0 + wn + nf * 8 + tig * 2;
            float2 o0, o1;
            o0.x = acc[mf][nf][0] + bias2[nf].x;
            o0.y = acc[mf][nf][1] + bias2[nf].y;
            o1.x = acc[mf][nf][2] + bias2[nf].x;
            o1.y = acc[mf][nf][3] + bias2[nf].y;
            *(float2*)(C + (size_t)m * kG + n)       = o0;
            *(float2*)(C + (size_t)(m + 8) * kG + n) = o1;
        }
    }
}

// ---------------- initial group barrier (per launch) ----------------------------
__device__ __forceinline__ void gbar_rel(int idx, int tid, int bg)
{
    __syncthreads();
    if (tid == 0) {
        int* cnt = &g_cnt[bg * 32];
        int* flg = &g_flg[bg * 32];
        int prev;
        asm volatile("atom.acq_rel.gpu.global.add.s32 %0, [%1], 1;"
                     : "=r"(prev) : "l"(cnt) : "memory");
        if (prev == idx * kGrpCTA - 1) {
            int dummy;
            asm volatile("atom.release.gpu.global.exch.b32 %0, [%1], %2;"
                         : "=r"(dummy) : "l"(flg), "r"(idx) : "memory");
        } else {
            int v;
            do {
                asm volatile("ld.acquire.gpu.global.s32 %0, [%1];"
                             : "=r"(v) : "l"(flg) : "memory");
            } while (v < idx);
        }
    }
    __syncthreads();
}

// ---------------- persistent HMMA LSTM recurrence ------------------------------
// R13 + layer-aware output: layer 0 emits h directly into g_As (bf16 hi|lo,
// GEMM layout) -> no split_x/g_h0 for layer 1. Flags are layer-monotonic via
// tbase (no state reset between launches).
__global__ void __launch_bounds__(256, 1)
lstm_recur_mma(const float* __restrict__ G,
               const __nv_bfloat16* __restrict__ WTh,
               const __nv_bfloat16* __restrict__ WTl,
               float* __restrict__ seqout,        // layer 1 only
               __nv_bfloat16* __restrict__ asOut, // layer 0 only
               float* __restrict__ hT, float* __restrict__ cT,
               const int tbase, const int gidx)
{
    __shared__ __align__(128) __nv_bfloat16 Ahs0[16][kHRowHalf];
    __shared__ __align__(128) __nv_bfloat16 Ahs1[16][kHRowHalf];
    __shared__ float gs[64 * 20];
    __shared__ float Gs[16][68];
    __shared__ float outF[16][16];
    __shared__ __nv_bfloat16 outB[16][32];
    __shared__ __align__(8) ull s_mbar[2];

    const int tid = threadIdx.x;
    const int cg  = blockIdx.x >> 2;
    const int bg  = blockIdx.x & 3;
    const int u0  = cg * 16;

    const int wid  = tid >> 5;
    const int lane = tid & 31;
    const int g8   = lane >> 2;
    const int tig  = lane & 3;

    const int pb = tid >> 4;
    const int pu = tid & 15;
    const int bglob = bg * 16 + pb;

    const uint32_t mbarA = smem_u32(&s_mbar[0]);
    const uint32_t mbarB = smem_u32(&s_mbar[1]);
    const uint32_t ahs0Addr = smem_u32(&Ahs0[0][0]);
    const uint32_t ahs1Addr = smem_u32(&Ahs1[0][0]);

    const int lrow = ((lane >> 3) & 1) * 8 + (lane & 7);
    const int lcol = (lane >> 4) * 8;
    const uint32_t lm0 = smem_u32(&Ahs0[lrow][lcol]);
    const uint32_t lm1 = smem_u32(&Ahs1[lrow][lcol]);

    // Wh B-fragments in registers (col c, full K, hi+lo)
    const int c  = wid * 8 + g8;
    const int ng = (c >> 4) * kH + u0 + (c & 15);
    uint32_t bfh[32][2], bfl[32][2];
#pragma unroll
    for (int ks = 0; ks < 32; ks++) {
        const int kk = ks * 16 + tig * 2;
        bfh[ks][0] = *(const uint32_t*)(WTh + (size_t)ng * 512 + kk);
        bfh[ks][1] = *(const uint32_t*)(WTh + (size_t)ng * 512 + kk + 8);
        bfl[ks][0] = *(const uint32_t*)(WTl + (size_t)ng * 512 + kk);
        bfl[ks][1] = *(const uint32_t*)(WTl + (size_t)ng * 512 + kk + 8);
    }

    // zero our slice of the h ping buffers (parity 0)
    {
        const int half = cg >> 4;
        const int cb = (cg & 15) * 16;
        g_hbf2[0][half][bglob][cb + pu]       = __float2bfloat16_rn(0.f);
        g_hbf2[0][half][bglob][256 + cb + pu] = __float2bfloat16_rn(0.f);
    }
    float c_state = 0.f;
    if (tid == 0) { mbar_init(mbarA, 1); mbar_init(mbarB, 1); }

    gbar_rel(gidx, tid, bg);   // once per launch

    for (int t = 0; t < kT; t++) {
        const int cur = t & 1;

        // stage this step's input projections (independent of h)
        {
            const int b = tid >> 4, q = tid & 15;
            const int gg = q >> 2, f = q & 3;
            const float* src = G + ((size_t)(bg * 16 + b) * kT + t) * kG
                             + gg * kH + u0 + f * 4;
            float4 v = __ldcs((const float4*)src);
            *(float4*)&Gs[b][gg * 16 + f * 4] = v;
        }

        // warp 0: poll all 32 producer flags; issue each half's copy the
        // moment its 16 producers are done
        if (wid == 0) {
            const int* fp = &g_hflag[bg][lane * 32];
            const int want = tbase + t;
            bool issuedA = false, issuedB = false;
            do {
                int v;
                asm volatile("ld.acquire.gpu.global.s32 %0, [%1];"
                             : "=r"(v) : "l"(fp) : "memory");
                const unsigned m = __ballot_sync(0xFFFFFFFFu, v >= want);
                if (!issuedA && (m & 0xFFFFu) == 0xFFFFu) {
                    if (lane == 0) {
                        mbar_expect(mbarA, kHalfBytes);
                        bulk_g2s(ahs0Addr, &g_hbf2[cur][0][bg * 16][0],
                                 kHalfBytes, mbarA);
                    }
                    issuedA = true;
                }
                if (!issuedB && (m >> 16) == 0xFFFFu) {
                    if (lane == 16) {
                        mbar_expect(mbarB, kHalfBytes);
                        bulk_g2s(ahs1Addr, &g_hbf2[cur][1][bg * 16][0],
                                 kHalfBytes, mbarB);
                    }
                    issuedB = true;
                }
            } while (!(issuedA && issuedB));
        }

        // gate GEMM: 16x8 per warp, K=512, 3-term split, per-half chains
        float a0[4] = {0.f, 0.f, 0.f, 0.f};
        float a1[4] = {0.f, 0.f, 0.f, 0.f};
        float a2[4] = {0.f, 0.f, 0.f, 0.f};
        float b0[4] = {0.f, 0.f, 0.f, 0.f};
        float b1[4] = {0.f, 0.f, 0.f, 0.f};
        float b2[4] = {0.f, 0.f, 0.f, 0.f};
        mbar_wait(mbarA, t & 1);
#pragma unroll
        for (int ks = 0; ks < 16; ks++) {
            uint32_t ah[4], al[4];
            ldmx4(ah, lm0 + ks * 32);
            ldmx4(al, lm0 + 512 + ks * 32);
            mma_bf16(a0, ah, bfh[ks]);
            mma_bf16(a1, al, bfh[ks]);
            mma_bf16(a2, ah, bfl[ks]);
        }
        mbar_wait(mbarB, t & 1);
#pragma unroll
        for (int ks = 0; ks < 16; ks++) {
            uint32_t ah[4], al[4];
            ldmx4(ah, lm1 + ks * 32);
            ldmx4(al, lm1 + 512 + ks * 32);
            mma_bf16(b0, ah, bfh[16 + ks]);
            mma_bf16(b1, al, bfh[16 + ks]);
            mma_bf16(b2, ah, bfl[16 + ks]);
        }
        const int cbase = (c - g8 + tig * 2) * 20;
        gs[cbase + g8]          = (a0[0] + a1[0]) + (a2[0] + b0[0]) + (b1[0] + b2[0]);
        gs[cbase + 20 + g8]     = (a0[1] + a1[1]) + (a2[1] + b0[1]) + (b1[1] + b2[1]);
        gs[cbase + g8 + 8]      = (a0[2] + a1[2]) + (a2[2] + b0[2]) + (b1[2] + b2[2]);
        gs[cbase + 20 + g8 + 8] = (a0[3] + a1[3]) + (a2[3] + b0[3]) + (b1[3] + b2[3]);
        __syncthreads();

        // pointwise LSTM cell (MUFU.TANH)
        {
            const float pre0 = Gs[pb][0 * 16 + pu] + gs[(0 * 16 + pu) * 20 + pb];
            const float pre1 = Gs[pb][1 * 16 + pu] + gs[(1 * 16 + pu) * 20 + pb];
            const float pre2 = Gs[pb][2 * 16 + pu] + gs[(2 * 16 + pu) * 20 + pb];
            const float pre3 = Gs[pb][3 * 16 + pu] + gs[(3 * 16 + pu) * 20 + pb];
            const float iv = sigf(pre0);
            const float fv = sigf(pre1);
            const float gv = tanh_hw(pre2);
            const float ov = sigf(pre3);
            c_state = fv * c_state + iv * gv;
            const float hval = ov * tanh_hw(c_state);

            outF[pb][pu] = hval;
            const __nv_bfloat16 hh = __float2bfloat16_rn(hval);
            const __nv_bfloat16 hl = __float2bfloat16_rn(hval - __bfloat162float(hh));
            outB[pb][pu]      = hh;
            outB[pb][16 + pu] = hl;
            if (t == kT - 1) {
                hT[(size_t)bglob * kH + u0 + pu] = hval;
                cT[(size_t)bglob * kH + u0 + pu] = c_state;
            }
        }
        __syncthreads();

        // warp 0: h-exchange writeback to our half-buffer + flag publish
        if (wid == 0) {
            const int half = cg >> 4;
            const int cb = (cg & 15) * 16;
#pragma unroll
            for (int j = 0; j < 2; j++) {
                const int e = lane * 2 + j;        // 0..63
                const int b = e >> 2, f = e & 3;
                const int col = (f < 2) ? (cb + f * 8)
                                        : (256 + cb + (f - 2) * 8);
                *(uint4*)(&g_hbf2[cur ^ 1][half][bg * 16 + b][col]) =
                    *(const uint4*)&outB[b][f * 8];
            }
            __syncwarp();
            if (lane == 0) {
                asm volatile("st.release.gpu.global.s32 [%0], %1;"
                             :: "l"(&g_hflag[bg][cg * 32]), "r"(tbase + t + 1)
                             : "memory");
            }
        } else if (wid < 3) {
            const int e = tid - 32;                // 0..63
            const int b = e >> 2, f = e & 3;
            if (asOut) {
                // layer 0: emit h as bf16 hi|lo straight into the GEMM A layout
                const size_t m = (size_t)(bg * 16 + b) * kT + t;
                const int col = (f < 2) ? (u0 + f * 8) : (512 + u0 + (f - 2) * 8);
                *(uint4*)(asOut + m * 1024 + col) = *(const uint4*)&outB[b][f * 8];
            } else {
                *(uint4*)(seqout + ((size_t)(bg * 16 + b) * kT + t) * kH
                          + u0 + f * 4) = *(const uint4*)&outF[b][f * 4];
            }
        }
        // SMEM reuse protected by the next step's mbar waits + post-gs sync
    }
}

// ---------------- launch --------------------------------------------------------
extern "C" void kernel_launch(void* const* d_in, const int* in_sizes, int n_in,
                              void* d_out, int out_size)
{
    const float* x  = (const float*)d_in[0];
    const float* Wi = (const float*)d_in[1];
    const float* Wh = (const float*)d_in[2];
    const float* bi = (const float*)d_in[3];
    const float* bh = (const float*)d_in[4];

    float* out  = (float*)d_out;
    float* outs = out;
    float* hT   = out + (size_t)kB * kT * kH;
    float* cT   = hT + (size_t)2 * kB * kH;

    float* Gp;  cudaGetSymbolAddress((void**)&Gp,  g_G);
    __nv_bfloat16 *asp, *wih, *wil, *whh, *whl;
    cudaGetSymbolAddress((void**)&asp, g_As);
    cudaGetSymbolAddress((void**)&wih, g_WiTh);
    cudaGetSymbolAddress((void**)&wil, g_WiTl);
    cudaGetSymbolAddress((void**)&whh, g_WhTh);
    cudaGetSymbolAddress((void**)&whl, g_WhTl);

    cudaFuncSetAttribute(gemm_mma, cudaFuncAttributeMaxDynamicSharedMemorySize,
                         kGemmSmem);

    const dim3 gSplit(64, 16);
    const dim3 gGemm(kG / 128, kM / 128);

    // ---- layer 0
    split_pair<<<gSplit, 256>>>(Wi, wih, wil);
    split_pair<<<gSplit, 256>>>(Wh, whh, whl);
    split_x<<<kM * kH / 1024, 256>>>(x);          // also resets barrier state
    gemm_mma<<<gGemm, 256, kGemmSmem>>>(bi, bh, Gp);
    lstm_recur_mma<<<kCG * kBG, 256>>>(Gp, whh, whl,
                                       nullptr, asp, hT, cT, 0, 1);

    // ---- layer 1 (g_As now holds layer-0 h, already split)
    split_pair<<<gSplit, 256>>>(Wi + (size_t)kH * kG, wih, wil);
    split_pair<<<gSplit, 256>>>(Wh + (size_t)kH * kG, whh, whl);
    gemm_mma<<<gGemm, 256, kGemmSmem>>>(bi + kG, bh + kG, Gp);
    lstm_recur_mma<<<kCG * kBG, 256>>>(Gp, whh, whl,
                                       outs, nullptr,
                                       hT + (size_t)kB * kH,
                                       cT + (size_t)kB * kH, kT, 2);
}

// round 15
// speedup vs baseline: 3.6005x; 1.0080x over previous
#include <cuda_runtime.h>
#include <cuda_bf16.h>
#include <cstdint>

typedef unsigned long long ull;

constexpr int kB = 64;      // batch
constexpr int kT = 256;     // time
constexpr int kH = 512;     // hidden
constexpr int kG = 2048;    // 4*H gate cols
constexpr int kM = kB * kT; // 16384 GEMM rows
constexpr int kCG = 32;     // column groups (16 hidden units each)
constexpr int kBG = 4;      // batch groups (16 batch elements each)
constexpr int kGrpCTA = kCG;
constexpr int kQRow = 264;                     // hi 128 | lo 128 | pad 8 (528B)
constexpr int kQBytes = 16 * kQRow * 2;        // 8448 per quarter tile

// ---------------- scratch ----------------------------------------------------
__device__ float  g_G[(size_t)kM * kG];            // input projections (128 MB)
__device__ __nv_bfloat16 g_As[(size_t)kM * 1024];  // A split hi|lo (32 MB)
__device__ __nv_bfloat16 g_WiTh[(size_t)kG * kH];  // Wi hi, transposed [N,K]
__device__ __nv_bfloat16 g_WiTl[(size_t)kG * kH];  // Wi lo
__device__ __nv_bfloat16 g_WhTh[(size_t)kG * kH];  // Wh hi, transposed [N,K]
__device__ __nv_bfloat16 g_WhTl[(size_t)kG * kH];  // Wh lo
// h exchange: [pingpong][k-quarter][batch][row(hi128|lo128|pad8)]
__device__ __align__(256) __nv_bfloat16 g_hbf4[2][4][kB][kQRow];
__device__ int g_cnt[kBG * 32];                    // initial barrier
__device__ int g_flg[kBG * 32];
__device__ int g_hflag[kBG][32 * 32];              // per-producer step flags

// ---------------- helpers -----------------------------------------------------
__device__ __forceinline__ float tanh_hw(float x) {
    float t;
    asm("tanh.approx.f32 %0, %1;" : "=f"(t) : "f"(x));
    return t;
}
__device__ __forceinline__ float sigf(float x) {
    return fmaf(tanh_hw(0.5f * x), 0.5f, 0.5f);
}

__device__ __forceinline__ void mma_bf16(float* c, const uint32_t* a,
                                         const uint32_t* b) {
    asm volatile(
        "mma.sync.aligned.m16n8k16.row.col.f32.bf16.bf16.f32 "
        "{%0,%1,%2,%3}, {%4,%5,%6,%7}, {%8,%9}, {%0,%1,%2,%3};"
        : "+f"(c[0]), "+f"(c[1]), "+f"(c[2]), "+f"(c[3])
        : "r"(a[0]), "r"(a[1]), "r"(a[2]), "r"(a[3]), "r"(b[0]), "r"(b[1]));
}
__device__ __forceinline__ void ldmx4(uint32_t* r, uint32_t addr) {
    asm volatile("ldmatrix.sync.aligned.m8n8.x4.shared.b16 {%0,%1,%2,%3}, [%4];"
                 : "=r"(r[0]), "=r"(r[1]), "=r"(r[2]), "=r"(r[3]) : "r"(addr));
}
__device__ __forceinline__ void ldmx2(uint32_t* r, uint32_t addr) {
    asm volatile("ldmatrix.sync.aligned.m8n8.x2.shared.b16 {%0,%1}, [%2];"
                 : "=r"(r[0]), "=r"(r[1]) : "r"(addr));
}
__device__ __forceinline__ uint32_t smem_u32(const void* p) {
    uint32_t a;
    asm("{ .reg .u64 t; cvta.to.shared.u64 t, %1; cvt.u32.u64 %0, t; }"
        : "=r"(a) : "l"(p));
    return a;
}
__device__ __forceinline__ void mbar_init(uint32_t a, uint32_t cnt) {
    asm volatile("mbarrier.init.shared.b64 [%0], %1;" :: "r"(a), "r"(cnt) : "memory");
}
__device__ __forceinline__ void mbar_wait(uint32_t a, uint32_t parity) {
    asm volatile(
        "{\n\t.reg .pred P;\n\t"
        "WL_%=:\n\t"
        "mbarrier.try_wait.parity.acquire.cta.shared::cta.b64 P, [%0], %1, 0x989680;\n\t"
        "@P bra.uni WD_%=;\n\t"
        "bra.uni WL_%=;\n\t"
        "WD_%=:\n\t}"
        :: "r"(a), "r"(parity) : "memory");
}
__device__ __forceinline__ void bulk_g2s(uint32_t dst, const void* src,
                                         uint32_t bytes, uint32_t mbar) {
    asm volatile(
        "cp.async.bulk.shared::cluster.global.mbarrier::complete_tx::bytes "
        "[%0], [%1], %2, [%3];"
        :: "r"(dst), "l"(src), "r"(bytes), "r"(mbar) : "memory");
}
__device__ __forceinline__ void mbar_expect(uint32_t mbar, uint32_t bytes) {
    asm volatile("mbarrier.arrive.expect_tx.shared.b64 _, [%0], %1;"
                 :: "r"(mbar), "r"(bytes) : "memory");
}

// ---------------- split/prep kernels -------------------------------------------
__global__ void __launch_bounds__(256)
split_x(const float* __restrict__ X)
{
    if (blockIdx.x == 0) {
        if (threadIdx.x < kBG) {
            g_cnt[threadIdx.x * 32] = 0;
            g_flg[threadIdx.x * 32] = 0;
        }
        for (int i = threadIdx.x; i < kBG * 32 * 32; i += 256)
            ((int*)g_hflag)[i] = 0;
    }
    size_t i = ((size_t)blockIdx.x * 256 + threadIdx.x) * 4;
    float4 v = *(const float4*)(X + i);
    size_t m = i >> 9;
    int k = (int)(i & 511);
    __nv_bfloat16 h0 = __float2bfloat16_rn(v.x);
    __nv_bfloat16 h1 = __float2bfloat16_rn(v.y);
    __nv_bfloat16 h2 = __float2bfloat16_rn(v.z);
    __nv_bfloat16 h3 = __float2bfloat16_rn(v.w);
    __nv_bfloat16 l0 = __float2bfloat16_rn(v.x - __bfloat162float(h0));
    __nv_bfloat16 l1 = __float2bfloat16_rn(v.y - __bfloat162float(h1));
    __nv_bfloat16 l2 = __float2bfloat16_rn(v.z - __bfloat162float(h2));
    __nv_bfloat16 l3 = __float2bfloat16_rn(v.w - __bfloat162float(h3));
    __nv_bfloat16* ph = g_As + m * 1024 + k;
    __nv_bfloat16* pl = ph + 512;
    *(__nv_bfloat162*)(ph)     = __nv_bfloat162(h0, h1);
    *(__nv_bfloat162*)(ph + 2) = __nv_bfloat162(h2, h3);
    *(__nv_bfloat162*)(pl)     = __nv_bfloat162(l0, l1);
    *(__nv_bfloat162*)(pl + 2) = __nv_bfloat162(l2, l3);
}

__global__ void __launch_bounds__(256)
split_pair(const float* __restrict__ W, __nv_bfloat16* __restrict__ dH,
           __nv_bfloat16* __restrict__ dL)
{
    __shared__ float tile[32][33];
    const int tx = threadIdx.x & 31;
    const int ty = threadIdx.x >> 5;
    const int n0 = blockIdx.x * 32;
    const int k0 = blockIdx.y * 32;
#pragma unroll
    for (int j = 0; j < 4; j++)
        tile[ty + j * 8][tx] = W[(size_t)(k0 + ty + j * 8) * kG + n0 + tx];
    __syncthreads();
#pragma unroll
    for (int j = 0; j < 4; j++) {
        const int n = n0 + ty + j * 8;
        const int k = k0 + tx;
        const float v = tile[tx][ty + j * 8];
        __nv_bfloat16 hi = __float2bfloat16_rn(v);
        __nv_bfloat16 lo = __float2bfloat16_rn(v - __bfloat162float(hi));
        dH[(size_t)n * kH + k] = hi;
        dL[(size_t)n * kH + k] = lo;
    }
}

// ---------------- HMMA input-projection GEMM (R13 version, measured best) ------
constexpr int kLds = 40;

__global__ void __launch_bounds__(256, 2)
gemm_mma(const float* __restrict__ bi, const float* __restrict__ bh,
         float* __restrict__ C)
{
    __shared__ __align__(16) __nv_bfloat16 Ah[128 * kLds];
    __shared__ __align__(16) __nv_bfloat16 Al[128 * kLds];
    __shared__ __align__(16) __nv_bfloat16 Bh[128 * kLds];
    __shared__ __align__(16) __nv_bfloat16 Bl[128 * kLds];

    const int tid  = threadIdx.x;
    const int wid  = tid >> 5;
    const int lane = tid & 31;
    const int g    = lane >> 2;
    const int tig  = lane & 3;
    const int n0 = blockIdx.x * 128;
    const int m0 = blockIdx.y * 128;
    const int wm = (wid >> 2) * 64;
    const int wn = (wid & 3) * 32;

    const int lr = tid >> 1;
    const int lh = tid & 1;

    const int lrow = ((lane >> 3) & 1) * 8 + (lane & 7);
    const int lcolB = (lane >> 4) * 16;
    const uint32_t aBaseH = smem_u32(Ah) + ((wm + lrow) * kLds) * 2 + lcolB;
    const uint32_t aBaseL = smem_u32(Al) + ((wm + lrow) * kLds) * 2 + lcolB;
    const int brow = wn + (lane & 7);
    const int bcolB = ((lane >> 3) & 1) * 16;
    const uint32_t bBaseH = smem_u32(Bh) + (brow * kLds) * 2 + bcolB;
    const uint32_t bBaseL = smem_u32(Bl) + (brow * kLds) * 2 + bcolB;

    float acc[4][4][4];
#pragma unroll
    for (int mf = 0; mf < 4; mf++)
#pragma unroll
        for (int nf = 0; nf < 4; nf++)
#pragma unroll
            for (int i = 0; i < 4; i++) acc[mf][nf][i] = 0.f;

    float2 bias2[4];
#pragma unroll
    for (int nf = 0; nf < 4; nf++) {
        const int n = n0 + wn + nf * 8 + tig * 2;
        bias2[nf].x = __ldg(bi + n) + __ldg(bh + n);
        bias2[nf].y = __ldg(bi + n + 1) + __ldg(bh + n + 1);
    }

    for (int kt = 0; kt < 16; kt++) {
        const int koff = kt * 32 + lh * 16;
        const __nv_bfloat16* pa = g_As   + (size_t)(m0 + lr) * 1024 + koff;
        const __nv_bfloat16* pl = pa + 512;
        const __nv_bfloat16* pb = g_WiTh + (size_t)(n0 + lr) * 512 + koff;
        const __nv_bfloat16* pc = g_WiTl + (size_t)(n0 + lr) * 512 + koff;
        uint4 vah0 = *(const uint4*)(pa);
        uint4 vah1 = *(const uint4*)(pa + 8);
        uint4 val0 = *(const uint4*)(pl);
        uint4 val1 = *(const uint4*)(pl + 8);
        uint4 vbh0 = *(const uint4*)(pb);
        uint4 vbh1 = *(const uint4*)(pb + 8);
        uint4 vbl0 = *(const uint4*)(pc);
        uint4 vbl1 = *(const uint4*)(pc + 8);
        __syncthreads();
        __nv_bfloat16* da = Ah + lr * kLds + lh * 16;
        __nv_bfloat16* dl = Al + lr * kLds + lh * 16;
        __nv_bfloat16* db = Bh + lr * kLds + lh * 16;
        __nv_bfloat16* dc = Bl + lr * kLds + lh * 16;
        *(uint4*)(da)     = vah0;
        *(uint4*)(da + 8) = vah1;
        *(uint4*)(dl)     = val0;
        *(uint4*)(dl + 8) = val1;
        *(uint4*)(db)     = vbh0;
        *(uint4*)(db + 8) = vbh1;
        *(uint4*)(dc)     = vbl0;
        *(uint4*)(dc + 8) = vbl1;
        __syncthreads();

#pragma unroll
        for (int ks = 0; ks < 2; ks++) {
            const int kOff = ks * 32;
            uint32_t bhf[4][2], blf[4][2];
#pragma unroll
            for (int nf = 0; nf < 4; nf++) {
                ldmx2(bhf[nf], bBaseH + nf * 8 * kLds * 2 + kOff);
                ldmx2(blf[nf], bBaseL + nf * 8 * kLds * 2 + kOff);
            }
#pragma unroll
            for (int mf = 0; mf < 4; mf++) {
                uint32_t ah[4], al[4];
                ldmx4(ah, aBaseH + mf * 16 * kLds * 2 + kOff);
                ldmx4(al, aBaseL + mf * 16 * kLds * 2 + kOff);
#pragma unroll
                for (int nf = 0; nf < 4; nf++) {
                    mma_bf16(acc[mf][nf], ah, bhf[nf]);
                    mma_bf16(acc[mf][nf], al, bhf[nf]);
                    mma_bf16(acc[mf][nf], ah, blf[nf]);
                }
            }
        }
    }

#pragma unroll
    for (int mf = 0; mf < 4; mf++) {
        const int m = m0 + wm + mf * 16 + g;
#pragma unroll
        for (int nf = 0; nf < 4; nf++) {
            const int n = n0 + wn + nf * 8 + tig * 2;
            float2 o0, o1;
            o0.x = acc[mf][nf][0] + bias2[nf].x;
            o0.y = acc[mf][nf][1] + bias2[nf].y;
            o1.x = acc[mf][nf][2] + bias2[nf].x;
            o1.y = acc[mf][nf][3] + bias2[nf].y;
            *(float2*)(C + (size_t)m * kG + n)       = o0;
            *(float2*)(C + (size_t)(m + 8) * kG + n) = o1;
        }
    }
}

// ---------------- initial group barrier (per launch) ----------------------------
__device__ __forceinline__ void gbar_rel(int idx, int tid, int bg)
{
    __syncthreads();
    if (tid == 0) {
        int* cnt = &g_cnt[bg * 32];
        int* flg = &g_flg[bg * 32];
        int prev;
        asm volatile("atom.acq_rel.gpu.global.add.s32 %0, [%1], 1;"
                     : "=r"(prev) : "l"(cnt) : "memory");
        if (prev == idx * kGrpCTA - 1) {
            int dummy;
            asm volatile("atom.release.gpu.global.exch.b32 %0, [%1], %2;"
                         : "=r"(dummy) : "l"(flg), "r"(idx) : "memory");
        } else {
            int v;
            do {
                asm volatile("ld.acquire.gpu.global.s32 %0, [%1];"
                             : "=r"(v) : "l"(flg) : "memory");
            } while (v < idx);
        }
    }
    __syncthreads();
}

// ---------------- persistent HMMA LSTM recurrence ------------------------------
// R14 + quarter-granularity exchange: 4 k-quarter buffers, 4 bulk copies, 4
// mbarriers. Each quarter's copy is issued the moment its 8 producers publish;
// the MMA consumes quarter-by-quarter so copies overlap compute.
__global__ void __launch_bounds__(256, 1)
lstm_recur_mma(const float* __restrict__ G,
               const __nv_bfloat16* __restrict__ WTh,
               const __nv_bfloat16* __restrict__ WTl,
               float* __restrict__ seqout,        // layer 1 only
               __nv_bfloat16* __restrict__ asOut, // layer 0 only
               float* __restrict__ hT, float* __restrict__ cT,
               const int tbase, const int gidx)
{
    __shared__ __align__(128) __nv_bfloat16 Ahs[4][16][kQRow];
    __shared__ float gs[64 * 20];
    __shared__ float Gs[16][68];
    __shared__ float outF[16][16];
    __shared__ __nv_bfloat16 outB[16][32];
    __shared__ __align__(8) ull s_mbar[4];

    const int tid = threadIdx.x;
    const int cg  = blockIdx.x >> 2;
    const int bg  = blockIdx.x & 3;
    const int u0  = cg * 16;

    const int wid  = tid >> 5;
    const int lane = tid & 31;
    const int g8   = lane >> 2;
    const int tig  = lane & 3;

    const int pb = tid >> 4;
    const int pu = tid & 15;
    const int bglob = bg * 16 + pb;

    uint32_t mbarQ[4], ahsQ[4], lmQ[4];
    const int lrow = ((lane >> 3) & 1) * 8 + (lane & 7);
    const int lcol = (lane >> 4) * 8;
#pragma unroll
    for (int q = 0; q < 4; q++) {
        mbarQ[q] = smem_u32(&s_mbar[q]);
        ahsQ[q]  = smem_u32(&Ahs[q][0][0]);
        lmQ[q]   = smem_u32(&Ahs[q][lrow][lcol]);
    }

    // Wh B-fragments in registers (col c, full K, hi+lo)
    const int c  = wid * 8 + g8;
    const int ng = (c >> 4) * kH + u0 + (c & 15);
    uint32_t bfh[32][2], bfl[32][2];
#pragma unroll
    for (int ks = 0; ks < 32; ks++) {
        const int kk = ks * 16 + tig * 2;
        bfh[ks][0] = *(const uint32_t*)(WTh + (size_t)ng * 512 + kk);
        bfh[ks][1] = *(const uint32_t*)(WTh + (size_t)ng * 512 + kk + 8);
        bfl[ks][0] = *(const uint32_t*)(WTl + (size_t)ng * 512 + kk);
        bfl[ks][1] = *(const uint32_t*)(WTl + (size_t)ng * 512 + kk + 8);
    }

    // producer's quarter + column base (16 units within the 128-unit quarter)
    const int qp = cg >> 3;
    const int cb = (cg & 7) * 16;

    // zero our slice of the h ping buffers (parity 0)
    g_hbf4[0][qp][bglob][cb + pu]       = __float2bfloat16_rn(0.f);
    g_hbf4[0][qp][bglob][128 + cb + pu] = __float2bfloat16_rn(0.f);
    float c_state = 0.f;
    if (tid < 4) mbar_init(mbarQ[tid], 1);

    gbar_rel(gidx, tid, bg);   // once per launch

    for (int t = 0; t < kT; t++) {
        const int cur = t & 1;

        // stage this step's input projections (independent of h)
        {
            const int b = tid >> 4, q = tid & 15;
            const int gg = q >> 2, f = q & 3;
            const float* src = G + ((size_t)(bg * 16 + b) * kT + t) * kG
                             + gg * kH + u0 + f * 4;
            float4 v = __ldcs((const float4*)src);
            *(float4*)&Gs[b][gg * 16 + f * 4] = v;
        }

        // warp 0: poll 32 producer flags; issue each quarter's copy the moment
        // its 8 producers are done
        if (wid == 0) {
            const int* fp = &g_hflag[bg][lane * 32];
            const int want = tbase + t;
            unsigned issued = 0;
            do {
                int v;
                asm volatile("ld.acquire.gpu.global.s32 %0, [%1];"
                             : "=r"(v) : "l"(fp) : "memory");
                const unsigned m = __ballot_sync(0xFFFFFFFFu, v >= want);
#pragma unroll
                for (int q = 0; q < 4; q++) {
                    if (!(issued & (1u << q)) &&
                        ((m >> (8 * q)) & 0xFFu) == 0xFFu) {
                        if (lane == 8 * q) {
                            mbar_expect(mbarQ[q], kQBytes);
                            bulk_g2s(ahsQ[q], &g_hbf4[cur][q][bg * 16][0],
                                     kQBytes, mbarQ[q]);
                        }
                        issued |= 1u << q;
                    }
                }
            } while (issued != 0xFu);
        }

        // gate GEMM: 16x8 per warp, K=512, 3-term split, per-half chains.
        // Consume quarter-by-quarter; later quarters' copies overlap compute.
        float a0[4] = {0.f, 0.f, 0.f, 0.f};
        float a1[4] = {0.f, 0.f, 0.f, 0.f};
        float a2[4] = {0.f, 0.f, 0.f, 0.f};
        float b0[4] = {0.f, 0.f, 0.f, 0.f};
        float b1[4] = {0.f, 0.f, 0.f, 0.f};
        float b2[4] = {0.f, 0.f, 0.f, 0.f};
#pragma unroll
        for (int q = 0; q < 4; q++) {
            mbar_wait(mbarQ[q], t & 1);
            float* r0 = (q < 2) ? a0 : b0;
            float* r1 = (q < 2) ? a1 : b1;
            float* r2 = (q < 2) ? a2 : b2;
#pragma unroll
            for (int ks = 0; ks < 8; ks++) {
                uint32_t ah[4], al[4];
                ldmx4(ah, lmQ[q] + ks * 32);
                ldmx4(al, lmQ[q] + 256 + ks * 32);
                mma_bf16(r0, ah, bfh[q * 8 + ks]);
                mma_bf16(r1, al, bfh[q * 8 + ks]);
                mma_bf16(r2, ah, bfl[q * 8 + ks]);
            }
        }
        const int cbase = (c - g8 + tig * 2) * 20;
        gs[cbase + g8]          = (a0[0] + a1[0]) + (a2[0] + b0[0]) + (b1[0] + b2[0]);
        gs[cbase + 20 + g8]     = (a0[1] + a1[1]) + (a2[1] + b0[1]) + (b1[1] + b2[1]);
        gs[cbase + g8 + 8]      = (a0[2] + a1[2]) + (a2[2] + b0[2]) + (b1[2] + b2[2]);
        gs[cbase + 20 + g8 + 8] = (a0[3] + a1[3]) + (a2[3] + b0[3]) + (b1[3] + b2[3]);
        __syncthreads();

        // pointwise LSTM cell (MUFU.TANH)
        {
            const float pre0 = Gs[pb][0 * 16 + pu] + gs[(0 * 16 + pu) * 20 + pb];
            const float pre1 = Gs[pb][1 * 16 + pu] + gs[(1 * 16 + pu) * 20 + pb];
            const float pre2 = Gs[pb][2 * 16 + pu] + gs[(2 * 16 + pu) * 20 + pb];
            const float pre3 = Gs[pb][3 * 16 + pu] + gs[(3 * 16 + pu) * 20 + pb];
            const float iv = sigf(pre0);
            const float fv = sigf(pre1);
            const float gv = tanh_hw(pre2);
            const float ov = sigf(pre3);
            c_state = fv * c_state + iv * gv;
            const float hval = ov * tanh_hw(c_state);

            outF[pb][pu] = hval;
            const __nv_bfloat16 hh = __float2bfloat16_rn(hval);
            const __nv_bfloat16 hl = __float2bfloat16_rn(hval - __bfloat162float(hh));
            outB[pb][pu]      = hh;
            outB[pb][16 + pu] = hl;
            if (t == kT - 1) {
                hT[(size_t)bglob * kH + u0 + pu] = hval;
                cT[(size_t)bglob * kH + u0 + pu] = c_state;
            }
        }
        __syncthreads();

        // warp 0: h-exchange writeback into our quarter buffer + flag publish
        if (wid == 0) {
#pragma unroll
            for (int j = 0; j < 2; j++) {
                const int e = lane * 2 + j;        // 0..63
                const int b = e >> 2, f = e & 3;
                const int col = (f < 2) ? (cb + f * 8)
                                        : (128 + cb + (f - 2) * 8);
                *(uint4*)(&g_hbf4[cur ^ 1][qp][bg * 16 + b][col]) =
                    *(const uint4*)&outB[b][f * 8];
            }
            __syncwarp();
            if (lane == 0) {
                asm volatile("st.release.gpu.global.s32 [%0], %1;"
                             :: "l"(&g_hflag[bg][cg * 32]), "r"(tbase + t + 1)
                             : "memory");
            }
        } else if (wid < 3) {
            const int e = tid - 32;                // 0..63
            const int b = e >> 2, f = e & 3;
            if (asOut) {
                // layer 0: emit h as bf16 hi|lo straight into the GEMM A layout
                const size_t m = (size_t)(bg * 16 + b) * kT + t;
                const int col = (f < 2) ? (u0 + f * 8) : (512 + u0 + (f - 2) * 8);
                *(uint4*)(asOut + m * 1024 + col) = *(const uint4*)&outB[b][f * 8];
            } else {
                *(uint4*)(seqout + ((size_t)(bg * 16 + b) * kT + t) * kH
                          + u0 + f * 4) = *(const uint4*)&outF[b][f * 4];
            }
        }
        // SMEM reuse protected by the next step's mbar waits + post-gs sync
    }
}

// ---------------- launch --------------------------------------------------------
extern "C" void kernel_launch(void* const* d_in, const int* in_sizes, int n_in,
                              void* d_out, int out_size)
{
    const float* x  = (const float*)d_in[0];
    const float* Wi = (const float*)d_in[1];
    const float* Wh = (const float*)d_in[2];
    const float* bi = (const float*)d_in[3];
    const float* bh = (const float*)d_in[4];

    float* out  = (float*)d_out;
    float* outs = out;
    float* hT   = out + (size_t)kB * kT * kH;
    float* cT   = hT + (size_t)2 * kB * kH;

    float* Gp;  cudaGetSymbolAddress((void**)&Gp,  g_G);
    __nv_bfloat16 *asp, *wih, *wil, *whh, *whl;
    cudaGetSymbolAddress((void**)&asp, g_As);
    cudaGetSymbolAddress((void**)&wih, g_WiTh);
    cudaGetSymbolAddress((void**)&wil, g_WiTl);
    cudaGetSymbolAddress((void**)&whh, g_WhTh);
    cudaGetSymbolAddress((void**)&whl, g_WhTl);

    const dim3 gSplit(64, 16);
    const dim3 gGemm(kG / 128, kM / 128);

    // ---- layer 0
    split_pair<<<gSplit, 256>>>(Wi, wih, wil);
    split_pair<<<gSplit, 256>>>(Wh, whh, whl);
    split_x<<<kM * kH / 1024, 256>>>(x);          // also resets barrier state
    gemm_mma<<<gGemm, 256>>>(bi, bh, Gp);
    lstm_recur_mma<<<kCG * kBG, 256>>>(Gp, whh, whl,
                                       nullptr, asp, hT, cT, 0, 1);

    // ---- layer 1 (g_As now holds layer-0 h, already split)
    split_pair<<<gSplit, 256>>>(Wi + (size_t)kH * kG, wih, wil);
    split_pair<<<gSplit, 256>>>(Wh + (size_t)kH * kG, whh, whl);
    gemm_mma<<<gGemm, 256>>>(bi + kG, bh + kG, Gp);
    lstm_recur_mma<<<kCG * kBG, 256>>>(Gp, whh, whl,
                                       outs, nullptr,
                                       hT + (size_t)kB * kH,
                                       cT + (size_t)kB * kH, kT, 2);
}

// round 16
// speedup vs baseline: 3.6262x; 1.0071x over previous
#include <cuda_runtime.h>
#include <cuda_bf16.h>
#include <cstdint>

typedef unsigned long long ull;

constexpr int kB = 64;      // batch
constexpr int kT = 256;     // time
constexpr int kH = 512;     // hidden
constexpr int kG = 2048;    // 4*H gate cols
constexpr int kM = kB * kT; // 16384 GEMM rows
constexpr int kCG = 32;     // column groups (16 hidden units each)
constexpr int kBG = 4;      // batch groups (16 batch elements each)
constexpr int kGrpCTA = kCG;
constexpr int kQRow = 264;                     // hi 128 | lo 128 | pad 8 (528B)
constexpr int kQBytes = 16 * kQRow * 2;        // 8448 per quarter tile

// ---------------- scratch ----------------------------------------------------
__device__ float  g_G[(size_t)kM * kG];            // input projections (128 MB)
__device__ __nv_bfloat16 g_As[(size_t)kM * 1024];  // A split hi|lo (32 MB)
__device__ __nv_bfloat16 g_WiTh[(size_t)kG * kH];  // Wi hi, transposed [N,K]
__device__ __nv_bfloat16 g_WiTl[(size_t)kG * kH];  // Wi lo
__device__ __nv_bfloat16 g_WhTh[(size_t)kG * kH];  // Wh hi, transposed [N,K]
__device__ __nv_bfloat16 g_WhTl[(size_t)kG * kH];  // Wh lo
// h exchange: [pingpong][k-quarter][batch][row(hi128|lo128|pad8)]
__device__ __align__(256) __nv_bfloat16 g_hbf4[2][4][kB][kQRow];
__device__ int g_cnt[kBG * 32];                    // initial barrier
__device__ int g_flg[kBG * 32];
__device__ int g_hflag[kBG][32 * 32];              // per-producer step flags

// ---------------- helpers -----------------------------------------------------
__device__ __forceinline__ float tanh_hw(float x) {
    float t;
    asm("tanh.approx.f32 %0, %1;" : "=f"(t) : "f"(x));
    return t;
}
__device__ __forceinline__ float sigf(float x) {
    return fmaf(tanh_hw(0.5f * x), 0.5f, 0.5f);
}

__device__ __forceinline__ void mma_bf16(float* c, const uint32_t* a,
                                         const uint32_t* b) {
    asm volatile(
        "mma.sync.aligned.m16n8k16.row.col.f32.bf16.bf16.f32 "
        "{%0,%1,%2,%3}, {%4,%5,%6,%7}, {%8,%9}, {%0,%1,%2,%3};"
        : "+f"(c[0]), "+f"(c[1]), "+f"(c[2]), "+f"(c[3])
        : "r"(a[0]), "r"(a[1]), "r"(a[2]), "r"(a[3]), "r"(b[0]), "r"(b[1]));
}
__device__ __forceinline__ void ldmx4(uint32_t* r, uint32_t addr) {
    asm volatile("ldmatrix.sync.aligned.m8n8.x4.shared.b16 {%0,%1,%2,%3}, [%4];"
                 : "=r"(r[0]), "=r"(r[1]), "=r"(r[2]), "=r"(r[3]) : "r"(addr));
}
__device__ __forceinline__ void ldmx2(uint32_t* r, uint32_t addr) {
    asm volatile("ldmatrix.sync.aligned.m8n8.x2.shared.b16 {%0,%1}, [%2];"
                 : "=r"(r[0]), "=r"(r[1]) : "r"(addr));
}
__device__ __forceinline__ uint32_t smem_u32(const void* p) {
    uint32_t a;
    asm("{ .reg .u64 t; cvta.to.shared.u64 t, %1; cvt.u32.u64 %0, t; }"
        : "=r"(a) : "l"(p));
    return a;
}
__device__ __forceinline__ void mbar_init(uint32_t a, uint32_t cnt) {
    asm volatile("mbarrier.init.shared.b64 [%0], %1;" :: "r"(a), "r"(cnt) : "memory");
}
__device__ __forceinline__ void mbar_wait(uint32_t a, uint32_t parity) {
    asm volatile(
        "{\n\t.reg .pred P;\n\t"
        "WL_%=:\n\t"
        "mbarrier.try_wait.parity.acquire.cta.shared::cta.b64 P, [%0], %1, 0x989680;\n\t"
        "@P bra.uni WD_%=;\n\t"
        "bra.uni WL_%=;\n\t"
        "WD_%=:\n\t}"
        :: "r"(a), "r"(parity) : "memory");
}
__device__ __forceinline__ void bulk_g2s(uint32_t dst, const void* src,
                                         uint32_t bytes, uint32_t mbar) {
    asm volatile(
        "cp.async.bulk.shared::cluster.global.mbarrier::complete_tx::bytes "
        "[%0], [%1], %2, [%3];"
        :: "r"(dst), "l"(src), "r"(bytes), "r"(mbar) : "memory");
}
__device__ __forceinline__ void mbar_expect(uint32_t mbar, uint32_t bytes) {
    asm volatile("mbarrier.arrive.expect_tx.shared.b64 _, [%0], %1;"
                 :: "r"(mbar), "r"(bytes) : "memory");
}

// ---------------- split/prep kernels -------------------------------------------
__global__ void __launch_bounds__(256)
split_x(const float* __restrict__ X)
{
    if (blockIdx.x == 0) {
        if (threadIdx.x < kBG) {
            g_cnt[threadIdx.x * 32] = 0;
            g_flg[threadIdx.x * 32] = 0;
        }
        for (int i = threadIdx.x; i < kBG * 32 * 32; i += 256)
            ((int*)g_hflag)[i] = 0;
    }
    size_t i = ((size_t)blockIdx.x * 256 + threadIdx.x) * 4;
    float4 v = *(const float4*)(X + i);
    size_t m = i >> 9;
    int k = (int)(i & 511);
    __nv_bfloat16 h0 = __float2bfloat16_rn(v.x);
    __nv_bfloat16 h1 = __float2bfloat16_rn(v.y);
    __nv_bfloat16 h2 = __float2bfloat16_rn(v.z);
    __nv_bfloat16 h3 = __float2bfloat16_rn(v.w);
    __nv_bfloat16 l0 = __float2bfloat16_rn(v.x - __bfloat162float(h0));
    __nv_bfloat16 l1 = __float2bfloat16_rn(v.y - __bfloat162float(h1));
    __nv_bfloat16 l2 = __float2bfloat16_rn(v.z - __bfloat162float(h2));
    __nv_bfloat16 l3 = __float2bfloat16_rn(v.w - __bfloat162float(h3));
    __nv_bfloat16* ph = g_As + m * 1024 + k;
    __nv_bfloat16* pl = ph + 512;
    *(__nv_bfloat162*)(ph)     = __nv_bfloat162(h0, h1);
    *(__nv_bfloat162*)(ph + 2) = __nv_bfloat162(h2, h3);
    *(__nv_bfloat162*)(pl)     = __nv_bfloat162(l0, l1);
    *(__nv_bfloat162*)(pl + 2) = __nv_bfloat162(l2, l3);
}

__global__ void __launch_bounds__(256)
split_pair(const float* __restrict__ W, __nv_bfloat16* __restrict__ dH,
           __nv_bfloat16* __restrict__ dL)
{
    __shared__ float tile[32][33];
    const int tx = threadIdx.x & 31;
    const int ty = threadIdx.x >> 5;
    const int n0 = blockIdx.x * 32;
    const int k0 = blockIdx.y * 32;
#pragma unroll
    for (int j = 0; j < 4; j++)
        tile[ty + j * 8][tx] = W[(size_t)(k0 + ty + j * 8) * kG + n0 + tx];
    __syncthreads();
#pragma unroll
    for (int j = 0; j < 4; j++) {
        const int n = n0 + ty + j * 8;
        const int k = k0 + tx;
        const float v = tile[tx][ty + j * 8];
        __nv_bfloat16 hi = __float2bfloat16_rn(v);
        __nv_bfloat16 lo = __float2bfloat16_rn(v - __bfloat162float(hi));
        dH[(size_t)n * kH + k] = hi;
        dL[(size_t)n * kH + k] = lo;
    }
}

// ---------------- HMMA input-projection GEMM (R15 version, measured best) ------
constexpr int kLds = 40;

__global__ void __launch_bounds__(256, 2)
gemm_mma(const float* __restrict__ bi, const float* __restrict__ bh,
         float* __restrict__ C)
{
    __shared__ __align__(16) __nv_bfloat16 Ah[128 * kLds];
    __shared__ __align__(16) __nv_bfloat16 Al[128 * kLds];
    __shared__ __align__(16) __nv_bfloat16 Bh[128 * kLds];
    __shared__ __align__(16) __nv_bfloat16 Bl[128 * kLds];

    const int tid  = threadIdx.x;
    const int wid  = tid >> 5;
    const int lane = tid & 31;
    const int g    = lane >> 2;
    const int tig  = lane & 3;
    const int n0 = blockIdx.x * 128;
    const int m0 = blockIdx.y * 128;
    const int wm = (wid >> 2) * 64;
    const int wn = (wid & 3) * 32;

    const int lr = tid >> 1;
    const int lh = tid & 1;

    const int lrow = ((lane >> 3) & 1) * 8 + (lane & 7);
    const int lcolB = (lane >> 4) * 16;
    const uint32_t aBaseH = smem_u32(Ah) + ((wm + lrow) * kLds) * 2 + lcolB;
    const uint32_t aBaseL = smem_u32(Al) + ((wm + lrow) * kLds) * 2 + lcolB;
    const int brow = wn + (lane & 7);
    const int bcolB = ((lane >> 3) & 1) * 16;
    const uint32_t bBaseH = smem_u32(Bh) + (brow * kLds) * 2 + bcolB;
    const uint32_t bBaseL = smem_u32(Bl) + (brow * kLds) * 2 + bcolB;

    float acc[4][4][4];
#pragma unroll
    for (int mf = 0; mf < 4; mf++)
#pragma unroll
        for (int nf = 0; nf < 4; nf++)
#pragma unroll
            for (int i = 0; i < 4; i++) acc[mf][nf][i] = 0.f;

    float2 bias2[4];
#pragma unroll
    for (int nf = 0; nf < 4; nf++) {
        const int n = n0 + wn + nf * 8 + tig * 2;
        bias2[nf].x = __ldg(bi + n) + __ldg(bh + n);
        bias2[nf].y = __ldg(bi + n + 1) + __ldg(bh + n + 1);
    }

    for (int kt = 0; kt < 16; kt++) {
        const int koff = kt * 32 + lh * 16;
        const __nv_bfloat16* pa = g_As   + (size_t)(m0 + lr) * 1024 + koff;
        const __nv_bfloat16* pl = pa + 512;
        const __nv_bfloat16* pb = g_WiTh + (size_t)(n0 + lr) * 512 + koff;
        const __nv_bfloat16* pc = g_WiTl + (size_t)(n0 + lr) * 512 + koff;
        uint4 vah0 = *(const uint4*)(pa);
        uint4 vah1 = *(const uint4*)(pa + 8);
        uint4 val0 = *(const uint4*)(pl);
        uint4 val1 = *(const uint4*)(pl + 8);
        uint4 vbh0 = *(const uint4*)(pb);
        uint4 vbh1 = *(const uint4*)(pb + 8);
        uint4 vbl0 = *(const uint4*)(pc);
        uint4 vbl1 = *(const uint4*)(pc + 8);
        __syncthreads();
        __nv_bfloat16* da = Ah + lr * kLds + lh * 16;
        __nv_bfloat16* dl = Al + lr * kLds + lh * 16;
        __nv_bfloat16* db = Bh + lr * kLds + lh * 16;
        __nv_bfloat16* dc = Bl + lr * kLds + lh * 16;
        *(uint4*)(da)     = vah0;
        *(uint4*)(da + 8) = vah1;
        *(uint4*)(dl)     = val0;
        *(uint4*)(dl + 8) = val1;
        *(uint4*)(db)     = vbh0;
        *(uint4*)(db + 8) = vbh1;
        *(uint4*)(dc)     = vbl0;
        *(uint4*)(dc + 8) = vbl1;
        __syncthreads();

#pragma unroll
        for (int ks = 0; ks < 2; ks++) {
            const int kOff = ks * 32;
            uint32_t bhf[4][2], blf[4][2];
#pragma unroll
            for (int nf = 0; nf < 4; nf++) {
                ldmx2(bhf[nf], bBaseH + nf * 8 * kLds * 2 + kOff);
                ldmx2(blf[nf], bBaseL + nf * 8 * kLds * 2 + kOff);
            }
#pragma unroll
            for (int mf = 0; mf < 4; mf++) {
                uint32_t ah[4], al[4];
                ldmx4(ah, aBaseH + mf * 16 * kLds * 2 + kOff);
                ldmx4(al, aBaseL + mf * 16 * kLds * 2 + kOff);
#pragma unroll
                for (int nf = 0; nf < 4; nf++) {
                    mma_bf16(acc[mf][nf], ah, bhf[nf]);
                    mma_bf16(acc[mf][nf], al, bhf[nf]);
                    mma_bf16(acc[mf][nf], ah, blf[nf]);
                }
            }
        }
    }

#pragma unroll
    for (int mf = 0; mf < 4; mf++) {
        const int m = m0 + wm + mf * 16 + g;
#pragma unroll
        for (int nf = 0; nf < 4; nf++) {
            const int n = n0 + wn + nf * 8 + tig * 2;
            float2 o0, o1;
            o0.x = acc[mf][nf][0] + bias2[nf].x;
            o0.y = acc[mf][nf][1] + bias2[nf].y;
            o1.x = acc[mf][nf][2] + bias2[nf].x;
            o1.y = acc[mf][nf][3] + bias2[nf].y;
            *(float2*)(C + (size_t)m * kG + n)       = o0;
            *(float2*)(C + (size_t)(m + 8) * kG + n) = o1;
        }
    }
}

// ---------------- initial group barrier (per launch) ----------------------------
__device__ __forceinline__ void gbar_rel(int idx, int tid, int bg)
{
    __syncthreads();
    if (tid == 0) {
        int* cnt = &g_cnt[bg * 32];
        int* flg = &g_flg[bg * 32];
        int prev;
        asm volatile("atom.acq_rel.gpu.global.add.s32 %0, [%1], 1;"
                     : "=r"(prev) : "l"(cnt) : "memory");
        if (prev == idx * kGrpCTA - 1) {
            int dummy;
            asm volatile("atom.release.gpu.global.exch.b32 %0, [%1], %2;"
                         : "=r"(dummy) : "l"(flg), "r"(idx) : "memory");
        } else {
            int v;
            do {
                asm volatile("ld.acquire.gpu.global.s32 %0, [%1];"
                             : "=r"(v) : "l"(flg) : "memory");
            } while (v < idx);
        }
    }
    __syncthreads();
}

// ---------------- persistent HMMA LSTM recurrence ------------------------------
// R15 + warp-local pointwise: warp w owns gate cols {g*16 + 2w + j}, so after
// its MMAs the 4 gates of each (b, u=2w+j) live in-warp. Tiny per-warp SMEM
// exchange (syncwarp), 1 pointwise value/thread, direct h store, ONE CTA
// barrier before the flag. seqout/asOut writes land after the flag.
__global__ void __launch_bounds__(256, 1)
lstm_recur_mma(const float* __restrict__ G,
               const __nv_bfloat16* __restrict__ WTh,
               const __nv_bfloat16* __restrict__ WTl,
               float* __restrict__ seqout,        // layer 1 only
               __nv_bfloat16* __restrict__ asOut, // layer 0 only
               float* __restrict__ hT, float* __restrict__ cT,
               const int tbase, const int gidx)
{
    __shared__ __align__(128) __nv_bfloat16 Ahs[4][16][kQRow];
    __shared__ __align__(16) float wgs[8 * 32 * 4];  // per-warp gate exchange
    __shared__ float Gs[16][68];
    __shared__ __align__(8) ull s_mbar[4];

    const int tid = threadIdx.x;
    const int cg  = blockIdx.x >> 2;
    const int bg  = blockIdx.x & 3;
    const int u0  = cg * 16;

    const int wid  = tid >> 5;
    const int lane = tid & 31;
    const int g8   = lane >> 2;
    const int tig  = lane & 3;

    uint32_t mbarQ[4], ahsQ[4], lmQ[4];
    const int lrow = ((lane >> 3) & 1) * 8 + (lane & 7);
    const int lcol = (lane >> 4) * 8;
#pragma unroll
    for (int q = 0; q < 4; q++) {
        mbarQ[q] = smem_u32(&s_mbar[q]);
        ahsQ[q]  = smem_u32(&Ahs[q][0][0]);
        lmQ[q]   = smem_u32(&Ahs[q][lrow][lcol]);
    }

    // Wh B-fragments: lane's B col (n_idx = g8) -> gate g8>>1, unit 2*wid+(g8&1)
    const int ng = (g8 >> 1) * kH + u0 + 2 * wid + (g8 & 1);
    uint32_t bfh[32][2], bfl[32][2];
#pragma unroll
    for (int ks = 0; ks < 32; ks++) {
        const int kk = ks * 16 + tig * 2;
        bfh[ks][0] = *(const uint32_t*)(WTh + (size_t)ng * 512 + kk);
        bfh[ks][1] = *(const uint32_t*)(WTh + (size_t)ng * 512 + kk + 8);
        bfl[ks][0] = *(const uint32_t*)(WTl + (size_t)ng * 512 + kk);
        bfl[ks][1] = *(const uint32_t*)(WTl + (size_t)ng * 512 + kk + 8);
    }

    // pointwise identity: thread = (warp wid, lane) -> u = 2*wid + (lane>>4),
    // local batch pb = lane & 15
    const int pj = lane >> 4;
    const int pb = lane & 15;
    const int pu = 2 * wid + pj;
    const int bglob = bg * 16 + pb;

    // producer's quarter + column base (16 units within the 128-unit quarter)
    const int qp = cg >> 3;
    const int cb = (cg & 7) * 16;

    // zero our slice of the h ping buffers (parity 0)
    g_hbf4[0][qp][bglob][cb + pu]       = __float2bfloat16_rn(0.f);
    g_hbf4[0][qp][bglob][128 + cb + pu] = __float2bfloat16_rn(0.f);
    float c_state = 0.f;
    if (tid < 4) mbar_init(mbarQ[tid], 1);

    gbar_rel(gidx, tid, bg);   // once per launch

    for (int t = 0; t < kT; t++) {
        const int cur = t & 1;

        // stage this step's input projections (coalesced)
        {
            const int b = tid >> 4, q = tid & 15;
            const int gg = q >> 2, f = q & 3;
            const float* src = G + ((size_t)(bg * 16 + b) * kT + t) * kG
                             + gg * kH + u0 + f * 4;
            float4 v = __ldcs((const float4*)src);
            *(float4*)&Gs[b][gg * 16 + f * 4] = v;
        }
        __syncthreads();   // Gs visible to all; also fences wgs/Ahs reuse

        // warp 0: poll 32 producer flags; issue each quarter's copy the moment
        // its 8 producers are done
        if (wid == 0) {
            const int* fp = &g_hflag[bg][lane * 32];
            const int want = tbase + t;
            unsigned issued = 0;
            do {
                int v;
                asm volatile("ld.acquire.gpu.global.s32 %0, [%1];"
                             : "=r"(v) : "l"(fp) : "memory");
                const unsigned m = __ballot_sync(0xFFFFFFFFu, v >= want);
#pragma unroll
                for (int q = 0; q < 4; q++) {
                    if (!(issued & (1u << q)) &&
                        ((m >> (8 * q)) & 0xFFu) == 0xFFu) {
                        if (lane == 8 * q) {
                            mbar_expect(mbarQ[q], kQBytes);
                            bulk_g2s(ahsQ[q], &g_hbf4[cur][q][bg * 16][0],
                                     kQBytes, mbarQ[q]);
                        }
                        issued |= 1u << q;
                    }
                }
            } while (issued != 0xFu);
        }

        // gate GEMM: 16x8 per warp, K=512, 3-term split, per-half chains
        float a0[4] = {0.f, 0.f, 0.f, 0.f};
        float a1[4] = {0.f, 0.f, 0.f, 0.f};
        float a2[4] = {0.f, 0.f, 0.f, 0.f};
        float b0[4] = {0.f, 0.f, 0.f, 0.f};
        float b1[4] = {0.f, 0.f, 0.f, 0.f};
        float b2[4] = {0.f, 0.f, 0.f, 0.f};
#pragma unroll
        for (int q = 0; q < 4; q++) {
            mbar_wait(mbarQ[q], t & 1);
            float* r0 = (q < 2) ? a0 : b0;
            float* r1 = (q < 2) ? a1 : b1;
            float* r2 = (q < 2) ? a2 : b2;
#pragma unroll
            for (int ks = 0; ks < 8; ks++) {
                uint32_t ah[4], al[4];
                ldmx4(ah, lmQ[q] + ks * 32);
                ldmx4(al, lmQ[q] + 256 + ks * 32);
                mma_bf16(r0, ah, bfh[q * 8 + ks]);
                mma_bf16(r1, al, bfh[q * 8 + ks]);
                mma_bf16(r2, ah, bfl[q * 8 + ks]);
            }
        }

        // warp-local gate exchange: thread (g8,tig) holds
        //   c[0]=(b=g8, gate=tig, j=0) c[1]=(g8,tig,1) c[2]=(g8+8,tig,0) c[3]=(g8+8,tig,1)
        // store into wgs[wid][j*16+b][gate]  (stride 4 -> conflict-free)
        {
            float* wg = wgs + wid * 128;
            wg[(0 * 16 + g8) * 4 + tig]     = (a0[0] + a1[0]) + (a2[0] + b0[0]) + (b1[0] + b2[0]);
            wg[(1 * 16 + g8) * 4 + tig]     = (a0[1] + a1[1]) + (a2[1] + b0[1]) + (b1[1] + b2[1]);
            wg[(0 * 16 + g8 + 8) * 4 + tig] = (a0[2] + a1[2]) + (a2[2] + b0[2]) + (b1[2] + b2[2]);
            wg[(1 * 16 + g8 + 8) * 4 + tig] = (a0[3] + a1[3]) + (a2[3] + b0[3]) + (b1[3] + b2[3]);
        }
        __syncwarp();

        // pointwise: one (b,u) per thread; float4 read is conflict-free
        float hval;
        {
            const float4 gv4 = *(const float4*)(wgs + wid * 128 + (pj * 16 + pb) * 4);
            const float iv = sigf(gv4.x + Gs[pb][0 * 16 + pu]);
            const float fv = sigf(gv4.y + Gs[pb][1 * 16 + pu]);
            const float gv = tanh_hw(gv4.z + Gs[pb][2 * 16 + pu]);
            const float ov = sigf(gv4.w + Gs[pb][3 * 16 + pu]);
            c_state = fv * c_state + iv * gv;
            hval = ov * tanh_hw(c_state);
        }
        // direct h-exchange store (bf16 hi/lo)
        const __nv_bfloat16 hh = __float2bfloat16_rn(hval);
        const __nv_bfloat16 hl = __float2bfloat16_rn(hval - __bfloat162float(hh));
        g_hbf4[cur ^ 1][qp][bglob][cb + pu]       = hh;
        g_hbf4[cur ^ 1][qp][bglob][128 + cb + pu] = hl;

        __syncthreads();   // all h stores happen-before the flag release
        if (tid == 0) {
            asm volatile("st.release.gpu.global.s32 [%0], %1;"
                         :: "l"(&g_hflag[bg][cg * 32]), "r"(tbase + t + 1)
                         : "memory");
        }

        // off-critical-path outputs (after flag)
        if (asOut) {
            const size_t m = (size_t)bglob * kT + t;
            asOut[m * 1024 + u0 + pu]       = hh;
            asOut[m * 1024 + 512 + u0 + pu] = hl;
        } else {
            seqout[((size_t)bglob * kT + t) * kH + u0 + pu] = hval;
        }
        if (t == kT - 1) {
            hT[(size_t)bglob * kH + u0 + pu] = hval;
            cT[(size_t)bglob * kH + u0 + pu] = c_state;
        }
        // Ahs/Gs/wgs reuse is fenced by next step's post-staging syncthreads
        // and the mbar waits.
    }
}

// ---------------- launch --------------------------------------------------------
extern "C" void kernel_launch(void* const* d_in, const int* in_sizes, int n_in,
                              void* d_out, int out_size)
{
    const float* x  = (const float*)d_in[0];
    const float* Wi = (const float*)d_in[1];
    const float* Wh = (const float*)d_in[2];
    const float* bi = (const float*)d_in[3];
    const float* bh = (const float*)d_in[4];

    float* out  = (float*)d_out;
    float* outs = out;
    float* hT   = out + (size_t)kB * kT * kH;
    float* cT   = hT + (size_t)2 * kB * kH;

    float* Gp;  cudaGetSymbolAddress((void**)&Gp,  g_G);
    __nv_bfloat16 *asp, *wih, *wil, *whh, *whl;
    cudaGetSymbolAddress((void**)&asp, g_As);
    cudaGetSymbolAddress((void**)&wih, g_WiTh);
    cudaGetSymbolAddress((void**)&wil, g_WiTl);
    cudaGetSymbolAddress((void**)&whh, g_WhTh);
    cudaGetSymbolAddress((void**)&whl, g_WhTl);

    const dim3 gSplit(64, 16);
    const dim3 gGemm(kG / 128, kM / 128);

    // ---- layer 0
    split_pair<<<gSplit, 256>>>(Wi, wih, wil);
    split_pair<<<gSplit, 256>>>(Wh, whh, whl);
    split_x<<<kM * kH / 1024, 256>>>(x);          // also resets barrier state
    gemm_mma<<<gGemm, 256>>>(bi, bh, Gp);
    lstm_recur_mma<<<kCG * kBG, 256>>>(Gp, whh, whl,
                                       nullptr, asp, hT, cT, 0, 1);

    // ---- layer 1 (g_As now holds layer-0 h, already split)
    split_pair<<<gSplit, 256>>>(Wi + (size_t)kH * kG, wih, wil);
    split_pair<<<gSplit, 256>>>(Wh + (size_t)kH * kG, whh, whl);
    gemm_mma<<<gGemm, 256>>>(bi + kG, bh + kG, Gp);
    lstm_recur_mma<<<kCG * kBG, 256>>>(Gp, whh, whl,
                                       outs, nullptr,
                                       hT + (size_t)kB * kH,
                                       cT + (size_t)kB * kH, kT, 2);
}